// round 1
// baseline (speedup 1.0000x reference)
#include <cuda_runtime.h>
#include <math.h>

#define Bb 2
#define Tt 2048
#define Dd 1024
#define Hh 16
#define Ll 8
#define II 4096
#define HD 64
#define MASK_BIAS -10000.0f
#define LN_EPS 1e-5f

// ---------------- scratch (device globals; no allocation allowed) ----------------
__device__ float g_h[Bb * Tt * Dd];        // residual stream (16 MB)
__device__ float g_x[Bb * Tt * Dd];        // LN output (16 MB)
__device__ float g_qkv[Bb * Tt * 3 * Dd];  // 48 MB
__device__ float g_ctx[Bb * Tt * Dd];      // 16 MB
__device__ float g_ff[Bb * Tt * II];       // 64 MB

// ---------------- copy inputs_embeds -> g_h ----------------
__global__ void copy_kernel(const float* __restrict__ src) {
    int i = blockIdx.x * blockDim.x + threadIdx.x;
    reinterpret_cast<float4*>(g_h)[i] = reinterpret_cast<const float4*>(src)[i];
}

// ---------------- layernorm: one block per row of D=1024 ----------------
__global__ void ln_kernel(const float* __restrict__ x, const float* __restrict__ w,
                          const float* __restrict__ b, float* __restrict__ out) {
    int row = blockIdx.x;
    int tid = threadIdx.x;
    const float* xr = x + (size_t)row * Dd;
    float v[4];
    float sum = 0.f, sq = 0.f;
#pragma unroll
    for (int u = 0; u < 4; u++) {
        v[u] = xr[tid + u * 256];
        sum += v[u];
        sq += v[u] * v[u];
    }
#pragma unroll
    for (int o = 16; o > 0; o >>= 1) {
        sum += __shfl_xor_sync(0xffffffffu, sum, o);
        sq  += __shfl_xor_sync(0xffffffffu, sq, o);
    }
    __shared__ float ssum[8], ssq[8], stat[2];
    if ((tid & 31) == 0) { ssum[tid >> 5] = sum; ssq[tid >> 5] = sq; }
    __syncthreads();
    if (tid == 0) {
        float S = 0.f, Q = 0.f;
#pragma unroll
        for (int i = 0; i < 8; i++) { S += ssum[i]; Q += ssq[i]; }
        float mean = S * (1.0f / Dd);
        float var = Q * (1.0f / Dd) - mean * mean;
        stat[0] = mean;
        stat[1] = rsqrtf(var + LN_EPS);
    }
    __syncthreads();
    float mean = stat[0], rstd = stat[1];
    float* orow = out + (size_t)row * Dd;
#pragma unroll
    for (int u = 0; u < 4; u++) {
        int c = tid + u * 256;
        orow[c] = (v[u] - mean) * rstd * w[c] + b[c];
    }
}

// ---------------- SGEMM: C[M,N] = op(A[M,K] @ W[K,N] + bias (+ C residual)) ----------------
// 128x128 block tile, BK=8, 256 threads, 8x8 microtile (split 4+4 for conflict-free smem).
template <bool RELU, bool RESID>
__global__ void __launch_bounds__(256, 2)
sgemm_kernel(const float* __restrict__ A, const float* __restrict__ W,
             const float* __restrict__ bias, float* __restrict__ C,
             int M, int N, int K) {
    __shared__ float As[8][128];
    __shared__ float Bs[8][128];
    int tid = threadIdx.x;
    int row0 = blockIdx.y * 128;
    int col0 = blockIdx.x * 128;
    int tx = tid & 15, ty = tid >> 4;

    float acc[8][8];
#pragma unroll
    for (int i = 0; i < 8; i++)
#pragma unroll
        for (int j = 0; j < 8; j++) acc[i][j] = 0.f;

    int arow = tid >> 1;
    int acol = (tid & 1) * 4;
    int brow = tid >> 5;
    int bcol = (tid & 31) * 4;
    const float* Aptr = A + (size_t)(row0 + arow) * K + acol;
    const float* Bptr = W + (size_t)brow * N + col0 + bcol;

    for (int k0 = 0; k0 < K; k0 += 8) {
        float4 a = *(const float4*)Aptr;
        float4 bv = *(const float4*)Bptr;
        Aptr += 8;
        Bptr += (size_t)8 * N;
        __syncthreads();
        As[acol + 0][arow] = a.x;
        As[acol + 1][arow] = a.y;
        As[acol + 2][arow] = a.z;
        As[acol + 3][arow] = a.w;
        *(float4*)&Bs[brow][bcol] = bv;
        __syncthreads();
#pragma unroll
        for (int k = 0; k < 8; k++) {
            float4 a0 = *(const float4*)&As[k][ty * 4];
            float4 a1 = *(const float4*)&As[k][64 + ty * 4];
            float4 b0 = *(const float4*)&Bs[k][tx * 4];
            float4 b1 = *(const float4*)&Bs[k][64 + tx * 4];
            float ar[8] = {a0.x, a0.y, a0.z, a0.w, a1.x, a1.y, a1.z, a1.w};
            float br[8] = {b0.x, b0.y, b0.z, b0.w, b1.x, b1.y, b1.z, b1.w};
#pragma unroll
            for (int i = 0; i < 8; i++)
#pragma unroll
                for (int j = 0; j < 8; j++) acc[i][j] += ar[i] * br[j];
        }
    }

#pragma unroll
    for (int i = 0; i < 8; i++) {
        int r = row0 + ((i < 4) ? (ty * 4 + i) : (64 + ty * 4 + i - 4));
        float* crow = C + (size_t)r * N;
#pragma unroll
        for (int jh = 0; jh < 2; jh++) {
            int c = col0 + ((jh == 0) ? (tx * 4) : (64 + tx * 4));
            float4 bv = *(const float4*)&bias[c];
            float4 v;
            v.x = acc[i][jh * 4 + 0] + bv.x;
            v.y = acc[i][jh * 4 + 1] + bv.y;
            v.z = acc[i][jh * 4 + 2] + bv.z;
            v.w = acc[i][jh * 4 + 3] + bv.w;
            if (RELU) {
                v.x = fmaxf(v.x, 0.f); v.y = fmaxf(v.y, 0.f);
                v.z = fmaxf(v.z, 0.f); v.w = fmaxf(v.w, 0.f);
            }
            if (RESID) {
                float4 o = *(const float4*)&crow[c];
                v.x += o.x; v.y += o.y; v.z += o.z; v.w += o.w;
            }
            *(float4*)&crow[c] = v;
        }
    }
}

// ---------------- fused causal flash attention, fp32, hd=64, 64x64 tiles ----------------
// dyn smem: Qs[64][64] | KsT[64][68] (K transposed; reused for P) | Vs[64][64]
#define ATTN_SMEM ((64 * 64 + 64 * 68 + 64 * 64) * 4)

__global__ void __launch_bounds__(256, 2)
attn_kernel(const float* __restrict__ qkv, const float* __restrict__ amask,
            float* __restrict__ ctx) {
    extern __shared__ float sm[];
    float* Qs = sm;                 // [64][64]
    float* KsT = sm + 64 * 64;      // [64][68], transposed: KsT[d*68 + n]
    float* Vs = KsT + 64 * 68;      // [64][64]
    float* Ps = KsT;                // reuse after S consumed

    const float scale = 0.125f;  // 1/sqrt(64)
    int i0 = blockIdx.x * 64;
    int bh = blockIdx.y;
    int b = bh / Hh, h = bh % Hh;
    const float* qb = qkv + (size_t)b * Tt * 3 * Dd + h * HD;
    int tid = threadIdx.x;
    int tx = tid & 15, ty = tid >> 4;

    // load Q tile
    {
        int r = tid >> 2, c0 = (tid & 3) * 16;
        const float* src = qb + (size_t)(i0 + r) * 3 * Dd + c0;
#pragma unroll
        for (int u = 0; u < 4; u++) {
            float4 v = *(const float4*)(src + u * 4);
            *(float4*)&Qs[r * 64 + c0 + u * 4] = v;
        }
    }

    float acc[4][4];
    float m_run[4], l_run[4];
#pragma unroll
    for (int i = 0; i < 4; i++) {
        m_run[i] = -1e30f;
        l_run[i] = 0.f;
#pragma unroll
        for (int j = 0; j < 4; j++) acc[i][j] = 0.f;
    }

    int ntiles = i0 / 64 + 1;
    for (int jt = 0; jt < ntiles; jt++) {
        int j0 = jt * 64;
        bool diag = (j0 + 63 > i0);
        __syncthreads();  // previous AV reads of Ps/Vs done (and Q stores on iter 0)
        // load K (transposed) and V
        {
            int d = tid & 63;
            int ng = tid >> 6;
            const float* kb = qb + Dd + (size_t)j0 * 3 * Dd + d;
            const float* vb = qb + 2 * Dd + (size_t)j0 * 3 * Dd + d;
#pragma unroll
            for (int u = 0; u < 16; u++) {
                int n = ng * 16 + u;
                KsT[d * 68 + n] = kb[(size_t)n * 3 * Dd];
                Vs[n * 64 + d] = vb[(size_t)n * 3 * Dd];
            }
        }
        __syncthreads();

        // S = Q K^T
        float s[4][4];
#pragma unroll
        for (int i = 0; i < 4; i++)
#pragma unroll
            for (int j = 0; j < 4; j++) s[i][j] = 0.f;
#pragma unroll 4
        for (int d = 0; d < 64; d++) {
            float4 kq = *(const float4*)&KsT[d * 68 + tx * 4];
            float q0 = Qs[(ty * 4 + 0) * 64 + d];
            float q1 = Qs[(ty * 4 + 1) * 64 + d];
            float q2 = Qs[(ty * 4 + 2) * 64 + d];
            float q3 = Qs[(ty * 4 + 3) * 64 + d];
            s[0][0] += q0 * kq.x; s[0][1] += q0 * kq.y; s[0][2] += q0 * kq.z; s[0][3] += q0 * kq.w;
            s[1][0] += q1 * kq.x; s[1][1] += q1 * kq.y; s[1][2] += q1 * kq.z; s[1][3] += q1 * kq.w;
            s[2][0] += q2 * kq.x; s[2][1] += q2 * kq.y; s[2][2] += q2 * kq.z; s[2][3] += q2 * kq.w;
            s[3][0] += q3 * kq.x; s[3][1] += q3 * kq.y; s[3][2] += q3 * kq.z; s[3][3] += q3 * kq.w;
        }

        // scale, causal mask, additive mask
#pragma unroll
        for (int jj = 0; jj < 4; jj++) {
            int kj = j0 + tx * 4 + jj;
            float am = (1.0f - amask[b * Tt + kj]) * MASK_BIAS;
#pragma unroll
            for (int ii = 0; ii < 4; ii++) {
                int qi = i0 + ty * 4 + ii;
                float val = (!diag || kj <= qi) ? s[ii][jj] * scale : MASK_BIAS;
                s[ii][jj] = val + am;
            }
        }

        // online softmax
#pragma unroll
        for (int ii = 0; ii < 4; ii++) {
            float mt = fmaxf(fmaxf(s[ii][0], s[ii][1]), fmaxf(s[ii][2], s[ii][3]));
#pragma unroll
            for (int o = 8; o >= 1; o >>= 1) mt = fmaxf(mt, __shfl_xor_sync(0xffffffffu, mt, o));
            float mnew = fmaxf(m_run[ii], mt);
            float alpha = __expf(m_run[ii] - mnew);
            m_run[ii] = mnew;
            l_run[ii] *= alpha;
#pragma unroll
            for (int j = 0; j < 4; j++) acc[ii][j] *= alpha;
            float lsum = 0.f;
#pragma unroll
            for (int jj = 0; jj < 4; jj++) {
                s[ii][jj] = __expf(s[ii][jj] - mnew);
                lsum += s[ii][jj];
            }
#pragma unroll
            for (int o = 8; o >= 1; o >>= 1) lsum += __shfl_xor_sync(0xffffffffu, lsum, o);
            l_run[ii] += lsum;
        }

        __syncthreads();  // everyone done reading KsT
        // write P into the K buffer
#pragma unroll
        for (int ii = 0; ii < 4; ii++)
#pragma unroll
            for (int jj = 0; jj < 4; jj++)
                Ps[(ty * 4 + ii) * 68 + tx * 4 + jj] = s[ii][jj];
        __syncthreads();

        // acc += P @ V
#pragma unroll 4
        for (int k = 0; k < 64; k++) {
            float4 vv = *(const float4*)&Vs[k * 64 + tx * 4];
            float p0 = Ps[(ty * 4 + 0) * 68 + k];
            float p1 = Ps[(ty * 4 + 1) * 68 + k];
            float p2 = Ps[(ty * 4 + 2) * 68 + k];
            float p3 = Ps[(ty * 4 + 3) * 68 + k];
            acc[0][0] += p0 * vv.x; acc[0][1] += p0 * vv.y; acc[0][2] += p0 * vv.z; acc[0][3] += p0 * vv.w;
            acc[1][0] += p1 * vv.x; acc[1][1] += p1 * vv.y; acc[1][2] += p1 * vv.z; acc[1][3] += p1 * vv.w;
            acc[2][0] += p2 * vv.x; acc[2][1] += p2 * vv.y; acc[2][2] += p2 * vv.z; acc[2][3] += p2 * vv.w;
            acc[3][0] += p3 * vv.x; acc[3][1] += p3 * vv.y; acc[3][2] += p3 * vv.z; acc[3][3] += p3 * vv.w;
        }
    }

    // write out
#pragma unroll
    for (int ii = 0; ii < 4; ii++) {
        int t = i0 + ty * 4 + ii;
        float inv = 1.0f / l_run[ii];
        float4 v;
        v.x = acc[ii][0] * inv;
        v.y = acc[ii][1] * inv;
        v.z = acc[ii][2] * inv;
        v.w = acc[ii][3] * inv;
        *(float4*)&ctx[(size_t)(b * Tt + t) * Dd + h * HD + tx * 4] = v;
    }
}

// ---------------- host launcher ----------------
extern "C" void kernel_launch(void* const* d_in, const int* in_sizes, int n_in,
                              void* d_out, int out_size) {
    const float* inputs_embeds = (const float*)d_in[0];
    const float* attention_mask = (const float*)d_in[1];
    const float* ln1_w = (const float*)d_in[2];
    const float* ln1_b = (const float*)d_in[3];
    const float* attn_w = (const float*)d_in[4];
    const float* attn_b = (const float*)d_in[5];
    const float* proj_w = (const float*)d_in[6];
    const float* proj_b = (const float*)d_in[7];
    const float* ln2_w = (const float*)d_in[8];
    const float* ln2_b = (const float*)d_in[9];
    const float* fc_w = (const float*)d_in[10];
    const float* fc_b = (const float*)d_in[11];
    const float* fcp_w = (const float*)d_in[12];
    const float* fcp_b = (const float*)d_in[13];
    const float* lnf_w = (const float*)d_in[14];
    const float* lnf_b = (const float*)d_in[15];
    float* out = (float*)d_out;

    cudaFuncSetAttribute(attn_kernel, cudaFuncAttributeMaxDynamicSharedMemorySize, ATTN_SMEM);

    float *ph, *px, *pqkv, *pctx, *pff;
    cudaGetSymbolAddress((void**)&ph, g_h);
    cudaGetSymbolAddress((void**)&px, g_x);
    cudaGetSymbolAddress((void**)&pqkv, g_qkv);
    cudaGetSymbolAddress((void**)&pctx, g_ctx);
    cudaGetSymbolAddress((void**)&pff, g_ff);

    const int MT = Bb * Tt;  // 4096 rows

    copy_kernel<<<(MT * Dd / 4) / 256, 256>>>(inputs_embeds);

    for (int l = 0; l < Ll; l++) {
        // x = ln1(h)
        ln_kernel<<<MT, 256>>>(ph, ln1_w + (size_t)l * Dd, ln1_b + (size_t)l * Dd, px);
        // qkv = x @ attn_w + attn_b
        sgemm_kernel<false, false><<<dim3(3 * Dd / 128, MT / 128), 256>>>(
            px, attn_w + (size_t)l * Dd * 3 * Dd, attn_b + (size_t)l * 3 * Dd, pqkv,
            MT, 3 * Dd, Dd);
        // ctx = causal attention(qkv)
        attn_kernel<<<dim3(Tt / 64, Bb * Hh), 256, ATTN_SMEM>>>(pqkv, attention_mask, pctx);
        // h = h + ctx @ proj_w + proj_b
        sgemm_kernel<false, true><<<dim3(Dd / 128, MT / 128), 256>>>(
            pctx, proj_w + (size_t)l * Dd * Dd, proj_b + (size_t)l * Dd, ph,
            MT, Dd, Dd);
        // x = ln2(h)
        ln_kernel<<<MT, 256>>>(ph, ln2_w + (size_t)l * Dd, ln2_b + (size_t)l * Dd, px);
        // ff = relu(x @ fc_w + fc_b)
        sgemm_kernel<true, false><<<dim3(II / 128, MT / 128), 256>>>(
            px, fc_w + (size_t)l * Dd * II, fc_b + (size_t)l * II, pff,
            MT, II, Dd);
        // h = h + ff @ fcp_w + fcp_b
        sgemm_kernel<false, true><<<dim3(Dd / 128, MT / 128), 256>>>(
            pff, fcp_w + (size_t)l * II * Dd, fcp_b + (size_t)l * Dd, ph,
            MT, Dd, II);
    }
    // out = lnf(h)
    ln_kernel<<<MT, 256>>>(ph, lnf_w, lnf_b, out);
}

// round 3
// speedup vs baseline: 1.7189x; 1.7189x over previous
#include <cuda_runtime.h>
#include <cuda_bf16.h>
#include <math.h>
#include <stdint.h>

#define Bb 2
#define Tt 2048
#define Dd 1024
#define Hh 16
#define Ll 8
#define II 4096
#define HD 64
#define MASK_BIAS -10000.0f
#define LN_EPS 1e-5f

// ================= scratch =================
__device__ float g_h[Bb * Tt * Dd];
__device__ float g_qkv[Bb * Tt * 3 * Dd];
__device__ __nv_bfloat16 g_xhi[Bb * Tt * Dd], g_xlo[Bb * Tt * Dd];
__device__ __nv_bfloat16 g_ctxhi[Bb * Tt * Dd], g_ctxlo[Bb * Tt * Dd];
__device__ __nv_bfloat16 g_ffhi[Bb * Tt * II], g_fflo[Bb * Tt * II];
// transposed weight slabs [L][N][K]
__device__ __nv_bfloat16 g_wqkv_hi[Ll * 3 * Dd * Dd], g_wqkv_lo[Ll * 3 * Dd * Dd];
__device__ __nv_bfloat16 g_wproj_hi[Ll * Dd * Dd], g_wproj_lo[Ll * Dd * Dd];
__device__ __nv_bfloat16 g_wfc_hi[Ll * II * Dd], g_wfc_lo[Ll * II * Dd];
__device__ __nv_bfloat16 g_wfcp_hi[Ll * Dd * II], g_wfcp_lo[Ll * Dd * II];

__device__ __forceinline__ uint32_t smem_u32(const void* p) {
    uint32_t a;
    asm("{ .reg .u64 t; cvta.to.shared.u64 t, %1; cvt.u32.u64 %0, t; }" : "=r"(a) : "l"(p));
    return a;
}

// ================= small kernels =================
__global__ void copy_kernel(const float* __restrict__ src) {
    int i = blockIdx.x * blockDim.x + threadIdx.x;
    reinterpret_cast<float4*>(g_h)[i] = reinterpret_cast<const float4*>(src)[i];
}

// weight transpose + hi/lo convert: W[K][N] -> Wt_hi/lo[N][K]
__global__ void wconv_kernel(const float* __restrict__ W, __nv_bfloat16* __restrict__ Whi,
                             __nv_bfloat16* __restrict__ Wlo, int K, int N) {
    __shared__ float s[32][33];
    int n0 = blockIdx.x * 32, k0 = blockIdx.y * 32;
    int tx = threadIdx.x & 31, ty = threadIdx.x >> 5;
#pragma unroll
    for (int i = 0; i < 4; i++)
        s[ty + i * 8][tx] = W[(size_t)(k0 + ty + i * 8) * N + n0 + tx];
    __syncthreads();
#pragma unroll
    for (int i = 0; i < 4; i++) {
        int n = ty + i * 8;
        float v = s[tx][n];
        __nv_bfloat16 hi = __float2bfloat16(v);
        size_t idx = (size_t)(n0 + n) * K + k0 + tx;
        Whi[idx] = hi;
        Wlo[idx] = __float2bfloat16(v - __bfloat162float(hi));
    }
}

// layernorm; HILO -> bf16 hi/lo outputs, else fp32 out
template <bool HILO>
__global__ void ln_kernel(const float* __restrict__ x, const float* __restrict__ w,
                          const float* __restrict__ b, float* __restrict__ out,
                          __nv_bfloat16* __restrict__ ohi, __nv_bfloat16* __restrict__ olo) {
    int row = blockIdx.x;
    int tid = threadIdx.x;
    const float* xr = x + (size_t)row * Dd;
    float v[4];
    float sum = 0.f, sq = 0.f;
#pragma unroll
    for (int u = 0; u < 4; u++) {
        v[u] = xr[tid + u * 256];
        sum += v[u];
        sq += v[u] * v[u];
    }
#pragma unroll
    for (int o = 16; o > 0; o >>= 1) {
        sum += __shfl_xor_sync(0xffffffffu, sum, o);
        sq += __shfl_xor_sync(0xffffffffu, sq, o);
    }
    __shared__ float ssum[8], ssq[8], stat[2];
    if ((tid & 31) == 0) { ssum[tid >> 5] = sum; ssq[tid >> 5] = sq; }
    __syncthreads();
    if (tid == 0) {
        float S = 0.f, Q = 0.f;
#pragma unroll
        for (int i = 0; i < 8; i++) { S += ssum[i]; Q += ssq[i]; }
        float mean = S * (1.0f / Dd);
        float var = Q * (1.0f / Dd) - mean * mean;
        stat[0] = mean;
        stat[1] = rsqrtf(var + LN_EPS);
    }
    __syncthreads();
    float mean = stat[0], rstd = stat[1];
#pragma unroll
    for (int u = 0; u < 4; u++) {
        int c = tid + u * 256;
        float y = (v[u] - mean) * rstd * w[c] + b[c];
        if (HILO) {
            __nv_bfloat16 hi = __float2bfloat16(y);
            ohi[(size_t)row * Dd + c] = hi;
            olo[(size_t)row * Dd + c] = __float2bfloat16(y - __bfloat162float(hi));
        } else {
            out[(size_t)row * Dd + c] = y;
        }
    }
}

// ================= HMMA GEMM (mma.sync bf16, compensated) =================
// C[M,N] = (Ahi+Alo)[M,K] @ (Whi+Wlo)^T + bias (+relu / +residual), fp32 or bf16 hi/lo out.
// 128x128 tile, BK=32, 8 warps (2x4), warp tile 64x32, m16n8k16.
#define PITCHB 80          // smem row pitch in bytes (40 bf16) — conflict-free ldmatrix
#define TILE_BYTES (128 * PITCHB)   // 10240 per operand
#define STAGE_BYTES (2 * TILE_BYTES)

__device__ __forceinline__ void ldsm4(uint32_t* r, uint32_t addr) {
    asm volatile("ldmatrix.sync.aligned.m8n8.x4.shared.b16 {%0,%1,%2,%3}, [%4];"
                 : "=r"(r[0]), "=r"(r[1]), "=r"(r[2]), "=r"(r[3]) : "r"(addr));
}
__device__ __forceinline__ void mma_bf16(float* d, const uint32_t* a, uint32_t b0, uint32_t b1) {
    asm volatile("mma.sync.aligned.m16n8k16.row.col.f32.bf16.bf16.f32 "
                 "{%0,%1,%2,%3}, {%4,%5,%6,%7}, {%8,%9}, {%0,%1,%2,%3};"
                 : "+f"(d[0]), "+f"(d[1]), "+f"(d[2]), "+f"(d[3])
                 : "r"(a[0]), "r"(a[1]), "r"(a[2]), "r"(a[3]), "r"(b0), "r"(b1));
}

template <bool RELU, bool RESID, bool OUTHILO>
__global__ void __launch_bounds__(256)
gemm_mma(const __nv_bfloat16* __restrict__ Ahi, const __nv_bfloat16* __restrict__ Alo,
         const __nv_bfloat16* __restrict__ Whi, const __nv_bfloat16* __restrict__ Wlo,
         const float* __restrict__ bias, float* __restrict__ C,
         __nv_bfloat16* __restrict__ Chi, __nv_bfloat16* __restrict__ Clo,
         int M, int N, int K) {
    __shared__ __align__(128) char smem[2 * STAGE_BYTES];
    uint32_t sb = smem_u32(smem);
    int tid = threadIdx.x, wid = tid >> 5, lane = tid & 31;
    int warp_m = wid & 1, warp_n = wid >> 1;     // 2 x 4
    int row0 = blockIdx.y * 128, col0 = blockIdx.x * 128;

    const int KC = K >> 5;      // chunks of 32 per pass
    const int NC = 3 * KC;      // 3 compensation passes

    float acc[4][4][4];
#pragma unroll
    for (int i = 0; i < 4; i++)
#pragma unroll
        for (int j = 0; j < 4; j++)
#pragma unroll
            for (int q = 0; q < 4; q++) acc[i][j][q] = 0.f;

    auto issue = [&](int c) {
        int p = c / KC;
        int k0 = (c - p * KC) << 5;
        const __nv_bfloat16* A = (p == 2) ? Alo : Ahi;
        const __nv_bfloat16* Bw = (p == 1) ? Wlo : Whi;
        uint32_t base = sb + (c & 1) * STAGE_BYTES;
#pragma unroll
        for (int j = 0; j < 4; j++) {
            int lin = j * 256 + tid;          // 0..1023
            int isB = lin >> 9;               // 0: A, 1: B
            int l2 = lin & 511;
            int r = l2 >> 2, seg = l2 & 3;
            const void* g = isB ? (const void*)(Bw + (size_t)(col0 + r) * K + k0 + seg * 8)
                                : (const void*)(A + (size_t)(row0 + r) * K + k0 + seg * 8);
            uint32_t s = base + isB * TILE_BYTES + r * PITCHB + seg * 16;
            asm volatile("cp.async.cg.shared.global [%0], [%1], 16;" :: "r"(s), "l"(g));
        }
        asm volatile("cp.async.commit_group;" ::: "memory");
    };

    issue(0);
    for (int c = 0; c < NC; c++) {
        if (c + 1 < NC) {
            issue(c + 1);
            asm volatile("cp.async.wait_group 1;" ::: "memory");
        } else {
            asm volatile("cp.async.wait_group 0;" ::: "memory");
        }
        __syncthreads();
        uint32_t abase = sb + (c & 1) * STAGE_BYTES;
        uint32_t bbase = abase + TILE_BYTES;
#pragma unroll
        for (int ks = 0; ks < 2; ks++) {
            uint32_t a[4][4];
#pragma unroll
            for (int mt = 0; mt < 4; mt++) {
                int arow = warp_m * 64 + mt * 16 + (lane & 15);
                uint32_t addr = abase + arow * PITCHB + ks * 32 + ((lane >> 4) << 4);
                ldsm4(a[mt], addr);
            }
            uint32_t b[2][4];
#pragma unroll
            for (int bt = 0; bt < 2; bt++) {
                int brow = warp_n * 32 + bt * 16 + (lane & 7) + ((lane >> 4) << 3);
                uint32_t addr = bbase + brow * PITCHB + ks * 32 + (((lane >> 3) & 1) << 4);
                ldsm4(b[bt], addr);
            }
#pragma unroll
            for (int mt = 0; mt < 4; mt++)
#pragma unroll
                for (int nt = 0; nt < 4; nt++)
                    mma_bf16(acc[mt][nt], a[mt], b[nt >> 1][(nt & 1) * 2], b[nt >> 1][(nt & 1) * 2 + 1]);
        }
        __syncthreads();
    }

    // epilogue
    int rin = lane >> 2;
    int colp = (lane & 3) * 2;
#pragma unroll
    for (int mt = 0; mt < 4; mt++) {
#pragma unroll
        for (int half = 0; half < 2; half++) {
            int r = row0 + warp_m * 64 + mt * 16 + rin + half * 8;
            size_t rowoff = (size_t)r * N;
#pragma unroll
            for (int nt = 0; nt < 4; nt++) {
                int cg = col0 + warp_n * 32 + nt * 8 + colp;
                float v0 = acc[mt][nt][half * 2 + 0] + bias[cg];
                float v1 = acc[mt][nt][half * 2 + 1] + bias[cg + 1];
                if (RELU) { v0 = fmaxf(v0, 0.f); v1 = fmaxf(v1, 0.f); }
                if (RESID) {
                    float2 o = *(const float2*)&C[rowoff + cg];
                    v0 += o.x; v1 += o.y;
                }
                if (OUTHILO) {
                    union { __nv_bfloat16 h[2]; uint32_t u; } ph, pl;
                    ph.h[0] = __float2bfloat16(v0);
                    ph.h[1] = __float2bfloat16(v1);
                    pl.h[0] = __float2bfloat16(v0 - __bfloat162float(ph.h[0]));
                    pl.h[1] = __float2bfloat16(v1 - __bfloat162float(ph.h[1]));
                    *(uint32_t*)&Chi[rowoff + cg] = ph.u;
                    *(uint32_t*)&Clo[rowoff + cg] = pl.u;
                } else {
                    *(float2*)&C[rowoff + cg] = make_float2(v0, v1);
                }
            }
        }
    }
}

// ================= fused causal flash attention, fp32, hd=64, 64x64 tiles =================
#define ATTN_SMEM ((64 * 64 + 64 * 68 + 64 * 64) * 4)

__global__ void __launch_bounds__(256, 2)
attn_kernel(const float* __restrict__ qkv, const float* __restrict__ amask,
            __nv_bfloat16* __restrict__ ctxhi, __nv_bfloat16* __restrict__ ctxlo) {
    extern __shared__ float sm[];
    float* Qs = sm;
    float* KsT = sm + 64 * 64;
    float* Vs = KsT + 64 * 68;
    float* Ps = KsT;

    const float scale = 0.125f;
    int i0 = blockIdx.x * 64;
    int bh = blockIdx.y;
    int b = bh / Hh, h = bh % Hh;
    const float* qb = qkv + (size_t)b * Tt * 3 * Dd + h * HD;
    int tid = threadIdx.x;
    int tx = tid & 15, ty = tid >> 4;

    {
        int r = tid >> 2, c0 = (tid & 3) * 16;
        const float* src = qb + (size_t)(i0 + r) * 3 * Dd + c0;
#pragma unroll
        for (int u = 0; u < 4; u++) {
            float4 v = *(const float4*)(src + u * 4);
            *(float4*)&Qs[r * 64 + c0 + u * 4] = v;
        }
    }

    float acc[4][4];
    float m_run[4], l_run[4];
#pragma unroll
    for (int i = 0; i < 4; i++) {
        m_run[i] = -1e30f;
        l_run[i] = 0.f;
#pragma unroll
        for (int j = 0; j < 4; j++) acc[i][j] = 0.f;
    }

    int ntiles = i0 / 64 + 1;
    for (int jt = 0; jt < ntiles; jt++) {
        int j0 = jt * 64;
        bool diag = (j0 + 63 > i0);
        __syncthreads();
        {
            int d = tid & 63;
            int ng = tid >> 6;
            const float* kb = qb + Dd + (size_t)j0 * 3 * Dd + d;
            const float* vb = qb + 2 * Dd + (size_t)j0 * 3 * Dd + d;
#pragma unroll
            for (int u = 0; u < 16; u++) {
                int n = ng * 16 + u;
                KsT[d * 68 + n] = kb[(size_t)n * 3 * Dd];
                Vs[n * 64 + d] = vb[(size_t)n * 3 * Dd];
            }
        }
        __syncthreads();

        float s[4][4];
#pragma unroll
        for (int i = 0; i < 4; i++)
#pragma unroll
            for (int j = 0; j < 4; j++) s[i][j] = 0.f;
#pragma unroll 4
        for (int d = 0; d < 64; d++) {
            float4 kq = *(const float4*)&KsT[d * 68 + tx * 4];
            float q0 = Qs[(ty * 4 + 0) * 64 + d];
            float q1 = Qs[(ty * 4 + 1) * 64 + d];
            float q2 = Qs[(ty * 4 + 2) * 64 + d];
            float q3 = Qs[(ty * 4 + 3) * 64 + d];
            s[0][0] += q0 * kq.x; s[0][1] += q0 * kq.y; s[0][2] += q0 * kq.z; s[0][3] += q0 * kq.w;
            s[1][0] += q1 * kq.x; s[1][1] += q1 * kq.y; s[1][2] += q1 * kq.z; s[1][3] += q1 * kq.w;
            s[2][0] += q2 * kq.x; s[2][1] += q2 * kq.y; s[2][2] += q2 * kq.z; s[2][3] += q2 * kq.w;
            s[3][0] += q3 * kq.x; s[3][1] += q3 * kq.y; s[3][2] += q3 * kq.z; s[3][3] += q3 * kq.w;
        }

#pragma unroll
        for (int jj = 0; jj < 4; jj++) {
            int kj = j0 + tx * 4 + jj;
            float am = (1.0f - amask[b * Tt + kj]) * MASK_BIAS;
#pragma unroll
            for (int ii = 0; ii < 4; ii++) {
                int qi = i0 + ty * 4 + ii;
                float val = (!diag || kj <= qi) ? s[ii][jj] * scale : MASK_BIAS;
                s[ii][jj] = val + am;
            }
        }

#pragma unroll
        for (int ii = 0; ii < 4; ii++) {
            float mt = fmaxf(fmaxf(s[ii][0], s[ii][1]), fmaxf(s[ii][2], s[ii][3]));
#pragma unroll
            for (int o = 8; o >= 1; o >>= 1) mt = fmaxf(mt, __shfl_xor_sync(0xffffffffu, mt, o));
            float mnew = fmaxf(m_run[ii], mt);
            float alpha = __expf(m_run[ii] - mnew);
            m_run[ii] = mnew;
            l_run[ii] *= alpha;
#pragma unroll
            for (int j = 0; j < 4; j++) acc[ii][j] *= alpha;
            float lsum = 0.f;
#pragma unroll
            for (int jj = 0; jj < 4; jj++) {
                s[ii][jj] = __expf(s[ii][jj] - mnew);
                lsum += s[ii][jj];
            }
#pragma unroll
            for (int o = 8; o >= 1; o >>= 1) lsum += __shfl_xor_sync(0xffffffffu, lsum, o);
            l_run[ii] += lsum;
        }

        __syncthreads();
#pragma unroll
        for (int ii = 0; ii < 4; ii++)
#pragma unroll
            for (int jj = 0; jj < 4; jj++)
                Ps[(ty * 4 + ii) * 68 + tx * 4 + jj] = s[ii][jj];
        __syncthreads();

#pragma unroll 4
        for (int k = 0; k < 64; k++) {
            float4 vv = *(const float4*)&Vs[k * 64 + tx * 4];
            float p0 = Ps[(ty * 4 + 0) * 68 + k];
            float p1 = Ps[(ty * 4 + 1) * 68 + k];
            float p2 = Ps[(ty * 4 + 2) * 68 + k];
            float p3 = Ps[(ty * 4 + 3) * 68 + k];
            acc[0][0] += p0 * vv.x; acc[0][1] += p0 * vv.y; acc[0][2] += p0 * vv.z; acc[0][3] += p0 * vv.w;
            acc[1][0] += p1 * vv.x; acc[1][1] += p1 * vv.y; acc[1][2] += p1 * vv.z; acc[1][3] += p1 * vv.w;
            acc[2][0] += p2 * vv.x; acc[2][1] += p2 * vv.y; acc[2][2] += p2 * vv.z; acc[2][3] += p2 * vv.w;
            acc[3][0] += p3 * vv.x; acc[3][1] += p3 * vv.y; acc[3][2] += p3 * vv.z; acc[3][3] += p3 * vv.w;
        }
    }

#pragma unroll
    for (int ii = 0; ii < 4; ii++) {
        int t = i0 + ty * 4 + ii;
        float inv = 1.0f / l_run[ii];
        size_t base = (size_t)(b * Tt + t) * Dd + h * HD + tx * 4;
        union { __nv_bfloat16 b2[4]; uint2 u; } ph, pl;
#pragma unroll
        for (int j = 0; j < 4; j++) {
            float y = acc[ii][j] * inv;
            ph.b2[j] = __float2bfloat16(y);
            pl.b2[j] = __float2bfloat16(y - __bfloat162float(ph.b2[j]));
        }
        *(uint2*)&ctxhi[base] = ph.u;
        *(uint2*)&ctxlo[base] = pl.u;
    }
}

// ================= host launcher =================
extern "C" void kernel_launch(void* const* d_in, const int* in_sizes, int n_in,
                              void* d_out, int out_size) {
    const float* inputs_embeds = (const float*)d_in[0];
    const float* attention_mask = (const float*)d_in[1];
    const float* ln1_w = (const float*)d_in[2];
    const float* ln1_b = (const float*)d_in[3];
    const float* attn_w = (const float*)d_in[4];
    const float* attn_b = (const float*)d_in[5];
    const float* proj_w = (const float*)d_in[6];
    const float* proj_b = (const float*)d_in[7];
    const float* ln2_w = (const float*)d_in[8];
    const float* ln2_b = (const float*)d_in[9];
    const float* fc_w = (const float*)d_in[10];
    const float* fc_b = (const float*)d_in[11];
    const float* fcp_w = (const float*)d_in[12];
    const float* fcp_b = (const float*)d_in[13];
    const float* lnf_w = (const float*)d_in[14];
    const float* lnf_b = (const float*)d_in[15];
    float* out = (float*)d_out;

    cudaFuncSetAttribute(attn_kernel, cudaFuncAttributeMaxDynamicSharedMemorySize, ATTN_SMEM);

    float *ph, *pqkv;
    __nv_bfloat16 *pxhi, *pxlo, *pchi, *pclo, *pfhi, *pflo;
    __nv_bfloat16 *wqh, *wql, *wph, *wpl, *wfh, *wfl, *wgh, *wgl;
    cudaGetSymbolAddress((void**)&ph, g_h);
    cudaGetSymbolAddress((void**)&pqkv, g_qkv);
    cudaGetSymbolAddress((void**)&pxhi, g_xhi);
    cudaGetSymbolAddress((void**)&pxlo, g_xlo);
    cudaGetSymbolAddress((void**)&pchi, g_ctxhi);
    cudaGetSymbolAddress((void**)&pclo, g_ctxlo);
    cudaGetSymbolAddress((void**)&pfhi, g_ffhi);
    cudaGetSymbolAddress((void**)&pflo, g_fflo);
    cudaGetSymbolAddress((void**)&wqh, g_wqkv_hi);
    cudaGetSymbolAddress((void**)&wql, g_wqkv_lo);
    cudaGetSymbolAddress((void**)&wph, g_wproj_hi);
    cudaGetSymbolAddress((void**)&wpl, g_wproj_lo);
    cudaGetSymbolAddress((void**)&wfh, g_wfc_hi);
    cudaGetSymbolAddress((void**)&wfl, g_wfc_lo);
    cudaGetSymbolAddress((void**)&wgh, g_wfcp_hi);
    cudaGetSymbolAddress((void**)&wgl, g_wfcp_lo);

    const int MT = Bb * Tt;  // 4096

    copy_kernel<<<(MT * Dd / 4) / 256, 256>>>(inputs_embeds);

    for (int l = 0; l < Ll; l++) {
        wconv_kernel<<<dim3(3 * Dd / 32, Dd / 32), 256>>>(
            attn_w + (size_t)l * Dd * 3 * Dd, wqh + (size_t)l * 3 * Dd * Dd, wql + (size_t)l * 3 * Dd * Dd, Dd, 3 * Dd);
        wconv_kernel<<<dim3(Dd / 32, Dd / 32), 256>>>(
            proj_w + (size_t)l * Dd * Dd, wph + (size_t)l * Dd * Dd, wpl + (size_t)l * Dd * Dd, Dd, Dd);
        wconv_kernel<<<dim3(II / 32, Dd / 32), 256>>>(
            fc_w + (size_t)l * Dd * II, wfh + (size_t)l * II * Dd, wfl + (size_t)l * II * Dd, Dd, II);
        wconv_kernel<<<dim3(Dd / 32, II / 32), 256>>>(
            fcp_w + (size_t)l * II * Dd, wgh + (size_t)l * Dd * II, wgl + (size_t)l * Dd * II, II, Dd);
    }

    for (int l = 0; l < Ll; l++) {
        ln_kernel<true><<<MT, 256>>>(ph, ln1_w + (size_t)l * Dd, ln1_b + (size_t)l * Dd, nullptr, pxhi, pxlo);
        gemm_mma<false, false, false><<<dim3(3 * Dd / 128, MT / 128), 256>>>(
            pxhi, pxlo, wqh + (size_t)l * 3 * Dd * Dd, wql + (size_t)l * 3 * Dd * Dd,
            attn_b + (size_t)l * 3 * Dd, pqkv, nullptr, nullptr, MT, 3 * Dd, Dd);
        attn_kernel<<<dim3(Tt / 64, Bb * Hh), 256, ATTN_SMEM>>>(pqkv, attention_mask, pchi, pclo);
        gemm_mma<false, true, false><<<dim3(Dd / 128, MT / 128), 256>>>(
            pchi, pclo, wph + (size_t)l * Dd * Dd, wpl + (size_t)l * Dd * Dd,
            proj_b + (size_t)l * Dd, ph, nullptr, nullptr, MT, Dd, Dd);
        ln_kernel<true><<<MT, 256>>>(ph, ln2_w + (size_t)l * Dd, ln2_b + (size_t)l * Dd, nullptr, pxhi, pxlo);
        gemm_mma<true, false, true><<<dim3(II / 128, MT / 128), 256>>>(
            pxhi, pxlo, wfh + (size_t)l * II * Dd, wfl + (size_t)l * II * Dd,
            fc_b + (size_t)l * II, nullptr, pfhi, pflo, MT, II, Dd);
        gemm_mma<false, true, false><<<dim3(Dd / 128, MT / 128), 256>>>(
            pfhi, pflo, wgh + (size_t)l * Dd * II, wgl + (size_t)l * Dd * II,
            fcp_b + (size_t)l * Dd, ph, nullptr, nullptr, MT, Dd, II);
    }
    ln_kernel<false><<<MT, 256>>>(ph, lnf_w, lnf_b, out, nullptr, nullptr);
}

// round 4
// speedup vs baseline: 2.0922x; 1.2171x over previous
#include <cuda_runtime.h>
#include <cuda_bf16.h>
#include <math.h>
#include <stdint.h>

#define Bb 2
#define Tt 2048
#define Dd 1024
#define Hh 16
#define Ll 8
#define II 4096
#define HD 64
#define MASK_BIAS -10000.0f
#define LN_EPS 1e-5f

// ================= scratch =================
__device__ float g_h[Bb * Tt * Dd];
__device__ float g_qkv[Bb * Tt * 3 * Dd];
__device__ __nv_bfloat16 g_xhi[Bb * Tt * Dd], g_xlo[Bb * Tt * Dd];
__device__ __nv_bfloat16 g_ctxhi[Bb * Tt * Dd], g_ctxlo[Bb * Tt * Dd];
__device__ __nv_bfloat16 g_ffhi[Bb * Tt * II], g_fflo[Bb * Tt * II];
// transposed weight slabs [L][N][K]
__device__ __nv_bfloat16 g_wqkv_hi[Ll * 3 * Dd * Dd], g_wqkv_lo[Ll * 3 * Dd * Dd];
__device__ __nv_bfloat16 g_wproj_hi[Ll * Dd * Dd], g_wproj_lo[Ll * Dd * Dd];
__device__ __nv_bfloat16 g_wfc_hi[Ll * II * Dd], g_wfc_lo[Ll * II * Dd];
__device__ __nv_bfloat16 g_wfcp_hi[Ll * Dd * II], g_wfcp_lo[Ll * Dd * II];

__device__ __forceinline__ uint32_t smem_u32(const void* p) {
    uint32_t a;
    asm("{ .reg .u64 t; cvta.to.shared.u64 t, %1; cvt.u32.u64 %0, t; }" : "=r"(a) : "l"(p));
    return a;
}
__device__ __forceinline__ void ldsm4(uint32_t* r, uint32_t addr) {
    asm volatile("ldmatrix.sync.aligned.m8n8.x4.shared.b16 {%0,%1,%2,%3}, [%4];"
                 : "=r"(r[0]), "=r"(r[1]), "=r"(r[2]), "=r"(r[3]) : "r"(addr));
}
__device__ __forceinline__ void mma_bf16(float* d, const uint32_t* a, uint32_t b0, uint32_t b1) {
    asm volatile("mma.sync.aligned.m16n8k16.row.col.f32.bf16.bf16.f32 "
                 "{%0,%1,%2,%3}, {%4,%5,%6,%7}, {%8,%9}, {%0,%1,%2,%3};"
                 : "+f"(d[0]), "+f"(d[1]), "+f"(d[2]), "+f"(d[3])
                 : "r"(a[0]), "r"(a[1]), "r"(a[2]), "r"(a[3]), "r"(b0), "r"(b1));
}
__device__ __forceinline__ uint32_t packbf(float x, float y) {
    __nv_bfloat162 t = __floats2bfloat162_rn(x, y);
    return *reinterpret_cast<uint32_t*>(&t);
}

// ================= small kernels =================
__global__ void copy_kernel(const float* __restrict__ src) {
    int i = blockIdx.x * blockDim.x + threadIdx.x;
    reinterpret_cast<float4*>(g_h)[i] = reinterpret_cast<const float4*>(src)[i];
}

__global__ void wconv_kernel(const float* __restrict__ W, __nv_bfloat16* __restrict__ Whi,
                             __nv_bfloat16* __restrict__ Wlo, int K, int N) {
    __shared__ float s[32][33];
    int n0 = blockIdx.x * 32, k0 = blockIdx.y * 32;
    int tx = threadIdx.x & 31, ty = threadIdx.x >> 5;
#pragma unroll
    for (int i = 0; i < 4; i++)
        s[ty + i * 8][tx] = W[(size_t)(k0 + ty + i * 8) * N + n0 + tx];
    __syncthreads();
#pragma unroll
    for (int i = 0; i < 4; i++) {
        int n = ty + i * 8;
        float v = s[tx][n];
        __nv_bfloat16 hi = __float2bfloat16(v);
        size_t idx = (size_t)(n0 + n) * K + k0 + tx;
        Whi[idx] = hi;
        Wlo[idx] = __float2bfloat16(v - __bfloat162float(hi));
    }
}

template <bool HILO>
__global__ void ln_kernel(const float* __restrict__ x, const float* __restrict__ w,
                          const float* __restrict__ b, float* __restrict__ out,
                          __nv_bfloat16* __restrict__ ohi, __nv_bfloat16* __restrict__ olo) {
    int row = blockIdx.x;
    int tid = threadIdx.x;
    const float* xr = x + (size_t)row * Dd;
    float v[4];
    float sum = 0.f, sq = 0.f;
#pragma unroll
    for (int u = 0; u < 4; u++) {
        v[u] = xr[tid + u * 256];
        sum += v[u];
        sq += v[u] * v[u];
    }
#pragma unroll
    for (int o = 16; o > 0; o >>= 1) {
        sum += __shfl_xor_sync(0xffffffffu, sum, o);
        sq += __shfl_xor_sync(0xffffffffu, sq, o);
    }
    __shared__ float ssum[8], ssq[8], stat[2];
    if ((tid & 31) == 0) { ssum[tid >> 5] = sum; ssq[tid >> 5] = sq; }
    __syncthreads();
    if (tid == 0) {
        float S = 0.f, Q = 0.f;
#pragma unroll
        for (int i = 0; i < 8; i++) { S += ssum[i]; Q += ssq[i]; }
        float mean = S * (1.0f / Dd);
        float var = Q * (1.0f / Dd) - mean * mean;
        stat[0] = mean;
        stat[1] = rsqrtf(var + LN_EPS);
    }
    __syncthreads();
    float mean = stat[0], rstd = stat[1];
#pragma unroll
    for (int u = 0; u < 4; u++) {
        int c = tid + u * 256;
        float y = (v[u] - mean) * rstd * w[c] + b[c];
        if (HILO) {
            __nv_bfloat16 hi = __float2bfloat16(y);
            ohi[(size_t)row * Dd + c] = hi;
            olo[(size_t)row * Dd + c] = __float2bfloat16(y - __bfloat162float(hi));
        } else {
            out[(size_t)row * Dd + c] = y;
        }
    }
}

// ================= HMMA GEMM (3-stage) =================
#define PITCHB 80
#define TILE_BYTES (128 * PITCHB)
#define STAGE_BYTES (2 * TILE_BYTES)
#define GEMM_SMEM (3 * STAGE_BYTES)

template <bool RELU, bool RESID, bool OUTHILO>
__global__ void __launch_bounds__(256)
gemm_mma(const __nv_bfloat16* __restrict__ Ahi, const __nv_bfloat16* __restrict__ Alo,
         const __nv_bfloat16* __restrict__ Whi, const __nv_bfloat16* __restrict__ Wlo,
         const float* __restrict__ bias, float* __restrict__ C,
         __nv_bfloat16* __restrict__ Chi, __nv_bfloat16* __restrict__ Clo,
         int M, int N, int K) {
    extern __shared__ char smem[];
    uint32_t sb = smem_u32(smem);
    int tid = threadIdx.x, wid = tid >> 5, lane = tid & 31;
    int warp_m = wid & 1, warp_n = wid >> 1;
    int row0 = blockIdx.y * 128, col0 = blockIdx.x * 128;

    const int KC = K >> 5;
    const int NC = 3 * KC;

    float acc[4][4][4];
#pragma unroll
    for (int i = 0; i < 4; i++)
#pragma unroll
        for (int j = 0; j < 4; j++)
#pragma unroll
            for (int q = 0; q < 4; q++) acc[i][j][q] = 0.f;

    auto issue = [&](int c) {
        int p = c / KC;
        int k0 = (c - p * KC) << 5;
        const __nv_bfloat16* A = (p == 2) ? Alo : Ahi;
        const __nv_bfloat16* Bw = (p == 1) ? Wlo : Whi;
        uint32_t base = sb + (c % 3) * STAGE_BYTES;
#pragma unroll
        for (int j = 0; j < 4; j++) {
            int lin = j * 256 + tid;
            int isB = lin >> 9;
            int l2 = lin & 511;
            int r = l2 >> 2, seg = l2 & 3;
            const void* g = isB ? (const void*)(Bw + (size_t)(col0 + r) * K + k0 + seg * 8)
                                : (const void*)(A + (size_t)(row0 + r) * K + k0 + seg * 8);
            uint32_t s = base + isB * TILE_BYTES + r * PITCHB + seg * 16;
            asm volatile("cp.async.cg.shared.global [%0], [%1], 16;" :: "r"(s), "l"(g));
        }
        asm volatile("cp.async.commit_group;" ::: "memory");
    };

    issue(0);
    issue(1);
    for (int c = 0; c < NC; c++) {
        if (c + 2 < NC) {
            issue(c + 2);
            asm volatile("cp.async.wait_group 2;" ::: "memory");
        } else if (c + 1 < NC) {
            asm volatile("cp.async.wait_group 1;" ::: "memory");
        } else {
            asm volatile("cp.async.wait_group 0;" ::: "memory");
        }
        __syncthreads();
        uint32_t abase = sb + (c % 3) * STAGE_BYTES;
        uint32_t bbase = abase + TILE_BYTES;
#pragma unroll
        for (int ks = 0; ks < 2; ks++) {
            uint32_t a[4][4];
#pragma unroll
            for (int mt = 0; mt < 4; mt++) {
                int arow = warp_m * 64 + mt * 16 + (lane & 15);
                uint32_t addr = abase + arow * PITCHB + ks * 32 + ((lane >> 4) << 4);
                ldsm4(a[mt], addr);
            }
            uint32_t b[2][4];
#pragma unroll
            for (int bt = 0; bt < 2; bt++) {
                int brow = warp_n * 32 + bt * 16 + (lane & 7) + ((lane >> 4) << 3);
                uint32_t addr = bbase + brow * PITCHB + ks * 32 + (((lane >> 3) & 1) << 4);
                ldsm4(b[bt], addr);
            }
#pragma unroll
            for (int mt = 0; mt < 4; mt++)
#pragma unroll
                for (int nt = 0; nt < 4; nt++)
                    mma_bf16(acc[mt][nt], a[mt], b[nt >> 1][(nt & 1) * 2], b[nt >> 1][(nt & 1) * 2 + 1]);
        }
        __syncthreads();
    }

    int rin = lane >> 2;
    int colp = (lane & 3) * 2;
#pragma unroll
    for (int mt = 0; mt < 4; mt++) {
#pragma unroll
        for (int half = 0; half < 2; half++) {
            int r = row0 + warp_m * 64 + mt * 16 + rin + half * 8;
            size_t rowoff = (size_t)r * N;
#pragma unroll
            for (int nt = 0; nt < 4; nt++) {
                int cg = col0 + warp_n * 32 + nt * 8 + colp;
                float v0 = acc[mt][nt][half * 2 + 0] + bias[cg];
                float v1 = acc[mt][nt][half * 2 + 1] + bias[cg + 1];
                if (RELU) { v0 = fmaxf(v0, 0.f); v1 = fmaxf(v1, 0.f); }
                if (RESID) {
                    float2 o = *(const float2*)&C[rowoff + cg];
                    v0 += o.x; v1 += o.y;
                }
                if (OUTHILO) {
                    union { __nv_bfloat16 h[2]; uint32_t u; } ph, pl;
                    ph.h[0] = __float2bfloat16(v0);
                    ph.h[1] = __float2bfloat16(v1);
                    pl.h[0] = __float2bfloat16(v0 - __bfloat162float(ph.h[0]));
                    pl.h[1] = __float2bfloat16(v1 - __bfloat162float(ph.h[1]));
                    *(uint32_t*)&Chi[rowoff + cg] = ph.u;
                    *(uint32_t*)&Clo[rowoff + cg] = pl.u;
                } else {
                    *(float2*)&C[rowoff + cg] = make_float2(v0, v1);
                }
            }
        }
    }
}

// ================= HMMA flash attention (compensated bf16) =================
// 128 q rows per block, 64-key tiles, 8 warps x 16 rows. hd = 64.
#define AQP 72  // pitch in bf16 elements = 144 bytes
#define SM_QHI 0
#define SM_QLO 18432
#define SM_KHI 36864
#define SM_KLO 46080
#define SM_VHI 55296
#define SM_VLO 64512
#define SM_AM  73728
#define ATTN_SMEM (73728 + 256)

__global__ void __launch_bounds__(256, 2)
attn_mma(const float* __restrict__ qkv, const float* __restrict__ amask,
         __nv_bfloat16* __restrict__ ctxhi, __nv_bfloat16* __restrict__ ctxlo) {
    extern __shared__ char sm[];
    uint32_t sb = smem_u32(sm);
    float* AM = (float*)(sm + SM_AM);
    int tid = threadIdx.x, wid = tid >> 5, lane = tid & 31;
    int i0 = blockIdx.x * 128;
    int b = blockIdx.y >> 4, h = blockIdx.y & 15;
    const float* base = qkv + (size_t)b * Tt * 3 * Dd + h * HD;

    // load Q tile (128 x 64) -> hi/lo bf16
#pragma unroll
    for (int i = 0; i < 8; i++) {
        int idx = i * 256 + tid;
        int r = idx >> 4, c = (idx & 15) * 4;
        float4 v = *(const float4*)(base + (size_t)(i0 + r) * 3 * Dd + c);
        union { __nv_bfloat16 bb[4]; uint2 u; } H, L;
        float vv[4] = {v.x, v.y, v.z, v.w};
#pragma unroll
        for (int u = 0; u < 4; u++) {
            H.bb[u] = __float2bfloat16(vv[u]);
            L.bb[u] = __float2bfloat16(vv[u] - __bfloat162float(H.bb[u]));
        }
        *(uint2*)(sm + SM_QHI + (r * AQP + c) * 2) = H.u;
        *(uint2*)(sm + SM_QLO + (r * AQP + c) * 2) = L.u;
    }

    float o[8][4];
#pragma unroll
    for (int i = 0; i < 8; i++)
#pragma unroll
        for (int q = 0; q < 4; q++) o[i][q] = 0.f;
    float m_run[2] = {-1e30f, -1e30f}, l_run[2] = {0.f, 0.f};

    int r0 = lane >> 2;
    int cq = (lane & 3) * 2;
    int qrow0 = i0 + wid * 16 + r0;

    int ntiles = i0 / 64 + 2;
    for (int jt = 0; jt < ntiles; jt++) {
        int j0 = jt * 64;
        bool diag = (j0 + 63 > i0);
        __syncthreads();
        // K tile (64 x 64) -> hi/lo
#pragma unroll
        for (int i = 0; i < 4; i++) {
            int idx = i * 256 + tid;
            int r = idx >> 4, c = (idx & 15) * 4;
            float4 v = *(const float4*)(base + Dd + (size_t)(j0 + r) * 3 * Dd + c);
            union { __nv_bfloat16 bb[4]; uint2 u; } H, L;
            float vv[4] = {v.x, v.y, v.z, v.w};
#pragma unroll
            for (int u = 0; u < 4; u++) {
                H.bb[u] = __float2bfloat16(vv[u]);
                L.bb[u] = __float2bfloat16(vv[u] - __bfloat162float(H.bb[u]));
            }
            *(uint2*)(sm + SM_KHI + (r * AQP + c) * 2) = H.u;
            *(uint2*)(sm + SM_KLO + (r * AQP + c) * 2) = L.u;
        }
        // V tile transposed: Vt[d][key]
#pragma unroll
        for (int i = 0; i < 4; i++) {
            int idx = i * 256 + tid;
            int n = idx >> 4, c = (idx & 15) * 4;
            float4 v = *(const float4*)(base + 2 * Dd + (size_t)(j0 + n) * 3 * Dd + c);
            float vv[4] = {v.x, v.y, v.z, v.w};
#pragma unroll
            for (int u = 0; u < 4; u++) {
                __nv_bfloat16 hi = __float2bfloat16(vv[u]);
                __nv_bfloat16 lo = __float2bfloat16(vv[u] - __bfloat162float(hi));
                *(__nv_bfloat16*)(sm + SM_VHI + ((c + u) * AQP + n) * 2) = hi;
                *(__nv_bfloat16*)(sm + SM_VLO + ((c + u) * AQP + n) * 2) = lo;
            }
        }
        if (tid < 64) AM[tid] = (1.0f - amask[b * Tt + j0 + tid]) * MASK_BIAS;
        __syncthreads();

        // S = Q K^T, 3 compensated passes
        float sf[8][4];
#pragma unroll
        for (int i = 0; i < 8; i++)
#pragma unroll
            for (int q = 0; q < 4; q++) sf[i][q] = 0.f;
#pragma unroll
        for (int pass = 0; pass < 3; pass++) {
            uint32_t qb = sb + (pass == 2 ? SM_QLO : SM_QHI);
            uint32_t kb = sb + (pass == 1 ? SM_KLO : SM_KHI);
#pragma unroll
            for (int s = 0; s < 4; s++) {
                uint32_t a[4];
                ldsm4(a, qb + (wid * 16 + (lane & 15)) * 144 + s * 32 + ((lane >> 4) << 4));
#pragma unroll
                for (int p2 = 0; p2 < 4; p2++) {
                    uint32_t bbq[4];
                    ldsm4(bbq, kb + (p2 * 16 + (lane & 7) + ((lane >> 4) << 3)) * 144 + s * 32 + (((lane >> 3) & 1) << 4));
                    mma_bf16(sf[p2 * 2], a, bbq[0], bbq[1]);
                    mma_bf16(sf[p2 * 2 + 1], a, bbq[2], bbq[3]);
                }
            }
        }

        // mask + scale + additive mask
#pragma unroll
        for (int nt = 0; nt < 8; nt++) {
#pragma unroll
            for (int q = 0; q < 4; q++) {
                int col = nt * 8 + cq + (q & 1);
                float val = sf[nt][q] * 0.125f;
                if (diag && (j0 + col) > (qrow0 + (q >> 1) * 8)) val = MASK_BIAS;
                sf[nt][q] = val + AM[col];
            }
        }

        // online softmax (2 rows per thread)
        float alpha[2];
#pragma unroll
        for (int rh = 0; rh < 2; rh++) {
            float mt = -1e30f;
#pragma unroll
            for (int nt = 0; nt < 8; nt++)
                mt = fmaxf(mt, fmaxf(sf[nt][rh * 2], sf[nt][rh * 2 + 1]));
            mt = fmaxf(mt, __shfl_xor_sync(0xffffffffu, mt, 1));
            mt = fmaxf(mt, __shfl_xor_sync(0xffffffffu, mt, 2));
            float mnew = fmaxf(m_run[rh], mt);
            alpha[rh] = __expf(m_run[rh] - mnew);
            m_run[rh] = mnew;
            float ls = 0.f;
#pragma unroll
            for (int nt = 0; nt < 8; nt++) {
                sf[nt][rh * 2] = __expf(sf[nt][rh * 2] - mnew);
                sf[nt][rh * 2 + 1] = __expf(sf[nt][rh * 2 + 1] - mnew);
                ls += sf[nt][rh * 2] + sf[nt][rh * 2 + 1];
            }
            ls += __shfl_xor_sync(0xffffffffu, ls, 1);
            ls += __shfl_xor_sync(0xffffffffu, ls, 2);
            l_run[rh] = l_run[rh] * alpha[rh] + ls;
        }
#pragma unroll
        for (int nt = 0; nt < 8; nt++) {
            o[nt][0] *= alpha[0]; o[nt][1] *= alpha[0];
            o[nt][2] *= alpha[1]; o[nt][3] *= alpha[1];
        }

        // PV: 3 compensated passes, P packed from registers
#pragma unroll
        for (int s2 = 0; s2 < 4; s2++) {
            float p0 = sf[2 * s2][0], p1 = sf[2 * s2][1], p2v = sf[2 * s2][2], p3 = sf[2 * s2][3];
            float q0 = sf[2 * s2 + 1][0], q1 = sf[2 * s2 + 1][1], q2 = sf[2 * s2 + 1][2], q3 = sf[2 * s2 + 1][3];
            uint32_t phi[4], plo[4];
            phi[0] = packbf(p0, p1); phi[1] = packbf(p2v, p3);
            phi[2] = packbf(q0, q1); phi[3] = packbf(q2, q3);
            {
                __nv_bfloat162 t;
                t = *(__nv_bfloat162*)&phi[0];
                plo[0] = packbf(p0 - __low2float(t), p1 - __high2float(t));
                t = *(__nv_bfloat162*)&phi[1];
                plo[1] = packbf(p2v - __low2float(t), p3 - __high2float(t));
                t = *(__nv_bfloat162*)&phi[2];
                plo[2] = packbf(q0 - __low2float(t), q1 - __high2float(t));
                t = *(__nv_bfloat162*)&phi[3];
                plo[3] = packbf(q2 - __low2float(t), q3 - __high2float(t));
            }
#pragma unroll
            for (int p2 = 0; p2 < 4; p2++) {
                uint32_t vrow = (p2 * 16 + (lane & 7) + ((lane >> 4) << 3)) * 144 + s2 * 32 + (((lane >> 3) & 1) << 4);
                uint32_t bh[4], bl[4];
                ldsm4(bh, sb + SM_VHI + vrow);
                ldsm4(bl, sb + SM_VLO + vrow);
                mma_bf16(o[p2 * 2], phi, bh[0], bh[1]);
                mma_bf16(o[p2 * 2 + 1], phi, bh[2], bh[3]);
                mma_bf16(o[p2 * 2], phi, bl[0], bl[1]);
                mma_bf16(o[p2 * 2 + 1], phi, bl[2], bl[3]);
                mma_bf16(o[p2 * 2], plo, bh[0], bh[1]);
                mma_bf16(o[p2 * 2 + 1], plo, bh[2], bh[3]);
            }
        }
    }

    // epilogue: ctx hi/lo
    float inv[2] = {1.f / l_run[0], 1.f / l_run[1]};
#pragma unroll
    for (int nt = 0; nt < 8; nt++) {
        int d0 = nt * 8 + cq;
#pragma unroll
        for (int rh = 0; rh < 2; rh++) {
            int row = i0 + wid * 16 + r0 + rh * 8;
            float x = o[nt][rh * 2] * inv[rh];
            float y = o[nt][rh * 2 + 1] * inv[rh];
            uint32_t hu = packbf(x, y);
            __nv_bfloat162 t = *(__nv_bfloat162*)&hu;
            uint32_t lu = packbf(x - __low2float(t), y - __high2float(t));
            size_t off = (size_t)(b * Tt + row) * Dd + h * HD + d0;
            *(uint32_t*)&ctxhi[off] = hu;
            *(uint32_t*)&ctxlo[off] = lu;
        }
    }
}

// ================= host launcher =================
extern "C" void kernel_launch(void* const* d_in, const int* in_sizes, int n_in,
                              void* d_out, int out_size) {
    const float* inputs_embeds = (const float*)d_in[0];
    const float* attention_mask = (const float*)d_in[1];
    const float* ln1_w = (const float*)d_in[2];
    const float* ln1_b = (const float*)d_in[3];
    const float* attn_w = (const float*)d_in[4];
    const float* attn_b = (const float*)d_in[5];
    const float* proj_w = (const float*)d_in[6];
    const float* proj_b = (const float*)d_in[7];
    const float* ln2_w = (const float*)d_in[8];
    const float* ln2_b = (const float*)d_in[9];
    const float* fc_w = (const float*)d_in[10];
    const float* fc_b = (const float*)d_in[11];
    const float* fcp_w = (const float*)d_in[12];
    const float* fcp_b = (const float*)d_in[13];
    const float* lnf_w = (const float*)d_in[14];
    const float* lnf_b = (const float*)d_in[15];
    float* out = (float*)d_out;

    cudaFuncSetAttribute(attn_mma, cudaFuncAttributeMaxDynamicSharedMemorySize, ATTN_SMEM);
    cudaFuncSetAttribute(gemm_mma<false, false, false>, cudaFuncAttributeMaxDynamicSharedMemorySize, GEMM_SMEM);
    cudaFuncSetAttribute(gemm_mma<false, true, false>, cudaFuncAttributeMaxDynamicSharedMemorySize, GEMM_SMEM);
    cudaFuncSetAttribute(gemm_mma<true, false, true>, cudaFuncAttributeMaxDynamicSharedMemorySize, GEMM_SMEM);

    float *ph, *pqkv;
    __nv_bfloat16 *pxhi, *pxlo, *pchi, *pclo, *pfhi, *pflo;
    __nv_bfloat16 *wqh, *wql, *wph, *wpl, *wfh, *wfl, *wgh, *wgl;
    cudaGetSymbolAddress((void**)&ph, g_h);
    cudaGetSymbolAddress((void**)&pqkv, g_qkv);
    cudaGetSymbolAddress((void**)&pxhi, g_xhi);
    cudaGetSymbolAddress((void**)&pxlo, g_xlo);
    cudaGetSymbolAddress((void**)&pchi, g_ctxhi);
    cudaGetSymbolAddress((void**)&pclo, g_ctxlo);
    cudaGetSymbolAddress((void**)&pfhi, g_ffhi);
    cudaGetSymbolAddress((void**)&pflo, g_fflo);
    cudaGetSymbolAddress((void**)&wqh, g_wqkv_hi);
    cudaGetSymbolAddress((void**)&wql, g_wqkv_lo);
    cudaGetSymbolAddress((void**)&wph, g_wproj_hi);
    cudaGetSymbolAddress((void**)&wpl, g_wproj_lo);
    cudaGetSymbolAddress((void**)&wfh, g_wfc_hi);
    cudaGetSymbolAddress((void**)&wfl, g_wfc_lo);
    cudaGetSymbolAddress((void**)&wgh, g_wfcp_hi);
    cudaGetSymbolAddress((void**)&wgl, g_wfcp_lo);

    const int MT = Bb * Tt;

    copy_kernel<<<(MT * Dd / 4) / 256, 256>>>(inputs_embeds);

    for (int l = 0; l < Ll; l++) {
        wconv_kernel<<<dim3(3 * Dd / 32, Dd / 32), 256>>>(
            attn_w + (size_t)l * Dd * 3 * Dd, wqh + (size_t)l * 3 * Dd * Dd, wql + (size_t)l * 3 * Dd * Dd, Dd, 3 * Dd);
        wconv_kernel<<<dim3(Dd / 32, Dd / 32), 256>>>(
            proj_w + (size_t)l * Dd * Dd, wph + (size_t)l * Dd * Dd, wpl + (size_t)l * Dd * Dd, Dd, Dd);
        wconv_kernel<<<dim3(II / 32, Dd / 32), 256>>>(
            fc_w + (size_t)l * Dd * II, wfh + (size_t)l * II * Dd, wfl + (size_t)l * II * Dd, Dd, II);
        wconv_kernel<<<dim3(Dd / 32, II / 32), 256>>>(
            fcp_w + (size_t)l * II * Dd, wgh + (size_t)l * Dd * II, wgl + (size_t)l * Dd * II, II, Dd);
    }

    for (int l = 0; l < Ll; l++) {
        ln_kernel<true><<<MT, 256>>>(ph, ln1_w + (size_t)l * Dd, ln1_b + (size_t)l * Dd, nullptr, pxhi, pxlo);
        gemm_mma<false, false, false><<<dim3(3 * Dd / 128, MT / 128), 256, GEMM_SMEM>>>(
            pxhi, pxlo, wqh + (size_t)l * 3 * Dd * Dd, wql + (size_t)l * 3 * Dd * Dd,
            attn_b + (size_t)l * 3 * Dd, pqkv, nullptr, nullptr, MT, 3 * Dd, Dd);
        attn_mma<<<dim3(Tt / 128, Bb * Hh), 256, ATTN_SMEM>>>(pqkv, attention_mask, pchi, pclo);
        gemm_mma<false, true, false><<<dim3(Dd / 128, MT / 128), 256, GEMM_SMEM>>>(
            pchi, pclo, wph + (size_t)l * Dd * Dd, wpl + (size_t)l * Dd * Dd,
            proj_b + (size_t)l * Dd, ph, nullptr, nullptr, MT, Dd, Dd);
        ln_kernel<true><<<MT, 256>>>(ph, ln2_w + (size_t)l * Dd, ln2_b + (size_t)l * Dd, nullptr, pxhi, pxlo);
        gemm_mma<true, false, true><<<dim3(II / 128, MT / 128), 256, GEMM_SMEM>>>(
            pxhi, pxlo, wfh + (size_t)l * II * Dd, wfl + (size_t)l * II * Dd,
            fc_b + (size_t)l * II, nullptr, pfhi, pflo, MT, II, Dd);
        gemm_mma<false, true, false><<<dim3(Dd / 128, MT / 128), 256, GEMM_SMEM>>>(
            pfhi, pflo, wgh + (size_t)l * Dd * II, wgl + (size_t)l * Dd * II,
            fcp_b + (size_t)l * Dd, ph, nullptr, nullptr, MT, Dd, II);
    }
    ln_kernel<false><<<MT, 256>>>(ph, lnf_w, lnf_b, out, nullptr, nullptr);
}

// round 5
// speedup vs baseline: 2.2757x; 1.0878x over previous
#include <cuda_runtime.h>
#include <cuda_bf16.h>
#include <math.h>
#include <stdint.h>

#define Bb 2
#define Tt 2048
#define Dd 1024
#define Hh 16
#define Ll 8
#define II 4096
#define HD 64
#define MASK_BIAS -10000.0f
#define LN_EPS 1e-5f

// ================= scratch =================
__device__ float g_h[Bb * Tt * Dd];
__device__ float g_qkv[Bb * Tt * 3 * Dd];
__device__ __nv_bfloat16 g_xhi[Bb * Tt * Dd], g_xlo[Bb * Tt * Dd];
__device__ __nv_bfloat16 g_ctxhi[Bb * Tt * Dd], g_ctxlo[Bb * Tt * Dd];
__device__ __nv_bfloat16 g_ffhi[Bb * Tt * II], g_fflo[Bb * Tt * II];
// transposed weight slabs [L][N][K]
__device__ __nv_bfloat16 g_wqkv_hi[Ll * 3 * Dd * Dd], g_wqkv_lo[Ll * 3 * Dd * Dd];
__device__ __nv_bfloat16 g_wproj_hi[Ll * Dd * Dd], g_wproj_lo[Ll * Dd * Dd];
__device__ __nv_bfloat16 g_wfc_hi[Ll * II * Dd], g_wfc_lo[Ll * II * Dd];
__device__ __nv_bfloat16 g_wfcp_hi[Ll * Dd * II], g_wfcp_lo[Ll * Dd * II];

__device__ __forceinline__ uint32_t smem_u32(const void* p) {
    uint32_t a;
    asm("{ .reg .u64 t; cvta.to.shared.u64 t, %1; cvt.u32.u64 %0, t; }" : "=r"(a) : "l"(p));
    return a;
}
__device__ __forceinline__ void ldsm4(uint32_t* r, uint32_t addr) {
    asm volatile("ldmatrix.sync.aligned.m8n8.x4.shared.b16 {%0,%1,%2,%3}, [%4];"
                 : "=r"(r[0]), "=r"(r[1]), "=r"(r[2]), "=r"(r[3]) : "r"(addr));
}
__device__ __forceinline__ void mma_bf16(float* d, const uint32_t* a, uint32_t b0, uint32_t b1) {
    asm volatile("mma.sync.aligned.m16n8k16.row.col.f32.bf16.bf16.f32 "
                 "{%0,%1,%2,%3}, {%4,%5,%6,%7}, {%8,%9}, {%0,%1,%2,%3};"
                 : "+f"(d[0]), "+f"(d[1]), "+f"(d[2]), "+f"(d[3])
                 : "r"(a[0]), "r"(a[1]), "r"(a[2]), "r"(a[3]), "r"(b0), "r"(b1));
}
__device__ __forceinline__ uint32_t packbf(float x, float y) {
    __nv_bfloat162 t = __floats2bfloat162_rn(x, y);
    return *reinterpret_cast<uint32_t*>(&t);
}

// ================= small kernels =================
__global__ void copy_kernel(const float* __restrict__ src) {
    int i = blockIdx.x * blockDim.x + threadIdx.x;
    reinterpret_cast<float4*>(g_h)[i] = reinterpret_cast<const float4*>(src)[i];
}

__global__ void wconv_kernel(const float* __restrict__ W, __nv_bfloat16* __restrict__ Whi,
                             __nv_bfloat16* __restrict__ Wlo, int K, int N) {
    __shared__ float s[32][33];
    int n0 = blockIdx.x * 32, k0 = blockIdx.y * 32;
    int tx = threadIdx.x & 31, ty = threadIdx.x >> 5;
#pragma unroll
    for (int i = 0; i < 4; i++)
        s[ty + i * 8][tx] = W[(size_t)(k0 + ty + i * 8) * N + n0 + tx];
    __syncthreads();
#pragma unroll
    for (int i = 0; i < 4; i++) {
        int n = ty + i * 8;
        float v = s[tx][n];
        __nv_bfloat16 hi = __float2bfloat16(v);
        size_t idx = (size_t)(n0 + n) * K + k0 + tx;
        Whi[idx] = hi;
        Wlo[idx] = __float2bfloat16(v - __bfloat162float(hi));
    }
}

template <bool HILO>
__global__ void ln_kernel(const float* __restrict__ x, const float* __restrict__ w,
                          const float* __restrict__ b, float* __restrict__ out,
                          __nv_bfloat16* __restrict__ ohi, __nv_bfloat16* __restrict__ olo) {
    int row = blockIdx.x;
    int tid = threadIdx.x;
    const float* xr = x + (size_t)row * Dd;
    float v[4];
    float sum = 0.f, sq = 0.f;
#pragma unroll
    for (int u = 0; u < 4; u++) {
        v[u] = xr[tid + u * 256];
        sum += v[u];
        sq += v[u] * v[u];
    }
#pragma unroll
    for (int o = 16; o > 0; o >>= 1) {
        sum += __shfl_xor_sync(0xffffffffu, sum, o);
        sq += __shfl_xor_sync(0xffffffffu, sq, o);
    }
    __shared__ float ssum[8], ssq[8], stat[2];
    if ((tid & 31) == 0) { ssum[tid >> 5] = sum; ssq[tid >> 5] = sq; }
    __syncthreads();
    if (tid == 0) {
        float S = 0.f, Q = 0.f;
#pragma unroll
        for (int i = 0; i < 8; i++) { S += ssum[i]; Q += ssq[i]; }
        float mean = S * (1.0f / Dd);
        float var = Q * (1.0f / Dd) - mean * mean;
        stat[0] = mean;
        stat[1] = rsqrtf(var + LN_EPS);
    }
    __syncthreads();
    float mean = stat[0], rstd = stat[1];
#pragma unroll
    for (int u = 0; u < 4; u++) {
        int c = tid + u * 256;
        float y = (v[u] - mean) * rstd * w[c] + b[c];
        if (HILO) {
            __nv_bfloat16 hi = __float2bfloat16(y);
            ohi[(size_t)row * Dd + c] = hi;
            olo[(size_t)row * Dd + c] = __float2bfloat16(y - __bfloat162float(hi));
        } else {
            out[(size_t)row * Dd + c] = y;
        }
    }
}

// ================= HMMA GEMM (3-stage, 2 CTAs/SM, 1 barrier/chunk) =================
#define PITCHB 80
#define TILE_BYTES (128 * PITCHB)
#define STAGE_BYTES (2 * TILE_BYTES)
#define GEMM_SMEM (3 * STAGE_BYTES)

template <bool RELU, bool RESID, bool OUTHILO>
__global__ void __launch_bounds__(256, 2)
gemm_mma(const __nv_bfloat16* __restrict__ Ahi, const __nv_bfloat16* __restrict__ Alo,
         const __nv_bfloat16* __restrict__ Whi, const __nv_bfloat16* __restrict__ Wlo,
         const float* __restrict__ bias, float* __restrict__ C,
         __nv_bfloat16* __restrict__ Chi, __nv_bfloat16* __restrict__ Clo,
         int M, int N, int K) {
    extern __shared__ char smem[];
    uint32_t sb = smem_u32(smem);
    int tid = threadIdx.x, wid = tid >> 5, lane = tid & 31;
    int warp_m = wid & 1, warp_n = wid >> 1;
    int row0 = blockIdx.y * 128, col0 = blockIdx.x * 128;

    const int KC = K >> 5;
    const int NC = 3 * KC;

    float acc[4][4][4];
#pragma unroll
    for (int i = 0; i < 4; i++)
#pragma unroll
        for (int j = 0; j < 4; j++)
#pragma unroll
            for (int q = 0; q < 4; q++) acc[i][j][q] = 0.f;

    // hoisted copy source/dest offsets
    int isB = tid >> 7;                    // first 128 threads: A, rest: B (x2 per j-iter)
    // per-thread copy mapping (1024 txns of 16B over 4 iters of 256 threads)
    // per-warp ldsm base offsets (within a stage)
    uint32_t a_off = (warp_m * 64 + (lane & 15)) * PITCHB + ((lane >> 4) << 4);
    uint32_t b_off = (warp_n * 32 + (lane & 7) + ((lane >> 4) << 3)) * PITCHB + (((lane >> 3) & 1) << 4);

    auto issue = [&](int c) {
        int p = c / KC;
        int k0 = (c - p * KC) << 5;
        const __nv_bfloat16* A = (p == 2) ? Alo : Ahi;
        const __nv_bfloat16* Bw = (p == 1) ? Wlo : Whi;
        uint32_t base = sb + (c % 3) * STAGE_BYTES;
#pragma unroll
        for (int j = 0; j < 4; j++) {
            int lin = j * 256 + tid;
            int ib = lin >> 9;
            int l2 = lin & 511;
            int r = l2 >> 2, seg = l2 & 3;
            const void* g = ib ? (const void*)(Bw + (size_t)(col0 + r) * K + k0 + seg * 8)
                               : (const void*)(A + (size_t)(row0 + r) * K + k0 + seg * 8);
            uint32_t s = base + ib * TILE_BYTES + r * PITCHB + seg * 16;
            asm volatile("cp.async.cg.shared.global [%0], [%1], 16;" :: "r"(s), "l"(g));
        }
        asm volatile("cp.async.commit_group;" ::: "memory");
    };

    issue(0);
    issue(1);
    for (int c = 0; c < NC; c++) {
        if (c + 1 < NC) {
            asm volatile("cp.async.wait_group 1;" ::: "memory");
        } else {
            asm volatile("cp.async.wait_group 0;" ::: "memory");
        }
        __syncthreads();
        if (c + 2 < NC) issue(c + 2);
        uint32_t abase = sb + (c % 3) * STAGE_BYTES;
        uint32_t bbase = abase + TILE_BYTES;
#pragma unroll
        for (int ks = 0; ks < 2; ks++) {
            uint32_t a[4][4];
#pragma unroll
            for (int mt = 0; mt < 4; mt++)
                ldsm4(a[mt], abase + a_off + mt * (16 * PITCHB) + ks * 32);
            uint32_t b[2][4];
#pragma unroll
            for (int bt = 0; bt < 2; bt++)
                ldsm4(b[bt], bbase + b_off + bt * (16 * PITCHB) + ks * 32);
#pragma unroll
            for (int mt = 0; mt < 4; mt++)
#pragma unroll
                for (int nt = 0; nt < 4; nt++)
                    mma_bf16(acc[mt][nt], a[mt], b[nt >> 1][(nt & 1) * 2], b[nt >> 1][(nt & 1) * 2 + 1]);
        }
    }

    int rin = lane >> 2;
    int colp = (lane & 3) * 2;
#pragma unroll
    for (int mt = 0; mt < 4; mt++) {
#pragma unroll
        for (int half = 0; half < 2; half++) {
            int r = row0 + warp_m * 64 + mt * 16 + rin + half * 8;
            size_t rowoff = (size_t)r * N;
#pragma unroll
            for (int nt = 0; nt < 4; nt++) {
                int cg = col0 + warp_n * 32 + nt * 8 + colp;
                float v0 = acc[mt][nt][half * 2 + 0] + bias[cg];
                float v1 = acc[mt][nt][half * 2 + 1] + bias[cg + 1];
                if (RELU) { v0 = fmaxf(v0, 0.f); v1 = fmaxf(v1, 0.f); }
                if (RESID) {
                    float2 o = *(const float2*)&C[rowoff + cg];
                    v0 += o.x; v1 += o.y;
                }
                if (OUTHILO) {
                    union { __nv_bfloat16 h[2]; uint32_t u; } ph, pl;
                    ph.h[0] = __float2bfloat16(v0);
                    ph.h[1] = __float2bfloat16(v1);
                    pl.h[0] = __float2bfloat16(v0 - __bfloat162float(ph.h[0]));
                    pl.h[1] = __float2bfloat16(v1 - __bfloat162float(ph.h[1]));
                    *(uint32_t*)&Chi[rowoff + cg] = ph.u;
                    *(uint32_t*)&Clo[rowoff + cg] = pl.u;
                } else {
                    *(float2*)&C[rowoff + cg] = make_float2(v0, v1);
                }
            }
        }
    }
}

// ================= HMMA flash attention (compensated bf16) =================
#define AQP 72
#define SM_QHI 0
#define SM_QLO 18432
#define SM_KHI 36864
#define SM_KLO 46080
#define SM_VHI 55296
#define SM_VLO 64512
#define SM_AM  73728
#define ATTN_SMEM (73728 + 256)

__global__ void __launch_bounds__(256, 2)
attn_mma(const float* __restrict__ qkv, const float* __restrict__ amask,
         __nv_bfloat16* __restrict__ ctxhi, __nv_bfloat16* __restrict__ ctxlo) {
    extern __shared__ char sm[];
    uint32_t sb = smem_u32(sm);
    float* AM = (float*)(sm + SM_AM);
    int tid = threadIdx.x, wid = tid >> 5, lane = tid & 31;
    int i0 = blockIdx.x * 128;
    int b = blockIdx.y >> 4, h = blockIdx.y & 15;
    const float* base = qkv + (size_t)b * Tt * 3 * Dd + h * HD;

#pragma unroll
    for (int i = 0; i < 8; i++) {
        int idx = i * 256 + tid;
        int r = idx >> 4, c = (idx & 15) * 4;
        float4 v = *(const float4*)(base + (size_t)(i0 + r) * 3 * Dd + c);
        union { __nv_bfloat16 bb[4]; uint2 u; } H, L;
        float vv[4] = {v.x, v.y, v.z, v.w};
#pragma unroll
        for (int u = 0; u < 4; u++) {
            H.bb[u] = __float2bfloat16(vv[u]);
            L.bb[u] = __float2bfloat16(vv[u] - __bfloat162float(H.bb[u]));
        }
        *(uint2*)(sm + SM_QHI + (r * AQP + c) * 2) = H.u;
        *(uint2*)(sm + SM_QLO + (r * AQP + c) * 2) = L.u;
    }

    float o[8][4];
#pragma unroll
    for (int i = 0; i < 8; i++)
#pragma unroll
        for (int q = 0; q < 4; q++) o[i][q] = 0.f;
    float m_run[2] = {-1e30f, -1e30f}, l_run[2] = {0.f, 0.f};

    int r0 = lane >> 2;
    int cq = (lane & 3) * 2;
    int qrow0 = i0 + wid * 16 + r0;

    int ntiles = i0 / 64 + 2;
    for (int jt = 0; jt < ntiles; jt++) {
        int j0 = jt * 64;
        bool diag = (j0 + 63 > i0);
        __syncthreads();
#pragma unroll
        for (int i = 0; i < 4; i++) {
            int idx = i * 256 + tid;
            int r = idx >> 4, c = (idx & 15) * 4;
            float4 v = *(const float4*)(base + Dd + (size_t)(j0 + r) * 3 * Dd + c);
            union { __nv_bfloat16 bb[4]; uint2 u; } H, L;
            float vv[4] = {v.x, v.y, v.z, v.w};
#pragma unroll
            for (int u = 0; u < 4; u++) {
                H.bb[u] = __float2bfloat16(vv[u]);
                L.bb[u] = __float2bfloat16(vv[u] - __bfloat162float(H.bb[u]));
            }
            *(uint2*)(sm + SM_KHI + (r * AQP + c) * 2) = H.u;
            *(uint2*)(sm + SM_KLO + (r * AQP + c) * 2) = L.u;
        }
#pragma unroll
        for (int i = 0; i < 4; i++) {
            int idx = i * 256 + tid;
            int n = idx >> 4, c = (idx & 15) * 4;
            float4 v = *(const float4*)(base + 2 * Dd + (size_t)(j0 + n) * 3 * Dd + c);
            float vv[4] = {v.x, v.y, v.z, v.w};
#pragma unroll
            for (int u = 0; u < 4; u++) {
                __nv_bfloat16 hi = __float2bfloat16(vv[u]);
                __nv_bfloat16 lo = __float2bfloat16(vv[u] - __bfloat162float(hi));
                *(__nv_bfloat16*)(sm + SM_VHI + ((c + u) * AQP + n) * 2) = hi;
                *(__nv_bfloat16*)(sm + SM_VLO + ((c + u) * AQP + n) * 2) = lo;
            }
        }
        if (tid < 64) AM[tid] = (1.0f - amask[b * Tt + j0 + tid]) * MASK_BIAS;
        __syncthreads();

        float sf[8][4];
#pragma unroll
        for (int i = 0; i < 8; i++)
#pragma unroll
            for (int q = 0; q < 4; q++) sf[i][q] = 0.f;
#pragma unroll
        for (int pass = 0; pass < 3; pass++) {
            uint32_t qb = sb + (pass == 2 ? SM_QLO : SM_QHI);
            uint32_t kb = sb + (pass == 1 ? SM_KLO : SM_KHI);
#pragma unroll
            for (int s = 0; s < 4; s++) {
                uint32_t a[4];
                ldsm4(a, qb + (wid * 16 + (lane & 15)) * 144 + s * 32 + ((lane >> 4) << 4));
#pragma unroll
                for (int p2 = 0; p2 < 4; p2++) {
                    uint32_t bbq[4];
                    ldsm4(bbq, kb + (p2 * 16 + (lane & 7) + ((lane >> 4) << 3)) * 144 + s * 32 + (((lane >> 3) & 1) << 4));
                    mma_bf16(sf[p2 * 2], a, bbq[0], bbq[1]);
                    mma_bf16(sf[p2 * 2 + 1], a, bbq[2], bbq[3]);
                }
            }
        }

#pragma unroll
        for (int nt = 0; nt < 8; nt++) {
#pragma unroll
            for (int q = 0; q < 4; q++) {
                int col = nt * 8 + cq + (q & 1);
                float val = sf[nt][q] * 0.125f;
                if (diag && (j0 + col) > (qrow0 + (q >> 1) * 8)) val = MASK_BIAS;
                sf[nt][q] = val + AM[col];
            }
        }

        float alpha[2];
#pragma unroll
        for (int rh = 0; rh < 2; rh++) {
            float mt = -1e30f;
#pragma unroll
            for (int nt = 0; nt < 8; nt++)
                mt = fmaxf(mt, fmaxf(sf[nt][rh * 2], sf[nt][rh * 2 + 1]));
            mt = fmaxf(mt, __shfl_xor_sync(0xffffffffu, mt, 1));
            mt = fmaxf(mt, __shfl_xor_sync(0xffffffffu, mt, 2));
            float mnew = fmaxf(m_run[rh], mt);
            alpha[rh] = __expf(m_run[rh] - mnew);
            m_run[rh] = mnew;
            float ls = 0.f;
#pragma unroll
            for (int nt = 0; nt < 8; nt++) {
                sf[nt][rh * 2] = __expf(sf[nt][rh * 2] - mnew);
                sf[nt][rh * 2 + 1] = __expf(sf[nt][rh * 2 + 1] - mnew);
                ls += sf[nt][rh * 2] + sf[nt][rh * 2 + 1];
            }
            ls += __shfl_xor_sync(0xffffffffu, ls, 1);
            ls += __shfl_xor_sync(0xffffffffu, ls, 2);
            l_run[rh] = l_run[rh] * alpha[rh] + ls;
        }
#pragma unroll
        for (int nt = 0; nt < 8; nt++) {
            o[nt][0] *= alpha[0]; o[nt][1] *= alpha[0];
            o[nt][2] *= alpha[1]; o[nt][3] *= alpha[1];
        }

#pragma unroll
        for (int s2 = 0; s2 < 4; s2++) {
            float p0 = sf[2 * s2][0], p1 = sf[2 * s2][1], p2v = sf[2 * s2][2], p3 = sf[2 * s2][3];
            float q0 = sf[2 * s2 + 1][0], q1 = sf[2 * s2 + 1][1], q2 = sf[2 * s2 + 1][2], q3 = sf[2 * s2 + 1][3];
            uint32_t phi[4], plo[4];
            phi[0] = packbf(p0, p1); phi[1] = packbf(p2v, p3);
            phi[2] = packbf(q0, q1); phi[3] = packbf(q2, q3);
            {
                __nv_bfloat162 t;
                t = *(__nv_bfloat162*)&phi[0];
                plo[0] = packbf(p0 - __low2float(t), p1 - __high2float(t));
                t = *(__nv_bfloat162*)&phi[1];
                plo[1] = packbf(p2v - __low2float(t), p3 - __high2float(t));
                t = *(__nv_bfloat162*)&phi[2];
                plo[2] = packbf(q0 - __low2float(t), q1 - __high2float(t));
                t = *(__nv_bfloat162*)&phi[3];
                plo[3] = packbf(q2 - __low2float(t), q3 - __high2float(t));
            }
#pragma unroll
            for (int p2 = 0; p2 < 4; p2++) {
                uint32_t vrow = (p2 * 16 + (lane & 7) + ((lane >> 4) << 3)) * 144 + s2 * 32 + (((lane >> 3) & 1) << 4);
                uint32_t bh[4], bl[4];
                ldsm4(bh, sb + SM_VHI + vrow);
                ldsm4(bl, sb + SM_VLO + vrow);
                mma_bf16(o[p2 * 2], phi, bh[0], bh[1]);
                mma_bf16(o[p2 * 2 + 1], phi, bh[2], bh[3]);
                mma_bf16(o[p2 * 2], phi, bl[0], bl[1]);
                mma_bf16(o[p2 * 2 + 1], phi, bl[2], bl[3]);
                mma_bf16(o[p2 * 2], plo, bh[0], bh[1]);
                mma_bf16(o[p2 * 2 + 1], plo, bh[2], bh[3]);
            }
        }
    }

    float inv[2] = {1.f / l_run[0], 1.f / l_run[1]};
#pragma unroll
    for (int nt = 0; nt < 8; nt++) {
        int d0 = nt * 8 + cq;
#pragma unroll
        for (int rh = 0; rh < 2; rh++) {
            int row = i0 + wid * 16 + r0 + rh * 8;
            float x = o[nt][rh * 2] * inv[rh];
            float y = o[nt][rh * 2 + 1] * inv[rh];
            uint32_t hu = packbf(x, y);
            __nv_bfloat162 t = *(__nv_bfloat162*)&hu;
            uint32_t lu = packbf(x - __low2float(t), y - __high2float(t));
            size_t off = (size_t)(b * Tt + row) * Dd + h * HD + d0;
            *(uint32_t*)&ctxhi[off] = hu;
            *(uint32_t*)&ctxlo[off] = lu;
        }
    }
}

// ================= host launcher =================
extern "C" void kernel_launch(void* const* d_in, const int* in_sizes, int n_in,
                              void* d_out, int out_size) {
    const float* inputs_embeds = (const float*)d_in[0];
    const float* attention_mask = (const float*)d_in[1];
    const float* ln1_w = (const float*)d_in[2];
    const float* ln1_b = (const float*)d_in[3];
    const float* attn_w = (const float*)d_in[4];
    const float* attn_b = (const float*)d_in[5];
    const float* proj_w = (const float*)d_in[6];
    const float* proj_b = (const float*)d_in[7];
    const float* ln2_w = (const float*)d_in[8];
    const float* ln2_b = (const float*)d_in[9];
    const float* fc_w = (const float*)d_in[10];
    const float* fc_b = (const float*)d_in[11];
    const float* fcp_w = (const float*)d_in[12];
    const float* fcp_b = (const float*)d_in[13];
    const float* lnf_w = (const float*)d_in[14];
    const float* lnf_b = (const float*)d_in[15];
    float* out = (float*)d_out;

    cudaFuncSetAttribute(attn_mma, cudaFuncAttributeMaxDynamicSharedMemorySize, ATTN_SMEM);
    cudaFuncSetAttribute(gemm_mma<false, false, false>, cudaFuncAttributeMaxDynamicSharedMemorySize, GEMM_SMEM);
    cudaFuncSetAttribute(gemm_mma<false, true, false>, cudaFuncAttributeMaxDynamicSharedMemorySize, GEMM_SMEM);
    cudaFuncSetAttribute(gemm_mma<true, false, true>, cudaFuncAttributeMaxDynamicSharedMemorySize, GEMM_SMEM);

    float *ph, *pqkv;
    __nv_bfloat16 *pxhi, *pxlo, *pchi, *pclo, *pfhi, *pflo;
    __nv_bfloat16 *wqh, *wql, *wph, *wpl, *wfh, *wfl, *wgh, *wgl;
    cudaGetSymbolAddress((void**)&ph, g_h);
    cudaGetSymbolAddress((void**)&pqkv, g_qkv);
    cudaGetSymbolAddress((void**)&pxhi, g_xhi);
    cudaGetSymbolAddress((void**)&pxlo, g_xlo);
    cudaGetSymbolAddress((void**)&pchi, g_ctxhi);
    cudaGetSymbolAddress((void**)&pclo, g_ctxlo);
    cudaGetSymbolAddress((void**)&pfhi, g_ffhi);
    cudaGetSymbolAddress((void**)&pflo, g_fflo);
    cudaGetSymbolAddress((void**)&wqh, g_wqkv_hi);
    cudaGetSymbolAddress((void**)&wql, g_wqkv_lo);
    cudaGetSymbolAddress((void**)&wph, g_wproj_hi);
    cudaGetSymbolAddress((void**)&wpl, g_wproj_lo);
    cudaGetSymbolAddress((void**)&wfh, g_wfc_hi);
    cudaGetSymbolAddress((void**)&wfl, g_wfc_lo);
    cudaGetSymbolAddress((void**)&wgh, g_wfcp_hi);
    cudaGetSymbolAddress((void**)&wgl, g_wfcp_lo);

    const int MT = Bb * Tt;

    copy_kernel<<<(MT * Dd / 4) / 256, 256>>>(inputs_embeds);

    for (int l = 0; l < Ll; l++) {
        wconv_kernel<<<dim3(3 * Dd / 32, Dd / 32), 256>>>(
            attn_w + (size_t)l * Dd * 3 * Dd, wqh + (size_t)l * 3 * Dd * Dd, wql + (size_t)l * 3 * Dd * Dd, Dd, 3 * Dd);
        wconv_kernel<<<dim3(Dd / 32, Dd / 32), 256>>>(
            proj_w + (size_t)l * Dd * Dd, wph + (size_t)l * Dd * Dd, wpl + (size_t)l * Dd * Dd, Dd, Dd);
        wconv_kernel<<<dim3(II / 32, Dd / 32), 256>>>(
            fc_w + (size_t)l * Dd * II, wfh + (size_t)l * II * Dd, wfl + (size_t)l * II * Dd, Dd, II);
        wconv_kernel<<<dim3(Dd / 32, II / 32), 256>>>(
            fcp_w + (size_t)l * II * Dd, wgh + (size_t)l * Dd * II, wgl + (size_t)l * Dd * II, II, Dd);
    }

    for (int l = 0; l < Ll; l++) {
        ln_kernel<true><<<MT, 256>>>(ph, ln1_w + (size_t)l * Dd, ln1_b + (size_t)l * Dd, nullptr, pxhi, pxlo);
        gemm_mma<false, false, false><<<dim3(3 * Dd / 128, MT / 128), 256, GEMM_SMEM>>>(
            pxhi, pxlo, wqh + (size_t)l * 3 * Dd * Dd, wql + (size_t)l * 3 * Dd * Dd,
            attn_b + (size_t)l * 3 * Dd, pqkv, nullptr, nullptr, MT, 3 * Dd, Dd);
        attn_mma<<<dim3(Tt / 128, Bb * Hh), 256, ATTN_SMEM>>>(pqkv, attention_mask, pchi, pclo);
        gemm_mma<false, true, false><<<dim3(Dd / 128, MT / 128), 256, GEMM_SMEM>>>(
            pchi, pclo, wph + (size_t)l * Dd * Dd, wpl + (size_t)l * Dd * Dd,
            proj_b + (size_t)l * Dd, ph, nullptr, nullptr, MT, Dd, Dd);
        ln_kernel<true><<<MT, 256>>>(ph, ln2_w + (size_t)l * Dd, ln2_b + (size_t)l * Dd, nullptr, pxhi, pxlo);
        gemm_mma<true, false, true><<<dim3(II / 128, MT / 128), 256, GEMM_SMEM>>>(
            pxhi, pxlo, wfh + (size_t)l * II * Dd, wfl + (size_t)l * II * Dd,
            fc_b + (size_t)l * II, nullptr, pfhi, pflo, MT, II, Dd);
        gemm_mma<false, true, false><<<dim3(Dd / 128, MT / 128), 256, GEMM_SMEM>>>(
            pfhi, pflo, wgh + (size_t)l * Dd * II, wgl + (size_t)l * Dd * II,
            fcp_b + (size_t)l * Dd, ph, nullptr, nullptr, MT, Dd, II);
    }
    ln_kernel<false><<<MT, 256>>>(ph, lnf_w, lnf_b, out, nullptr, nullptr);
}

// round 6
// speedup vs baseline: 2.5229x; 1.1086x over previous
#include <cuda_runtime.h>
#include <cuda_bf16.h>
#include <math.h>
#include <stdint.h>

#define Bb 2
#define Tt 2048
#define Dd 1024
#define Hh 16
#define Ll 8
#define II 4096
#define HD 64
#define MASK_BIAS -10000.0f
#define LN_EPS 1e-5f

// ================= scratch =================
__device__ float g_h[Bb * Tt * Dd];
__device__ float g_qkv[Bb * Tt * 3 * Dd];
__device__ __nv_bfloat16 g_xhi[Bb * Tt * Dd], g_xlo[Bb * Tt * Dd];
__device__ __nv_bfloat16 g_ctxhi[Bb * Tt * Dd], g_ctxlo[Bb * Tt * Dd];
__device__ __nv_bfloat16 g_ffhi[Bb * Tt * II], g_fflo[Bb * Tt * II];
// transposed weight slabs [L][N][K]
__device__ __nv_bfloat16 g_wqkv_hi[Ll * 3 * Dd * Dd], g_wqkv_lo[Ll * 3 * Dd * Dd];
__device__ __nv_bfloat16 g_wproj_hi[Ll * Dd * Dd], g_wproj_lo[Ll * Dd * Dd];
__device__ __nv_bfloat16 g_wfc_hi[Ll * II * Dd], g_wfc_lo[Ll * II * Dd];
__device__ __nv_bfloat16 g_wfcp_hi[Ll * Dd * II], g_wfcp_lo[Ll * Dd * II];

__device__ __forceinline__ uint32_t smem_u32(const void* p) {
    uint32_t a;
    asm("{ .reg .u64 t; cvta.to.shared.u64 t, %1; cvt.u32.u64 %0, t; }" : "=r"(a) : "l"(p));
    return a;
}
__device__ __forceinline__ void ldsm4(uint32_t* r, uint32_t addr) {
    asm volatile("ldmatrix.sync.aligned.m8n8.x4.shared.b16 {%0,%1,%2,%3}, [%4];"
                 : "=r"(r[0]), "=r"(r[1]), "=r"(r[2]), "=r"(r[3]) : "r"(addr));
}
__device__ __forceinline__ void mma_bf16(float* d, const uint32_t* a, uint32_t b0, uint32_t b1) {
    asm volatile("mma.sync.aligned.m16n8k16.row.col.f32.bf16.bf16.f32 "
                 "{%0,%1,%2,%3}, {%4,%5,%6,%7}, {%8,%9}, {%0,%1,%2,%3};"
                 : "+f"(d[0]), "+f"(d[1]), "+f"(d[2]), "+f"(d[3])
                 : "r"(a[0]), "r"(a[1]), "r"(a[2]), "r"(a[3]), "r"(b0), "r"(b1));
}
__device__ __forceinline__ uint32_t packbf(float x, float y) {
    __nv_bfloat162 t = __floats2bfloat162_rn(x, y);
    return *reinterpret_cast<uint32_t*>(&t);
}

// ================= small kernels =================
__global__ void copy_kernel(const float* __restrict__ src) {
    int i = blockIdx.x * blockDim.x + threadIdx.x;
    reinterpret_cast<float4*>(g_h)[i] = reinterpret_cast<const float4*>(src)[i];
}

__global__ void wconv_kernel(const float* __restrict__ W, __nv_bfloat16* __restrict__ Whi,
                             __nv_bfloat16* __restrict__ Wlo, int K, int N) {
    __shared__ float s[32][33];
    int n0 = blockIdx.x * 32, k0 = blockIdx.y * 32;
    int tx = threadIdx.x & 31, ty = threadIdx.x >> 5;
#pragma unroll
    for (int i = 0; i < 4; i++)
        s[ty + i * 8][tx] = W[(size_t)(k0 + ty + i * 8) * N + n0 + tx];
    __syncthreads();
#pragma unroll
    for (int i = 0; i < 4; i++) {
        int n = ty + i * 8;
        float v = s[tx][n];
        __nv_bfloat16 hi = __float2bfloat16(v);
        size_t idx = (size_t)(n0 + n) * K + k0 + tx;
        Whi[idx] = hi;
        Wlo[idx] = __float2bfloat16(v - __bfloat162float(hi));
    }
}

template <bool HILO>
__global__ void ln_kernel(const float* __restrict__ x, const float* __restrict__ w,
                          const float* __restrict__ b, float* __restrict__ out,
                          __nv_bfloat16* __restrict__ ohi, __nv_bfloat16* __restrict__ olo) {
    int row = blockIdx.x;
    int tid = threadIdx.x;
    const float* xr = x + (size_t)row * Dd;
    float v[4];
    float sum = 0.f, sq = 0.f;
#pragma unroll
    for (int u = 0; u < 4; u++) {
        v[u] = xr[tid + u * 256];
        sum += v[u];
        sq += v[u] * v[u];
    }
#pragma unroll
    for (int o = 16; o > 0; o >>= 1) {
        sum += __shfl_xor_sync(0xffffffffu, sum, o);
        sq += __shfl_xor_sync(0xffffffffu, sq, o);
    }
    __shared__ float ssum[8], ssq[8], stat[2];
    if ((tid & 31) == 0) { ssum[tid >> 5] = sum; ssq[tid >> 5] = sq; }
    __syncthreads();
    if (tid == 0) {
        float S = 0.f, Q = 0.f;
#pragma unroll
        for (int i = 0; i < 8; i++) { S += ssum[i]; Q += ssq[i]; }
        float mean = S * (1.0f / Dd);
        float var = Q * (1.0f / Dd) - mean * mean;
        stat[0] = mean;
        stat[1] = rsqrtf(var + LN_EPS);
    }
    __syncthreads();
    float mean = stat[0], rstd = stat[1];
#pragma unroll
    for (int u = 0; u < 4; u++) {
        int c = tid + u * 256;
        float y = (v[u] - mean) * rstd * w[c] + b[c];
        if (HILO) {
            __nv_bfloat16 hi = __float2bfloat16(y);
            ohi[(size_t)row * Dd + c] = hi;
            olo[(size_t)row * Dd + c] = __float2bfloat16(y - __bfloat162float(hi));
        } else {
            out[(size_t)row * Dd + c] = y;
        }
    }
}

// ================= HMMA GEMM (fused 3-pass, 2-stage, 2 CTAs/SM) =================
// Stage = {Ahi, Alo, Whi, Wlo} tiles of 128 x 32 bf16, pitch 80B.
#define PITCHB 80
#define TILE_BYTES (128 * PITCHB)            // 10240
#define STAGE_BYTES (4 * TILE_BYTES)         // 40960
#define GEMM_SMEM (2 * STAGE_BYTES)          // 81920

template <bool RELU, bool RESID, bool OUTHILO>
__global__ void __launch_bounds__(256, 2)
gemm_mma(const __nv_bfloat16* __restrict__ Ahi, const __nv_bfloat16* __restrict__ Alo,
         const __nv_bfloat16* __restrict__ Whi, const __nv_bfloat16* __restrict__ Wlo,
         const float* __restrict__ bias, float* __restrict__ C,
         __nv_bfloat16* __restrict__ Chi, __nv_bfloat16* __restrict__ Clo,
         int M, int N, int K) {
    extern __shared__ char smem[];
    uint32_t sb = smem_u32(smem);
    int tid = threadIdx.x, wid = tid >> 5, lane = tid & 31;
    int warp_m = wid & 1, warp_n = wid >> 1;
    int row0 = blockIdx.y * 128, col0 = blockIdx.x * 128;

    const int KC = K >> 5;   // 32-wide chunks

    float acc[4][4][4];
#pragma unroll
    for (int i = 0; i < 4; i++)
#pragma unroll
        for (int j = 0; j < 4; j++)
#pragma unroll
            for (int q = 0; q < 4; q++) acc[i][j][q] = 0.f;

    uint32_t a_off = (warp_m * 64 + (lane & 15)) * PITCHB + ((lane >> 4) << 4);
    uint32_t b_off = (warp_n * 32 + (lane & 7) + ((lane >> 4) << 3)) * PITCHB + (((lane >> 3) & 1) << 4);

    auto issue = [&](int c) {
        int k0 = c << 5;
        uint32_t base = sb + (c & 1) * STAGE_BYTES;
#pragma unroll
        for (int j = 0; j < 8; j++) {
            int lin = j * 256 + tid;           // 0..2047
            int tile = lin >> 9;               // 0:Ahi 1:Alo 2:Whi 3:Wlo
            int l2 = lin & 511;
            int r = l2 >> 2, seg = l2 & 3;
            const __nv_bfloat16* src;
            if (tile == 0)      src = Ahi + (size_t)(row0 + r) * K;
            else if (tile == 1) src = Alo + (size_t)(row0 + r) * K;
            else if (tile == 2) src = Whi + (size_t)(col0 + r) * K;
            else                src = Wlo + (size_t)(col0 + r) * K;
            const void* g = src + k0 + seg * 8;
            uint32_t s = base + tile * TILE_BYTES + r * PITCHB + seg * 16;
            asm volatile("cp.async.cg.shared.global [%0], [%1], 16;" :: "r"(s), "l"(g));
        }
        asm volatile("cp.async.commit_group;" ::: "memory");
    };

    issue(0);
    if (KC > 1) issue(1);
    for (int c = 0; c < KC; c++) {
        if (c + 1 < KC) {
            asm volatile("cp.async.wait_group 1;" ::: "memory");
        } else {
            asm volatile("cp.async.wait_group 0;" ::: "memory");
        }
        __syncthreads();
        uint32_t stage = sb + (c & 1) * STAGE_BYTES;
        uint32_t ahi_b = stage;
        uint32_t alo_b = stage + TILE_BYTES;
        uint32_t whi_b = stage + 2 * TILE_BYTES;
        uint32_t wlo_b = stage + 3 * TILE_BYTES;
#pragma unroll
        for (int ks = 0; ks < 2; ks++) {
            uint32_t bhi[2][4], blo[2][4];
#pragma unroll
            for (int bt = 0; bt < 2; bt++) {
                ldsm4(bhi[bt], whi_b + b_off + bt * (16 * PITCHB) + ks * 32);
                ldsm4(blo[bt], wlo_b + b_off + bt * (16 * PITCHB) + ks * 32);
            }
#pragma unroll
            for (int mt = 0; mt < 4; mt++) {
                uint32_t ah[4], al[4];
                ldsm4(ah, ahi_b + a_off + mt * (16 * PITCHB) + ks * 32);
                ldsm4(al, alo_b + a_off + mt * (16 * PITCHB) + ks * 32);
#pragma unroll
                for (int nt = 0; nt < 4; nt++) {
                    uint32_t h0 = bhi[nt >> 1][(nt & 1) * 2], h1 = bhi[nt >> 1][(nt & 1) * 2 + 1];
                    mma_bf16(acc[mt][nt], ah, h0, h1);
                    mma_bf16(acc[mt][nt], ah, blo[nt >> 1][(nt & 1) * 2], blo[nt >> 1][(nt & 1) * 2 + 1]);
                    mma_bf16(acc[mt][nt], al, h0, h1);
                }
            }
        }
        __syncthreads();
        if (c + 2 < KC) issue(c + 2);
    }

    int rin = lane >> 2;
    int colp = (lane & 3) * 2;
#pragma unroll
    for (int mt = 0; mt < 4; mt++) {
#pragma unroll
        for (int half = 0; half < 2; half++) {
            int r = row0 + warp_m * 64 + mt * 16 + rin + half * 8;
            size_t rowoff = (size_t)r * N;
#pragma unroll
            for (int nt = 0; nt < 4; nt++) {
                int cg = col0 + warp_n * 32 + nt * 8 + colp;
                float v0 = acc[mt][nt][half * 2 + 0] + bias[cg];
                float v1 = acc[mt][nt][half * 2 + 1] + bias[cg + 1];
                if (RELU) { v0 = fmaxf(v0, 0.f); v1 = fmaxf(v1, 0.f); }
                if (RESID) {
                    float2 o = *(const float2*)&C[rowoff + cg];
                    v0 += o.x; v1 += o.y;
                }
                if (OUTHILO) {
                    union { __nv_bfloat16 h[2]; uint32_t u; } ph, pl;
                    ph.h[0] = __float2bfloat16(v0);
                    ph.h[1] = __float2bfloat16(v1);
                    pl.h[0] = __float2bfloat16(v0 - __bfloat162float(ph.h[0]));
                    pl.h[1] = __float2bfloat16(v1 - __bfloat162float(ph.h[1]));
                    *(uint32_t*)&Chi[rowoff + cg] = ph.u;
                    *(uint32_t*)&Clo[rowoff + cg] = pl.u;
                } else {
                    *(float2*)&C[rowoff + cg] = make_float2(v0, v1);
                }
            }
        }
    }
}

// ================= HMMA flash attention (compensated bf16) =================
#define AQP 72
#define SM_QHI 0
#define SM_QLO 18432
#define SM_KHI 36864
#define SM_KLO 46080
#define SM_VHI 55296
#define SM_VLO 64512
#define SM_AM  73728
#define ATTN_SMEM (73728 + 256)

__global__ void __launch_bounds__(256, 2)
attn_mma(const float* __restrict__ qkv, const float* __restrict__ amask,
         __nv_bfloat16* __restrict__ ctxhi, __nv_bfloat16* __restrict__ ctxlo) {
    extern __shared__ char sm[];
    uint32_t sb = smem_u32(sm);
    float* AM = (float*)(sm + SM_AM);
    int tid = threadIdx.x, wid = tid >> 5, lane = tid & 31;
    int i0 = blockIdx.x * 128;
    int b = blockIdx.y >> 4, h = blockIdx.y & 15;
    const float* base = qkv + (size_t)b * Tt * 3 * Dd + h * HD;

#pragma unroll
    for (int i = 0; i < 8; i++) {
        int idx = i * 256 + tid;
        int r = idx >> 4, c = (idx & 15) * 4;
        float4 v = *(const float4*)(base + (size_t)(i0 + r) * 3 * Dd + c);
        union { __nv_bfloat16 bb[4]; uint2 u; } H, L;
        float vv[4] = {v.x, v.y, v.z, v.w};
#pragma unroll
        for (int u = 0; u < 4; u++) {
            H.bb[u] = __float2bfloat16(vv[u]);
            L.bb[u] = __float2bfloat16(vv[u] - __bfloat162float(H.bb[u]));
        }
        *(uint2*)(sm + SM_QHI + (r * AQP + c) * 2) = H.u;
        *(uint2*)(sm + SM_QLO + (r * AQP + c) * 2) = L.u;
    }

    float o[8][4];
#pragma unroll
    for (int i = 0; i < 8; i++)
#pragma unroll
        for (int q = 0; q < 4; q++) o[i][q] = 0.f;
    float m_run[2] = {-1e30f, -1e30f}, l_run[2] = {0.f, 0.f};

    int r0 = lane >> 2;
    int cq = (lane & 3) * 2;
    int qrow0 = i0 + wid * 16 + r0;

    int ntiles = i0 / 64 + 2;
    for (int jt = 0; jt < ntiles; jt++) {
        int j0 = jt * 64;
        bool diag = (j0 + 63 > i0);
        __syncthreads();
#pragma unroll
        for (int i = 0; i < 4; i++) {
            int idx = i * 256 + tid;
            int r = idx >> 4, c = (idx & 15) * 4;
            float4 v = *(const float4*)(base + Dd + (size_t)(j0 + r) * 3 * Dd + c);
            union { __nv_bfloat16 bb[4]; uint2 u; } H, L;
            float vv[4] = {v.x, v.y, v.z, v.w};
#pragma unroll
            for (int u = 0; u < 4; u++) {
                H.bb[u] = __float2bfloat16(vv[u]);
                L.bb[u] = __float2bfloat16(vv[u] - __bfloat162float(H.bb[u]));
            }
            *(uint2*)(sm + SM_KHI + (r * AQP + c) * 2) = H.u;
            *(uint2*)(sm + SM_KLO + (r * AQP + c) * 2) = L.u;
        }
#pragma unroll
        for (int i = 0; i < 4; i++) {
            int idx = i * 256 + tid;
            int n = idx >> 4, c = (idx & 15) * 4;
            float4 v = *(const float4*)(base + 2 * Dd + (size_t)(j0 + n) * 3 * Dd + c);
            float vv[4] = {v.x, v.y, v.z, v.w};
#pragma unroll
            for (int u = 0; u < 4; u++) {
                __nv_bfloat16 hi = __float2bfloat16(vv[u]);
                __nv_bfloat16 lo = __float2bfloat16(vv[u] - __bfloat162float(hi));
                *(__nv_bfloat16*)(sm + SM_VHI + ((c + u) * AQP + n) * 2) = hi;
                *(__nv_bfloat16*)(sm + SM_VLO + ((c + u) * AQP + n) * 2) = lo;
            }
        }
        if (tid < 64) AM[tid] = (1.0f - amask[b * Tt + j0 + tid]) * MASK_BIAS;
        __syncthreads();

        float sf[8][4];
#pragma unroll
        for (int i = 0; i < 8; i++)
#pragma unroll
            for (int q = 0; q < 4; q++) sf[i][q] = 0.f;
#pragma unroll
        for (int pass = 0; pass < 3; pass++) {
            uint32_t qb = sb + (pass == 2 ? SM_QLO : SM_QHI);
            uint32_t kb = sb + (pass == 1 ? SM_KLO : SM_KHI);
#pragma unroll
            for (int s = 0; s < 4; s++) {
                uint32_t a[4];
                ldsm4(a, qb + (wid * 16 + (lane & 15)) * 144 + s * 32 + ((lane >> 4) << 4));
#pragma unroll
                for (int p2 = 0; p2 < 4; p2++) {
                    uint32_t bbq[4];
                    ldsm4(bbq, kb + (p2 * 16 + (lane & 7) + ((lane >> 4) << 3)) * 144 + s * 32 + (((lane >> 3) & 1) << 4));
                    mma_bf16(sf[p2 * 2], a, bbq[0], bbq[1]);
                    mma_bf16(sf[p2 * 2 + 1], a, bbq[2], bbq[3]);
                }
            }
        }

#pragma unroll
        for (int nt = 0; nt < 8; nt++) {
#pragma unroll
            for (int q = 0; q < 4; q++) {
                int col = nt * 8 + cq + (q & 1);
                float val = sf[nt][q] * 0.125f;
                if (diag && (j0 + col) > (qrow0 + (q >> 1) * 8)) val = MASK_BIAS;
                sf[nt][q] = val + AM[col];
            }
        }

        float alpha[2];
#pragma unroll
        for (int rh = 0; rh < 2; rh++) {
            float mt = -1e30f;
#pragma unroll
            for (int nt = 0; nt < 8; nt++)
                mt = fmaxf(mt, fmaxf(sf[nt][rh * 2], sf[nt][rh * 2 + 1]));
            mt = fmaxf(mt, __shfl_xor_sync(0xffffffffu, mt, 1));
            mt = fmaxf(mt, __shfl_xor_sync(0xffffffffu, mt, 2));
            float mnew = fmaxf(m_run[rh], mt);
            alpha[rh] = __expf(m_run[rh] - mnew);
            m_run[rh] = mnew;
            float ls = 0.f;
#pragma unroll
            for (int nt = 0; nt < 8; nt++) {
                sf[nt][rh * 2] = __expf(sf[nt][rh * 2] - mnew);
                sf[nt][rh * 2 + 1] = __expf(sf[nt][rh * 2 + 1] - mnew);
                ls += sf[nt][rh * 2] + sf[nt][rh * 2 + 1];
            }
            ls += __shfl_xor_sync(0xffffffffu, ls, 1);
            ls += __shfl_xor_sync(0xffffffffu, ls, 2);
            l_run[rh] = l_run[rh] * alpha[rh] + ls;
        }
#pragma unroll
        for (int nt = 0; nt < 8; nt++) {
            o[nt][0] *= alpha[0]; o[nt][1] *= alpha[0];
            o[nt][2] *= alpha[1]; o[nt][3] *= alpha[1];
        }

#pragma unroll
        for (int s2 = 0; s2 < 4; s2++) {
            float p0 = sf[2 * s2][0], p1 = sf[2 * s2][1], p2v = sf[2 * s2][2], p3 = sf[2 * s2][3];
            float q0 = sf[2 * s2 + 1][0], q1 = sf[2 * s2 + 1][1], q2 = sf[2 * s2 + 1][2], q3 = sf[2 * s2 + 1][3];
            uint32_t phi[4], plo[4];
            phi[0] = packbf(p0, p1); phi[1] = packbf(p2v, p3);
            phi[2] = packbf(q0, q1); phi[3] = packbf(q2, q3);
            {
                __nv_bfloat162 t;
                t = *(__nv_bfloat162*)&phi[0];
                plo[0] = packbf(p0 - __low2float(t), p1 - __high2float(t));
                t = *(__nv_bfloat162*)&phi[1];
                plo[1] = packbf(p2v - __low2float(t), p3 - __high2float(t));
                t = *(__nv_bfloat162*)&phi[2];
                plo[2] = packbf(q0 - __low2float(t), q1 - __high2float(t));
                t = *(__nv_bfloat162*)&phi[3];
                plo[3] = packbf(q2 - __low2float(t), q3 - __high2float(t));
            }
#pragma unroll
            for (int p2 = 0; p2 < 4; p2++) {
                uint32_t vrow = (p2 * 16 + (lane & 7) + ((lane >> 4) << 3)) * 144 + s2 * 32 + (((lane >> 3) & 1) << 4);
                uint32_t bh[4], bl[4];
                ldsm4(bh, sb + SM_VHI + vrow);
                ldsm4(bl, sb + SM_VLO + vrow);
                mma_bf16(o[p2 * 2], phi, bh[0], bh[1]);
                mma_bf16(o[p2 * 2 + 1], phi, bh[2], bh[3]);
                mma_bf16(o[p2 * 2], phi, bl[0], bl[1]);
                mma_bf16(o[p2 * 2 + 1], phi, bl[2], bl[3]);
                mma_bf16(o[p2 * 2], plo, bh[0], bh[1]);
                mma_bf16(o[p2 * 2 + 1], plo, bh[2], bh[3]);
            }
        }
    }

    float inv[2] = {1.f / l_run[0], 1.f / l_run[1]};
#pragma unroll
    for (int nt = 0; nt < 8; nt++) {
        int d0 = nt * 8 + cq;
#pragma unroll
        for (int rh = 0; rh < 2; rh++) {
            int row = i0 + wid * 16 + r0 + rh * 8;
            float x = o[nt][rh * 2] * inv[rh];
            float y = o[nt][rh * 2 + 1] * inv[rh];
            uint32_t hu = packbf(x, y);
            __nv_bfloat162 t = *(__nv_bfloat162*)&hu;
            uint32_t lu = packbf(x - __low2float(t), y - __high2float(t));
            size_t off = (size_t)(b * Tt + row) * Dd + h * HD + d0;
            *(uint32_t*)&ctxhi[off] = hu;
            *(uint32_t*)&ctxlo[off] = lu;
        }
    }
}

// ================= host launcher =================
extern "C" void kernel_launch(void* const* d_in, const int* in_sizes, int n_in,
                              void* d_out, int out_size) {
    const float* inputs_embeds = (const float*)d_in[0];
    const float* attention_mask = (const float*)d_in[1];
    const float* ln1_w = (const float*)d_in[2];
    const float* ln1_b = (const float*)d_in[3];
    const float* attn_w = (const float*)d_in[4];
    const float* attn_b = (const float*)d_in[5];
    const float* proj_w = (const float*)d_in[6];
    const float* proj_b = (const float*)d_in[7];
    const float* ln2_w = (const float*)d_in[8];
    const float* ln2_b = (const float*)d_in[9];
    const float* fc_w = (const float*)d_in[10];
    const float* fc_b = (const float*)d_in[11];
    const float* fcp_w = (const float*)d_in[12];
    const float* fcp_b = (const float*)d_in[13];
    const float* lnf_w = (const float*)d_in[14];
    const float* lnf_b = (const float*)d_in[15];
    float* out = (float*)d_out;

    cudaFuncSetAttribute(attn_mma, cudaFuncAttributeMaxDynamicSharedMemorySize, ATTN_SMEM);
    cudaFuncSetAttribute(gemm_mma<false, false, false>, cudaFuncAttributeMaxDynamicSharedMemorySize, GEMM_SMEM);
    cudaFuncSetAttribute(gemm_mma<false, true, false>, cudaFuncAttributeMaxDynamicSharedMemorySize, GEMM_SMEM);
    cudaFuncSetAttribute(gemm_mma<true, false, true>, cudaFuncAttributeMaxDynamicSharedMemorySize, GEMM_SMEM);

    float *ph, *pqkv;
    __nv_bfloat16 *pxhi, *pxlo, *pchi, *pclo, *pfhi, *pflo;
    __nv_bfloat16 *wqh, *wql, *wph, *wpl, *wfh, *wfl, *wgh, *wgl;
    cudaGetSymbolAddress((void**)&ph, g_h);
    cudaGetSymbolAddress((void**)&pqkv, g_qkv);
    cudaGetSymbolAddress((void**)&pxhi, g_xhi);
    cudaGetSymbolAddress((void**)&pxlo, g_xlo);
    cudaGetSymbolAddress((void**)&pchi, g_ctxhi);
    cudaGetSymbolAddress((void**)&pclo, g_ctxlo);
    cudaGetSymbolAddress((void**)&pfhi, g_ffhi);
    cudaGetSymbolAddress((void**)&pflo, g_fflo);
    cudaGetSymbolAddress((void**)&wqh, g_wqkv_hi);
    cudaGetSymbolAddress((void**)&wql, g_wqkv_lo);
    cudaGetSymbolAddress((void**)&wph, g_wproj_hi);
    cudaGetSymbolAddress((void**)&wpl, g_wproj_lo);
    cudaGetSymbolAddress((void**)&wfh, g_wfc_hi);
    cudaGetSymbolAddress((void**)&wfl, g_wfc_lo);
    cudaGetSymbolAddress((void**)&wgh, g_wfcp_hi);
    cudaGetSymbolAddress((void**)&wgl, g_wfcp_lo);

    const int MT = Bb * Tt;

    copy_kernel<<<(MT * Dd / 4) / 256, 256>>>(inputs_embeds);

    for (int l = 0; l < Ll; l++) {
        wconv_kernel<<<dim3(3 * Dd / 32, Dd / 32), 256>>>(
            attn_w + (size_t)l * Dd * 3 * Dd, wqh + (size_t)l * 3 * Dd * Dd, wql + (size_t)l * 3 * Dd * Dd, Dd, 3 * Dd);
        wconv_kernel<<<dim3(Dd / 32, Dd / 32), 256>>>(
            proj_w + (size_t)l * Dd * Dd, wph + (size_t)l * Dd * Dd, wpl + (size_t)l * Dd * Dd, Dd, Dd);
        wconv_kernel<<<dim3(II / 32, Dd / 32), 256>>>(
            fc_w + (size_t)l * Dd * II, wfh + (size_t)l * II * Dd, wfl + (size_t)l * II * Dd, Dd, II);
        wconv_kernel<<<dim3(Dd / 32, II / 32), 256>>>(
            fcp_w + (size_t)l * II * Dd, wgh + (size_t)l * Dd * II, wgl + (size_t)l * Dd * II, II, Dd);
    }

    for (int l = 0; l < Ll; l++) {
        ln_kernel<true><<<MT, 256>>>(ph, ln1_w + (size_t)l * Dd, ln1_b + (size_t)l * Dd, nullptr, pxhi, pxlo);
        gemm_mma<false, false, false><<<dim3(3 * Dd / 128, MT / 128), 256, GEMM_SMEM>>>(
            pxhi, pxlo, wqh + (size_t)l * 3 * Dd * Dd, wql + (size_t)l * 3 * Dd * Dd,
            attn_b + (size_t)l * 3 * Dd, pqkv, nullptr, nullptr, MT, 3 * Dd, Dd);
        attn_mma<<<dim3(Tt / 128, Bb * Hh), 256, ATTN_SMEM>>>(pqkv, attention_mask, pchi, pclo);
        gemm_mma<false, true, false><<<dim3(Dd / 128, MT / 128), 256, GEMM_SMEM>>>(
            pchi, pclo, wph + (size_t)l * Dd * Dd, wpl + (size_t)l * Dd * Dd,
            proj_b + (size_t)l * Dd, ph, nullptr, nullptr, MT, Dd, Dd);
        ln_kernel<true><<<MT, 256>>>(ph, ln2_w + (size_t)l * Dd, ln2_b + (size_t)l * Dd, nullptr, pxhi, pxlo);
        gemm_mma<true, false, true><<<dim3(II / 128, MT / 128), 256, GEMM_SMEM>>>(
            pxhi, pxlo, wfh + (size_t)l * II * Dd, wfl + (size_t)l * II * Dd,
            fc_b + (size_t)l * II, nullptr, pfhi, pflo, MT, II, Dd);
        gemm_mma<false, true, false><<<dim3(Dd / 128, MT / 128), 256, GEMM_SMEM>>>(
            pfhi, pflo, wgh + (size_t)l * Dd * II, wgl + (size_t)l * Dd * II,
            fcp_b + (size_t)l * Dd, ph, nullptr, nullptr, MT, Dd, II);
    }
    ln_kernel<false><<<MT, 256>>>(ph, lnf_w, lnf_b, out, nullptr, nullptr);
}

// round 7
// speedup vs baseline: 2.5627x; 1.0158x over previous
#include <cuda_runtime.h>
#include <cuda_bf16.h>
#include <math.h>
#include <stdint.h>

#define Bb 2
#define Tt 2048
#define Dd 1024
#define Hh 16
#define Ll 8
#define II 4096
#define HD 64
#define MASK_BIAS -10000.0f
#define LN_EPS 1e-5f

// ================= scratch =================
__device__ float g_h[Bb * Tt * Dd];
__device__ __nv_bfloat16 g_qkvhi[Bb * Tt * 3 * Dd], g_qkvlo[Bb * Tt * 3 * Dd];
__device__ __nv_bfloat16 g_xhi[Bb * Tt * Dd], g_xlo[Bb * Tt * Dd];
__device__ __nv_bfloat16 g_ctxhi[Bb * Tt * Dd], g_ctxlo[Bb * Tt * Dd];
__device__ __nv_bfloat16 g_ffhi[Bb * Tt * II], g_fflo[Bb * Tt * II];
__device__ __nv_bfloat16 g_wqkv_hi[Ll * 3 * Dd * Dd], g_wqkv_lo[Ll * 3 * Dd * Dd];
__device__ __nv_bfloat16 g_wproj_hi[Ll * Dd * Dd], g_wproj_lo[Ll * Dd * Dd];
__device__ __nv_bfloat16 g_wfc_hi[Ll * II * Dd], g_wfc_lo[Ll * II * Dd];
__device__ __nv_bfloat16 g_wfcp_hi[Ll * Dd * II], g_wfcp_lo[Ll * Dd * II];

__device__ __forceinline__ uint32_t smem_u32(const void* p) {
    uint32_t a;
    asm("{ .reg .u64 t; cvta.to.shared.u64 t, %1; cvt.u32.u64 %0, t; }" : "=r"(a) : "l"(p));
    return a;
}
__device__ __forceinline__ void ldsm4(uint32_t* r, uint32_t addr) {
    asm volatile("ldmatrix.sync.aligned.m8n8.x4.shared.b16 {%0,%1,%2,%3}, [%4];"
                 : "=r"(r[0]), "=r"(r[1]), "=r"(r[2]), "=r"(r[3]) : "r"(addr));
}
__device__ __forceinline__ void ldsm4t(uint32_t* r, uint32_t addr) {
    asm volatile("ldmatrix.sync.aligned.m8n8.x4.trans.shared.b16 {%0,%1,%2,%3}, [%4];"
                 : "=r"(r[0]), "=r"(r[1]), "=r"(r[2]), "=r"(r[3]) : "r"(addr));
}
__device__ __forceinline__ void mma_bf16(float* d, const uint32_t* a, uint32_t b0, uint32_t b1) {
    asm volatile("mma.sync.aligned.m16n8k16.row.col.f32.bf16.bf16.f32 "
                 "{%0,%1,%2,%3}, {%4,%5,%6,%7}, {%8,%9}, {%0,%1,%2,%3};"
                 : "+f"(d[0]), "+f"(d[1]), "+f"(d[2]), "+f"(d[3])
                 : "r"(a[0]), "r"(a[1]), "r"(a[2]), "r"(a[3]), "r"(b0), "r"(b1));
}
__device__ __forceinline__ uint32_t packbf(float x, float y) {
    __nv_bfloat162 t = __floats2bfloat162_rn(x, y);
    return *reinterpret_cast<uint32_t*>(&t);
}
__device__ __forceinline__ void cpa16(uint32_t s, const void* g) {
    asm volatile("cp.async.cg.shared.global [%0], [%1], 16;" :: "r"(s), "l"(g));
}

// ================= small kernels =================
__global__ void copy_kernel(const float* __restrict__ src) {
    int i = blockIdx.x * blockDim.x + threadIdx.x;
    reinterpret_cast<float4*>(g_h)[i] = reinterpret_cast<const float4*>(src)[i];
}

__global__ void wconv_kernel(const float* __restrict__ W, __nv_bfloat16* __restrict__ Whi,
                             __nv_bfloat16* __restrict__ Wlo, int K, int N) {
    __shared__ float s[32][33];
    int n0 = blockIdx.x * 32, k0 = blockIdx.y * 32;
    int tx = threadIdx.x & 31, ty = threadIdx.x >> 5;
#pragma unroll
    for (int i = 0; i < 4; i++)
        s[ty + i * 8][tx] = W[(size_t)(k0 + ty + i * 8) * N + n0 + tx];
    __syncthreads();
#pragma unroll
    for (int i = 0; i < 4; i++) {
        int n = ty + i * 8;
        float v = s[tx][n];
        __nv_bfloat16 hi = __float2bfloat16(v);
        size_t idx = (size_t)(n0 + n) * K + k0 + tx;
        Whi[idx] = hi;
        Wlo[idx] = __float2bfloat16(v - __bfloat162float(hi));
    }
}

template <bool HILO>
__global__ void ln_kernel(const float* __restrict__ x, const float* __restrict__ w,
                          const float* __restrict__ b, float* __restrict__ out,
                          __nv_bfloat16* __restrict__ ohi, __nv_bfloat16* __restrict__ olo) {
    int row = blockIdx.x;
    int tid = threadIdx.x;
    const float* xr = x + (size_t)row * Dd;
    float v[4];
    float sum = 0.f, sq = 0.f;
#pragma unroll
    for (int u = 0; u < 4; u++) {
        v[u] = xr[tid + u * 256];
        sum += v[u];
        sq += v[u] * v[u];
    }
#pragma unroll
    for (int o = 16; o > 0; o >>= 1) {
        sum += __shfl_xor_sync(0xffffffffu, sum, o);
        sq += __shfl_xor_sync(0xffffffffu, sq, o);
    }
    __shared__ float ssum[8], ssq[8], stat[2];
    if ((tid & 31) == 0) { ssum[tid >> 5] = sum; ssq[tid >> 5] = sq; }
    __syncthreads();
    if (tid == 0) {
        float S = 0.f, Q = 0.f;
#pragma unroll
        for (int i = 0; i < 8; i++) { S += ssum[i]; Q += ssq[i]; }
        float mean = S * (1.0f / Dd);
        float var = Q * (1.0f / Dd) - mean * mean;
        stat[0] = mean;
        stat[1] = rsqrtf(var + LN_EPS);
    }
    __syncthreads();
    float mean = stat[0], rstd = stat[1];
#pragma unroll
    for (int u = 0; u < 4; u++) {
        int c = tid + u * 256;
        float y = (v[u] - mean) * rstd * w[c] + b[c];
        if (HILO) {
            __nv_bfloat16 hi = __float2bfloat16(y);
            ohi[(size_t)row * Dd + c] = hi;
            olo[(size_t)row * Dd + c] = __float2bfloat16(y - __bfloat162float(hi));
        } else {
            out[(size_t)row * Dd + c] = y;
        }
    }
}

// ================= HMMA GEMM (fused 3-pass, 2-stage, 2 CTAs/SM) =================
#define PITCHB 80
#define TILE_BYTES (128 * PITCHB)
#define STAGE_BYTES (4 * TILE_BYTES)
#define GEMM_SMEM (2 * STAGE_BYTES)

template <bool RELU, bool RESID, bool OUTHILO>
__global__ void __launch_bounds__(256, 2)
gemm_mma(const __nv_bfloat16* __restrict__ Ahi, const __nv_bfloat16* __restrict__ Alo,
         const __nv_bfloat16* __restrict__ Whi, const __nv_bfloat16* __restrict__ Wlo,
         const float* __restrict__ bias, float* __restrict__ C,
         __nv_bfloat16* __restrict__ Chi, __nv_bfloat16* __restrict__ Clo,
         int M, int N, int K) {
    extern __shared__ char smem[];
    uint32_t sb = smem_u32(smem);
    int tid = threadIdx.x, wid = tid >> 5, lane = tid & 31;
    int warp_m = wid & 1, warp_n = wid >> 1;
    int row0 = blockIdx.y * 128, col0 = blockIdx.x * 128;

    const int KC = K >> 5;

    float acc[4][4][4];
#pragma unroll
    for (int i = 0; i < 4; i++)
#pragma unroll
        for (int j = 0; j < 4; j++)
#pragma unroll
            for (int q = 0; q < 4; q++) acc[i][j][q] = 0.f;

    uint32_t a_off = (warp_m * 64 + (lane & 15)) * PITCHB + ((lane >> 4) << 4);
    uint32_t b_off = (warp_n * 32 + (lane & 7) + ((lane >> 4) << 3)) * PITCHB + (((lane >> 3) & 1) << 4);

    auto issue = [&](int c) {
        int k0 = c << 5;
        uint32_t base = sb + (c & 1) * STAGE_BYTES;
#pragma unroll
        for (int j = 0; j < 8; j++) {
            int lin = j * 256 + tid;
            int tile = lin >> 9;
            int l2 = lin & 511;
            int r = l2 >> 2, seg = l2 & 3;
            const __nv_bfloat16* src;
            if (tile == 0)      src = Ahi + (size_t)(row0 + r) * K;
            else if (tile == 1) src = Alo + (size_t)(row0 + r) * K;
            else if (tile == 2) src = Whi + (size_t)(col0 + r) * K;
            else                src = Wlo + (size_t)(col0 + r) * K;
            cpa16(base + tile * TILE_BYTES + r * PITCHB + seg * 16, src + k0 + seg * 8);
        }
        asm volatile("cp.async.commit_group;" ::: "memory");
    };

    issue(0);
    if (KC > 1) issue(1);
    for (int c = 0; c < KC; c++) {
        if (c + 1 < KC) {
            asm volatile("cp.async.wait_group 1;" ::: "memory");
        } else {
            asm volatile("cp.async.wait_group 0;" ::: "memory");
        }
        __syncthreads();
        uint32_t stage = sb + (c & 1) * STAGE_BYTES;
        uint32_t ahi_b = stage;
        uint32_t alo_b = stage + TILE_BYTES;
        uint32_t whi_b = stage + 2 * TILE_BYTES;
        uint32_t wlo_b = stage + 3 * TILE_BYTES;
#pragma unroll
        for (int ks = 0; ks < 2; ks++) {
            uint32_t bhi[2][4], blo[2][4];
#pragma unroll
            for (int bt = 0; bt < 2; bt++) {
                ldsm4(bhi[bt], whi_b + b_off + bt * (16 * PITCHB) + ks * 32);
                ldsm4(blo[bt], wlo_b + b_off + bt * (16 * PITCHB) + ks * 32);
            }
#pragma unroll
            for (int mt = 0; mt < 4; mt++) {
                uint32_t ah[4], al[4];
                ldsm4(ah, ahi_b + a_off + mt * (16 * PITCHB) + ks * 32);
                ldsm4(al, alo_b + a_off + mt * (16 * PITCHB) + ks * 32);
#pragma unroll
                for (int nt = 0; nt < 4; nt++) {
                    uint32_t h0 = bhi[nt >> 1][(nt & 1) * 2], h1 = bhi[nt >> 1][(nt & 1) * 2 + 1];
                    mma_bf16(acc[mt][nt], ah, h0, h1);
                    mma_bf16(acc[mt][nt], ah, blo[nt >> 1][(nt & 1) * 2], blo[nt >> 1][(nt & 1) * 2 + 1]);
                    mma_bf16(acc[mt][nt], al, h0, h1);
                }
            }
        }
        __syncthreads();
        if (c + 2 < KC) issue(c + 2);
    }

    int rin = lane >> 2;
    int colp = (lane & 3) * 2;
#pragma unroll
    for (int mt = 0; mt < 4; mt++) {
#pragma unroll
        for (int half = 0; half < 2; half++) {
            int r = row0 + warp_m * 64 + mt * 16 + rin + half * 8;
            size_t rowoff = (size_t)r * N;
#pragma unroll
            for (int nt = 0; nt < 4; nt++) {
                int cg = col0 + warp_n * 32 + nt * 8 + colp;
                float v0 = acc[mt][nt][half * 2 + 0] + bias[cg];
                float v1 = acc[mt][nt][half * 2 + 1] + bias[cg + 1];
                if (RELU) { v0 = fmaxf(v0, 0.f); v1 = fmaxf(v1, 0.f); }
                if (RESID) {
                    float2 o = *(const float2*)&C[rowoff + cg];
                    v0 += o.x; v1 += o.y;
                }
                if (OUTHILO) {
                    union { __nv_bfloat16 h[2]; uint32_t u; } ph, pl;
                    ph.h[0] = __float2bfloat16(v0);
                    ph.h[1] = __float2bfloat16(v1);
                    pl.h[0] = __float2bfloat16(v0 - __bfloat162float(ph.h[0]));
                    pl.h[1] = __float2bfloat16(v1 - __bfloat162float(ph.h[1]));
                    *(uint32_t*)&Chi[rowoff + cg] = ph.u;
                    *(uint32_t*)&Clo[rowoff + cg] = pl.u;
                } else {
                    *(float2*)&C[rowoff + cg] = make_float2(v0, v1);
                }
            }
        }
    }
}

// ================= HMMA flash attention (bf16 hi/lo inputs, cp.async double-buffered) =================
// smem: Qhi[128x64] Qlo | 2 x {Khi, Klo, Vhi, Vlo}[64x64], pitch 144B
#define APB 144
#define SM_QHI 0
#define SM_QLO 18432
#define SM_KV  36864
#define KVBUF  36864   // per buffer: 4 tiles x 9216
#define KVT    9216
#define ATTN_SMEM (36864 + 2 * KVBUF)

__global__ void __launch_bounds__(256, 2)
attn_mma(const __nv_bfloat16* __restrict__ qkvhi, const __nv_bfloat16* __restrict__ qkvlo,
         const float* __restrict__ amask,
         __nv_bfloat16* __restrict__ ctxhi, __nv_bfloat16* __restrict__ ctxlo) {
    extern __shared__ char sm[];
    uint32_t sb = smem_u32(sm);
    int tid = threadIdx.x, wid = tid >> 5, lane = tid & 31;
    int i0 = blockIdx.x * 128;
    int b = blockIdx.y >> 4, h = blockIdx.y & 15;
    const size_t hq = (size_t)b * Tt * 3 * Dd + h * HD;

    // Q tiles via cp.async: 2048 x 16B
#pragma unroll
    for (int j = 0; j < 8; j++) {
        int lin = j * 256 + tid;
        int sel = lin >> 10;            // 0: hi, 1: lo
        int l = lin & 1023;
        int r = l >> 3, seg = l & 7;
        const __nv_bfloat16* src = (sel ? qkvlo : qkvhi) + hq + (size_t)(i0 + r) * 3 * Dd + seg * 8;
        cpa16(sb + (sel ? SM_QLO : SM_QHI) + r * APB + seg * 16, src);
    }
    asm volatile("cp.async.commit_group;" ::: "memory");

    int ntiles = i0 / 64 + 2;

    auto issueKV = [&](int jt) {
        int j0 = jt * 64;
        uint32_t buf = sb + SM_KV + (jt & 1) * KVBUF;
#pragma unroll
        for (int j = 0; j < 8; j++) {
            int lin = j * 256 + tid;
            int t = lin >> 9;           // 0:Khi 1:Klo 2:Vhi 3:Vlo
            int l = lin & 511;
            int r = l >> 3, seg = l & 7;
            const __nv_bfloat16* basep = (t & 1) ? qkvlo : qkvhi;
            int off = (t < 2) ? Dd : 2 * Dd;
            const __nv_bfloat16* src = basep + hq + (size_t)(j0 + r) * 3 * Dd + off + seg * 8;
            cpa16(buf + t * KVT + r * APB + seg * 16, src);
        }
        asm volatile("cp.async.commit_group;" ::: "memory");
    };

    issueKV(0);

    float o[8][4];
#pragma unroll
    for (int i = 0; i < 8; i++)
#pragma unroll
        for (int q = 0; q < 4; q++) o[i][q] = 0.f;
    float m_run[2] = {-1e30f, -1e30f}, l_run[2] = {0.f, 0.f};

    int r0 = lane >> 2;
    int cq = (lane & 3) * 2;
    int qrow0 = i0 + wid * 16 + r0;
    const float* amrow = amask + b * Tt;

    uint32_t qa_off = (wid * 16 + (lane & 15)) * APB + ((lane >> 4) << 4);
    uint32_t kb_off = ((lane & 7) + ((lane >> 4) << 3)) * APB + (((lane >> 3) & 1) << 4);
    uint32_t vt_off = (lane & 15) * APB + ((lane >> 4) << 4);

    for (int jt = 0; jt < ntiles; jt++) {
        int j0 = jt * 64;
        bool diag = (j0 + 63 > i0);
        asm volatile("cp.async.wait_group 0;" ::: "memory");
        __syncthreads();
        if (jt + 1 < ntiles) issueKV(jt + 1);

        uint32_t buf = sb + SM_KV + (jt & 1) * KVBUF;
        uint32_t khi_b = buf, klo_b = buf + KVT;
        uint32_t vhi_b = buf + 2 * KVT, vlo_b = buf + 3 * KVT;

        // S = Q K^T, 3 compensated passes
        float sf[8][4];
#pragma unroll
        for (int i = 0; i < 8; i++)
#pragma unroll
            for (int q = 0; q < 4; q++) sf[i][q] = 0.f;
#pragma unroll
        for (int pass = 0; pass < 3; pass++) {
            uint32_t qb = sb + (pass == 2 ? SM_QLO : SM_QHI);
            uint32_t kb = (pass == 1 ? klo_b : khi_b);
#pragma unroll
            for (int s = 0; s < 4; s++) {
                uint32_t a[4];
                ldsm4(a, qb + qa_off + s * 32);
#pragma unroll
                for (int p2 = 0; p2 < 4; p2++) {
                    uint32_t bbq[4];
                    ldsm4(bbq, kb + kb_off + p2 * (16 * APB) + s * 32);
                    mma_bf16(sf[p2 * 2], a, bbq[0], bbq[1]);
                    mma_bf16(sf[p2 * 2 + 1], a, bbq[2], bbq[3]);
                }
            }
        }

        // scale + causal + additive mask
#pragma unroll
        for (int nt = 0; nt < 8; nt++) {
#pragma unroll
            for (int q = 0; q < 4; q++) {
                int col = nt * 8 + cq + (q & 1);
                float am = (1.0f - __ldg(amrow + j0 + col)) * MASK_BIAS;
                float val = sf[nt][q] * 0.125f;
                if (diag && (j0 + col) > (qrow0 + (q >> 1) * 8)) val = MASK_BIAS;
                sf[nt][q] = val + am;
            }
        }

        // online softmax
        float alpha[2];
#pragma unroll
        for (int rh = 0; rh < 2; rh++) {
            float mt = -1e30f;
#pragma unroll
            for (int nt = 0; nt < 8; nt++)
                mt = fmaxf(mt, fmaxf(sf[nt][rh * 2], sf[nt][rh * 2 + 1]));
            mt = fmaxf(mt, __shfl_xor_sync(0xffffffffu, mt, 1));
            mt = fmaxf(mt, __shfl_xor_sync(0xffffffffu, mt, 2));
            float mnew = fmaxf(m_run[rh], mt);
            alpha[rh] = __expf(m_run[rh] - mnew);
            m_run[rh] = mnew;
            float ls = 0.f;
#pragma unroll
            for (int nt = 0; nt < 8; nt++) {
                sf[nt][rh * 2] = __expf(sf[nt][rh * 2] - mnew);
                sf[nt][rh * 2 + 1] = __expf(sf[nt][rh * 2 + 1] - mnew);
                ls += sf[nt][rh * 2] + sf[nt][rh * 2 + 1];
            }
            ls += __shfl_xor_sync(0xffffffffu, ls, 1);
            ls += __shfl_xor_sync(0xffffffffu, ls, 2);
            l_run[rh] = l_run[rh] * alpha[rh] + ls;
        }
#pragma unroll
        for (int nt = 0; nt < 8; nt++) {
            o[nt][0] *= alpha[0]; o[nt][1] *= alpha[0];
            o[nt][2] *= alpha[1]; o[nt][3] *= alpha[1];
        }

        // PV: V row-major, B frags via ldsm.trans
#pragma unroll
        for (int s2 = 0; s2 < 4; s2++) {
            float p0 = sf[2 * s2][0], p1 = sf[2 * s2][1], p2v = sf[2 * s2][2], p3 = sf[2 * s2][3];
            float q0 = sf[2 * s2 + 1][0], q1 = sf[2 * s2 + 1][1], q2 = sf[2 * s2 + 1][2], q3 = sf[2 * s2 + 1][3];
            uint32_t phi[4], plo[4];
            phi[0] = packbf(p0, p1); phi[1] = packbf(p2v, p3);
            phi[2] = packbf(q0, q1); phi[3] = packbf(q2, q3);
            {
                __nv_bfloat162 t;
                t = *(__nv_bfloat162*)&phi[0];
                plo[0] = packbf(p0 - __low2float(t), p1 - __high2float(t));
                t = *(__nv_bfloat162*)&phi[1];
                plo[1] = packbf(p2v - __low2float(t), p3 - __high2float(t));
                t = *(__nv_bfloat162*)&phi[2];
                plo[2] = packbf(q0 - __low2float(t), q1 - __high2float(t));
                t = *(__nv_bfloat162*)&phi[3];
                plo[3] = packbf(q2 - __low2float(t), q3 - __high2float(t));
            }
#pragma unroll
            for (int p2 = 0; p2 < 4; p2++) {
                uint32_t vaddr = s2 * (16 * APB) + vt_off + p2 * 32;
                uint32_t bh[4], bl[4];
                ldsm4t(bh, vhi_b + vaddr);
                ldsm4t(bl, vlo_b + vaddr);
                mma_bf16(o[p2 * 2], phi, bh[0], bh[1]);
                mma_bf16(o[p2 * 2 + 1], phi, bh[2], bh[3]);
                mma_bf16(o[p2 * 2], phi, bl[0], bl[1]);
                mma_bf16(o[p2 * 2 + 1], phi, bl[2], bl[3]);
                mma_bf16(o[p2 * 2], plo, bh[0], bh[1]);
                mma_bf16(o[p2 * 2 + 1], plo, bh[2], bh[3]);
            }
        }
    }

    float inv[2] = {1.f / l_run[0], 1.f / l_run[1]};
#pragma unroll
    for (int nt = 0; nt < 8; nt++) {
        int d0 = nt * 8 + cq;
#pragma unroll
        for (int rh = 0; rh < 2; rh++) {
            int row = i0 + wid * 16 + r0 + rh * 8;
            float x = o[nt][rh * 2] * inv[rh];
            float y = o[nt][rh * 2 + 1] * inv[rh];
            uint32_t hu = packbf(x, y);
            __nv_bfloat162 t = *(__nv_bfloat162*)&hu;
            uint32_t lu = packbf(x - __low2float(t), y - __high2float(t));
            size_t off = (size_t)(b * Tt + row) * Dd + h * HD + d0;
            *(uint32_t*)&ctxhi[off] = hu;
            *(uint32_t*)&ctxlo[off] = lu;
        }
    }
}

// ================= host launcher =================
extern "C" void kernel_launch(void* const* d_in, const int* in_sizes, int n_in,
                              void* d_out, int out_size) {
    const float* inputs_embeds = (const float*)d_in[0];
    const float* attention_mask = (const float*)d_in[1];
    const float* ln1_w = (const float*)d_in[2];
    const float* ln1_b = (const float*)d_in[3];
    const float* attn_w = (const float*)d_in[4];
    const float* attn_b = (const float*)d_in[5];
    const float* proj_w = (const float*)d_in[6];
    const float* proj_b = (const float*)d_in[7];
    const float* ln2_w = (const float*)d_in[8];
    const float* ln2_b = (const float*)d_in[9];
    const float* fc_w = (const float*)d_in[10];
    const float* fc_b = (const float*)d_in[11];
    const float* fcp_w = (const float*)d_in[12];
    const float* fcp_b = (const float*)d_in[13];
    const float* lnf_w = (const float*)d_in[14];
    const float* lnf_b = (const float*)d_in[15];
    float* out = (float*)d_out;

    cudaFuncSetAttribute(attn_mma, cudaFuncAttributeMaxDynamicSharedMemorySize, ATTN_SMEM);
    cudaFuncSetAttribute(gemm_mma<false, false, true>, cudaFuncAttributeMaxDynamicSharedMemorySize, GEMM_SMEM);
    cudaFuncSetAttribute(gemm_mma<false, true, false>, cudaFuncAttributeMaxDynamicSharedMemorySize, GEMM_SMEM);
    cudaFuncSetAttribute(gemm_mma<true, false, true>, cudaFuncAttributeMaxDynamicSharedMemorySize, GEMM_SMEM);

    float *ph;
    __nv_bfloat16 *pqh, *pql, *pxhi, *pxlo, *pchi, *pclo, *pfhi, *pflo;
    __nv_bfloat16 *wqh, *wql, *wph, *wpl, *wfh, *wfl, *wgh, *wgl;
    cudaGetSymbolAddress((void**)&ph, g_h);
    cudaGetSymbolAddress((void**)&pqh, g_qkvhi);
    cudaGetSymbolAddress((void**)&pql, g_qkvlo);
    cudaGetSymbolAddress((void**)&pxhi, g_xhi);
    cudaGetSymbolAddress((void**)&pxlo, g_xlo);
    cudaGetSymbolAddress((void**)&pchi, g_ctxhi);
    cudaGetSymbolAddress((void**)&pclo, g_ctxlo);
    cudaGetSymbolAddress((void**)&pfhi, g_ffhi);
    cudaGetSymbolAddress((void**)&pflo, g_fflo);
    cudaGetSymbolAddress((void**)&wqh, g_wqkv_hi);
    cudaGetSymbolAddress((void**)&wql, g_wqkv_lo);
    cudaGetSymbolAddress((void**)&wph, g_wproj_hi);
    cudaGetSymbolAddress((void**)&wpl, g_wproj_lo);
    cudaGetSymbolAddress((void**)&wfh, g_wfc_hi);
    cudaGetSymbolAddress((void**)&wfl, g_wfc_lo);
    cudaGetSymbolAddress((void**)&wgh, g_wfcp_hi);
    cudaGetSymbolAddress((void**)&wgl, g_wfcp_lo);

    const int MT = Bb * Tt;

    copy_kernel<<<(MT * Dd / 4) / 256, 256>>>(inputs_embeds);

    for (int l = 0; l < Ll; l++) {
        wconv_kernel<<<dim3(3 * Dd / 32, Dd / 32), 256>>>(
            attn_w + (size_t)l * Dd * 3 * Dd, wqh + (size_t)l * 3 * Dd * Dd, wql + (size_t)l * 3 * Dd * Dd, Dd, 3 * Dd);
        wconv_kernel<<<dim3(Dd / 32, Dd / 32), 256>>>(
            proj_w + (size_t)l * Dd * Dd, wph + (size_t)l * Dd * Dd, wpl + (size_t)l * Dd * Dd, Dd, Dd);
        wconv_kernel<<<dim3(II / 32, Dd / 32), 256>>>(
            fc_w + (size_t)l * Dd * II, wfh + (size_t)l * II * Dd, wfl + (size_t)l * II * Dd, Dd, II);
        wconv_kernel<<<dim3(Dd / 32, II / 32), 256>>>(
            fcp_w + (size_t)l * II * Dd, wgh + (size_t)l * Dd * II, wgl + (size_t)l * Dd * II, II, Dd);
    }

    for (int l = 0; l < Ll; l++) {
        ln_kernel<true><<<MT, 256>>>(ph, ln1_w + (size_t)l * Dd, ln1_b + (size_t)l * Dd, nullptr, pxhi, pxlo);
        gemm_mma<false, false, true><<<dim3(3 * Dd / 128, MT / 128), 256, GEMM_SMEM>>>(
            pxhi, pxlo, wqh + (size_t)l * 3 * Dd * Dd, wql + (size_t)l * 3 * Dd * Dd,
            attn_b + (size_t)l * 3 * Dd, nullptr, pqh, pql, MT, 3 * Dd, Dd);
        attn_mma<<<dim3(Tt / 128, Bb * Hh), 256, ATTN_SMEM>>>(pqh, pql, attention_mask, pchi, pclo);
        gemm_mma<false, true, false><<<dim3(Dd / 128, MT / 128), 256, GEMM_SMEM>>>(
            pchi, pclo, wph + (size_t)l * Dd * Dd, wpl + (size_t)l * Dd * Dd,
            proj_b + (size_t)l * Dd, ph, nullptr, nullptr, MT, Dd, Dd);
        ln_kernel<true><<<MT, 256>>>(ph, ln2_w + (size_t)l * Dd, ln2_b + (size_t)l * Dd, nullptr, pxhi, pxlo);
        gemm_mma<true, false, true><<<dim3(II / 128, MT / 128), 256, GEMM_SMEM>>>(
            pxhi, pxlo, wfh + (size_t)l * II * Dd, wfl + (size_t)l * II * Dd,
            fc_b + (size_t)l * II, nullptr, pfhi, pflo, MT, II, Dd);
        gemm_mma<false, true, false><<<dim3(Dd / 128, MT / 128), 256, GEMM_SMEM>>>(
            pfhi, pflo, wgh + (size_t)l * Dd * II, wgl + (size_t)l * Dd * II,
            fcp_b + (size_t)l * Dd, ph, nullptr, nullptr, MT, Dd, II);
    }
    ln_kernel<false><<<MT, 256>>>(ph, lnf_w, lnf_b, out, nullptr, nullptr);
}

// round 8
// speedup vs baseline: 3.2671x; 1.2749x over previous
#include <cuda_runtime.h>
#include <cuda_bf16.h>
#include <cuda_fp16.h>
#include <math.h>
#include <stdint.h>

#define Bb 2
#define Tt 2048
#define Dd 1024
#define Hh 16
#define Ll 8
#define II 4096
#define HD 64
#define MASK_BIAS -10000.0f
#define LN_EPS 1e-5f
#define WSCALE 64.0f
#define WISCALE 0.015625f

// ================= scratch =================
__device__ float g_h[Bb * Tt * Dd];
__device__ __nv_bfloat16 g_qkvhi[Bb * Tt * 3 * Dd], g_qkvlo[Bb * Tt * 3 * Dd];
__device__ __half g_x16[Bb * Tt * Dd];
__device__ __half g_ctx16[Bb * Tt * Dd];
__device__ __half g_ff16[Bb * Tt * II];
// transposed, 64x-scaled fp16 weight slabs [L][N][K]
__device__ __half g_wqkv_hi[Ll * 3 * Dd * Dd], g_wqkv_lo[Ll * 3 * Dd * Dd];
__device__ __half g_wproj_hi[Ll * Dd * Dd], g_wproj_lo[Ll * Dd * Dd];
__device__ __half g_wfc_hi[Ll * II * Dd], g_wfc_lo[Ll * II * Dd];
__device__ __half g_wfcp_hi[Ll * Dd * II], g_wfcp_lo[Ll * Dd * II];

__device__ __forceinline__ uint32_t smem_u32(const void* p) {
    uint32_t a;
    asm("{ .reg .u64 t; cvta.to.shared.u64 t, %1; cvt.u32.u64 %0, t; }" : "=r"(a) : "l"(p));
    return a;
}
__device__ __forceinline__ void ldsm4(uint32_t* r, uint32_t addr) {
    asm volatile("ldmatrix.sync.aligned.m8n8.x4.shared.b16 {%0,%1,%2,%3}, [%4];"
                 : "=r"(r[0]), "=r"(r[1]), "=r"(r[2]), "=r"(r[3]) : "r"(addr));
}
__device__ __forceinline__ void ldsm4t(uint32_t* r, uint32_t addr) {
    asm volatile("ldmatrix.sync.aligned.m8n8.x4.trans.shared.b16 {%0,%1,%2,%3}, [%4];"
                 : "=r"(r[0]), "=r"(r[1]), "=r"(r[2]), "=r"(r[3]) : "r"(addr));
}
__device__ __forceinline__ void mma_bf16(float* d, const uint32_t* a, uint32_t b0, uint32_t b1) {
    asm volatile("mma.sync.aligned.m16n8k16.row.col.f32.bf16.bf16.f32 "
                 "{%0,%1,%2,%3}, {%4,%5,%6,%7}, {%8,%9}, {%0,%1,%2,%3};"
                 : "+f"(d[0]), "+f"(d[1]), "+f"(d[2]), "+f"(d[3])
                 : "r"(a[0]), "r"(a[1]), "r"(a[2]), "r"(a[3]), "r"(b0), "r"(b1));
}
__device__ __forceinline__ void mma_f16(float* d, const uint32_t* a, uint32_t b0, uint32_t b1) {
    asm volatile("mma.sync.aligned.m16n8k16.row.col.f32.f16.f16.f32 "
                 "{%0,%1,%2,%3}, {%4,%5,%6,%7}, {%8,%9}, {%0,%1,%2,%3};"
                 : "+f"(d[0]), "+f"(d[1]), "+f"(d[2]), "+f"(d[3])
                 : "r"(a[0]), "r"(a[1]), "r"(a[2]), "r"(a[3]), "r"(b0), "r"(b1));
}
__device__ __forceinline__ uint32_t packbf(float x, float y) {
    __nv_bfloat162 t = __floats2bfloat162_rn(x, y);
    return *reinterpret_cast<uint32_t*>(&t);
}
__device__ __forceinline__ void cpa16(uint32_t s, const void* g) {
    asm volatile("cp.async.cg.shared.global [%0], [%1], 16;" :: "r"(s), "l"(g));
}

// ================= small kernels =================
__global__ void copy_kernel(const float* __restrict__ src) {
    int i = blockIdx.x * blockDim.x + threadIdx.x;
    reinterpret_cast<float4*>(g_h)[i] = reinterpret_cast<const float4*>(src)[i];
}

// weight transpose + 64x-scaled fp16 hi/lo split: W[K][N] -> W'[N][K]
__global__ void wconv_kernel(const float* __restrict__ W, __half* __restrict__ Whi,
                             __half* __restrict__ Wlo, int K, int N) {
    __shared__ float s[32][33];
    int n0 = blockIdx.x * 32, k0 = blockIdx.y * 32;
    int tx = threadIdx.x & 31, ty = threadIdx.x >> 5;
#pragma unroll
    for (int i = 0; i < 4; i++)
        s[ty + i * 8][tx] = W[(size_t)(k0 + ty + i * 8) * N + n0 + tx];
    __syncthreads();
#pragma unroll
    for (int i = 0; i < 4; i++) {
        int n = ty + i * 8;
        float v = s[tx][n] * WSCALE;
        __half hi = __float2half(v);
        size_t idx = (size_t)(n0 + n) * K + k0 + tx;
        Whi[idx] = hi;
        Wlo[idx] = __float2half(v - __half2float(hi));
    }
}

// layernorm; F16OUT -> single fp16, else fp32
template <bool F16OUT>
__global__ void ln_kernel(const float* __restrict__ x, const float* __restrict__ w,
                          const float* __restrict__ b, float* __restrict__ out,
                          __half* __restrict__ o16) {
    int row = blockIdx.x;
    int tid = threadIdx.x;
    const float* xr = x + (size_t)row * Dd;
    float v[4];
    float sum = 0.f, sq = 0.f;
#pragma unroll
    for (int u = 0; u < 4; u++) {
        v[u] = xr[tid + u * 256];
        sum += v[u];
        sq += v[u] * v[u];
    }
#pragma unroll
    for (int o = 16; o > 0; o >>= 1) {
        sum += __shfl_xor_sync(0xffffffffu, sum, o);
        sq += __shfl_xor_sync(0xffffffffu, sq, o);
    }
    __shared__ float ssum[8], ssq[8], stat[2];
    if ((tid & 31) == 0) { ssum[tid >> 5] = sum; ssq[tid >> 5] = sq; }
    __syncthreads();
    if (tid == 0) {
        float S = 0.f, Q = 0.f;
#pragma unroll
        for (int i = 0; i < 8; i++) { S += ssum[i]; Q += ssq[i]; }
        float mean = S * (1.0f / Dd);
        float var = Q * (1.0f / Dd) - mean * mean;
        stat[0] = mean;
        stat[1] = rsqrtf(var + LN_EPS);
    }
    __syncthreads();
    float mean = stat[0], rstd = stat[1];
#pragma unroll
    for (int u = 0; u < 4; u++) {
        int c = tid + u * 256;
        float y = (v[u] - mean) * rstd * w[c] + b[c];
        if (F16OUT) {
            o16[(size_t)row * Dd + c] = __float2half(y);
        } else {
            out[(size_t)row * Dd + c] = y;
        }
    }
}

// ================= HMMA GEMM (fp16 2-pass, 2-stage, 2 CTAs/SM) =================
// C = A16[M,K] @ (W'hi + W'lo)^T / 64 + bias (+relu / +resid)
// OUT: 0 = fp32 C, 1 = fp16 Cf, 2 = bf16 hi/lo (Chi, Clo)
#define PITCHB 80
#define TILE_BYTES (128 * PITCHB)            // 10240
#define STAGE_BYTES (3 * TILE_BYTES)         // 30720: A, Whi, Wlo
#define GEMM_SMEM (2 * STAGE_BYTES)          // 61440

template <bool RELU, bool RESID, int OUT>
__global__ void __launch_bounds__(256, 2)
gemm_mma(const __half* __restrict__ A,
         const __half* __restrict__ Whi, const __half* __restrict__ Wlo,
         const float* __restrict__ bias, float* __restrict__ C,
         __half* __restrict__ Cf,
         __nv_bfloat16* __restrict__ Chi, __nv_bfloat16* __restrict__ Clo,
         int M, int N, int K) {
    extern __shared__ char smem[];
    uint32_t sb = smem_u32(smem);
    int tid = threadIdx.x, wid = tid >> 5, lane = tid & 31;
    int warp_m = wid & 1, warp_n = wid >> 1;
    int row0 = blockIdx.y * 128, col0 = blockIdx.x * 128;

    const int KC = K >> 5;

    float acc[4][4][4];
#pragma unroll
    for (int i = 0; i < 4; i++)
#pragma unroll
        for (int j = 0; j < 4; j++)
#pragma unroll
            for (int q = 0; q < 4; q++) acc[i][j][q] = 0.f;

    uint32_t a_off = (warp_m * 64 + (lane & 15)) * PITCHB + ((lane >> 4) << 4);
    uint32_t b_off = (warp_n * 32 + (lane & 7) + ((lane >> 4) << 3)) * PITCHB + (((lane >> 3) & 1) << 4);

    auto issue = [&](int c) {
        int k0 = c << 5;
        uint32_t base = sb + (c & 1) * STAGE_BYTES;
#pragma unroll
        for (int j = 0; j < 6; j++) {
            int lin = j * 256 + tid;          // 0..1535
            int tile = lin >> 9;              // 0:A 1:Whi 2:Wlo
            int l2 = lin & 511;
            int r = l2 >> 2, seg = l2 & 3;
            const __half* src;
            if (tile == 0)      src = A + (size_t)(row0 + r) * K;
            else if (tile == 1) src = Whi + (size_t)(col0 + r) * K;
            else                src = Wlo + (size_t)(col0 + r) * K;
            cpa16(base + tile * TILE_BYTES + r * PITCHB + seg * 16, src + k0 + seg * 8);
        }
        asm volatile("cp.async.commit_group;" ::: "memory");
    };

    issue(0);
    if (KC > 1) issue(1);
    for (int c = 0; c < KC; c++) {
        if (c + 1 < KC) {
            asm volatile("cp.async.wait_group 1;" ::: "memory");
        } else {
            asm volatile("cp.async.wait_group 0;" ::: "memory");
        }
        __syncthreads();
        uint32_t stage = sb + (c & 1) * STAGE_BYTES;
        uint32_t a_b = stage;
        uint32_t whi_b = stage + TILE_BYTES;
        uint32_t wlo_b = stage + 2 * TILE_BYTES;
#pragma unroll
        for (int ks = 0; ks < 2; ks++) {
            uint32_t bhi[2][4], blo[2][4];
#pragma unroll
            for (int bt = 0; bt < 2; bt++) {
                ldsm4(bhi[bt], whi_b + b_off + bt * (16 * PITCHB) + ks * 32);
                ldsm4(blo[bt], wlo_b + b_off + bt * (16 * PITCHB) + ks * 32);
            }
#pragma unroll
            for (int mt = 0; mt < 4; mt++) {
                uint32_t ah[4];
                ldsm4(ah, a_b + a_off + mt * (16 * PITCHB) + ks * 32);
#pragma unroll
                for (int nt = 0; nt < 4; nt++) {
                    mma_f16(acc[mt][nt], ah, bhi[nt >> 1][(nt & 1) * 2], bhi[nt >> 1][(nt & 1) * 2 + 1]);
                    mma_f16(acc[mt][nt], ah, blo[nt >> 1][(nt & 1) * 2], blo[nt >> 1][(nt & 1) * 2 + 1]);
                }
            }
        }
        __syncthreads();
        if (c + 2 < KC) issue(c + 2);
    }

    int rin = lane >> 2;
    int colp = (lane & 3) * 2;
#pragma unroll
    for (int mt = 0; mt < 4; mt++) {
#pragma unroll
        for (int half = 0; half < 2; half++) {
            int r = row0 + warp_m * 64 + mt * 16 + rin + half * 8;
            size_t rowoff = (size_t)r * N;
#pragma unroll
            for (int nt = 0; nt < 4; nt++) {
                int cg = col0 + warp_n * 32 + nt * 8 + colp;
                float v0 = acc[mt][nt][half * 2 + 0] * WISCALE + bias[cg];
                float v1 = acc[mt][nt][half * 2 + 1] * WISCALE + bias[cg + 1];
                if (RELU) { v0 = fmaxf(v0, 0.f); v1 = fmaxf(v1, 0.f); }
                if (RESID) {
                    float2 o = *(const float2*)&C[rowoff + cg];
                    v0 += o.x; v1 += o.y;
                }
                if (OUT == 0) {
                    *(float2*)&C[rowoff + cg] = make_float2(v0, v1);
                } else if (OUT == 1) {
                    __half2 hv = __floats2half2_rn(v0, v1);
                    *(uint32_t*)&Cf[rowoff + cg] = *(uint32_t*)&hv;
                } else {
                    union { __nv_bfloat16 h[2]; uint32_t u; } ph, pl;
                    ph.h[0] = __float2bfloat16(v0);
                    ph.h[1] = __float2bfloat16(v1);
                    pl.h[0] = __float2bfloat16(v0 - __bfloat162float(ph.h[0]));
                    pl.h[1] = __float2bfloat16(v1 - __bfloat162float(ph.h[1]));
                    *(uint32_t*)&Chi[rowoff + cg] = ph.u;
                    *(uint32_t*)&Clo[rowoff + cg] = pl.u;
                }
            }
        }
    }
}

// ================= HMMA flash attention (bf16 hi/lo, double-buffered) =================
#define APB 144
#define SM_QHI 0
#define SM_QLO 18432
#define SM_KV  36864
#define KVBUF  36864
#define KVT    9216
#define ATTN_SMEM (36864 + 2 * KVBUF)

__global__ void __launch_bounds__(256, 2)
attn_mma(const __nv_bfloat16* __restrict__ qkvhi, const __nv_bfloat16* __restrict__ qkvlo,
         const float* __restrict__ amask, __half* __restrict__ ctx) {
    extern __shared__ char sm[];
    uint32_t sb = smem_u32(sm);
    int tid = threadIdx.x, wid = tid >> 5, lane = tid & 31;
    int i0 = blockIdx.x * 128;
    int b = blockIdx.y >> 4, h = blockIdx.y & 15;
    const size_t hq = (size_t)b * Tt * 3 * Dd + h * HD;

#pragma unroll
    for (int j = 0; j < 8; j++) {
        int lin = j * 256 + tid;
        int sel = lin >> 10;
        int l = lin & 1023;
        int r = l >> 3, seg = l & 7;
        const __nv_bfloat16* src = (sel ? qkvlo : qkvhi) + hq + (size_t)(i0 + r) * 3 * Dd + seg * 8;
        cpa16(sb + (sel ? SM_QLO : SM_QHI) + r * APB + seg * 16, src);
    }
    asm volatile("cp.async.commit_group;" ::: "memory");

    int ntiles = i0 / 64 + 2;

    auto issueKV = [&](int jt) {
        int j0 = jt * 64;
        uint32_t buf = sb + SM_KV + (jt & 1) * KVBUF;
#pragma unroll
        for (int j = 0; j < 8; j++) {
            int lin = j * 256 + tid;
            int t = lin >> 9;
            int l = lin & 511;
            int r = l >> 3, seg = l & 7;
            const __nv_bfloat16* basep = (t & 1) ? qkvlo : qkvhi;
            int off = (t < 2) ? Dd : 2 * Dd;
            const __nv_bfloat16* src = basep + hq + (size_t)(j0 + r) * 3 * Dd + off + seg * 8;
            cpa16(buf + t * KVT + r * APB + seg * 16, src);
        }
        asm volatile("cp.async.commit_group;" ::: "memory");
    };

    issueKV(0);

    float o[8][4];
#pragma unroll
    for (int i = 0; i < 8; i++)
#pragma unroll
        for (int q = 0; q < 4; q++) o[i][q] = 0.f;
    float m_run[2] = {-1e30f, -1e30f}, l_run[2] = {0.f, 0.f};

    int r0 = lane >> 2;
    int cq = (lane & 3) * 2;
    int qrow0 = i0 + wid * 16 + r0;
    const float* amrow = amask + b * Tt;

    uint32_t qa_off = (wid * 16 + (lane & 15)) * APB + ((lane >> 4) << 4);
    uint32_t kb_off = ((lane & 7) + ((lane >> 4) << 3)) * APB + (((lane >> 3) & 1) << 4);
    uint32_t vt_off = (lane & 15) * APB + ((lane >> 4) << 4);

    for (int jt = 0; jt < ntiles; jt++) {
        int j0 = jt * 64;
        bool diag = (j0 + 63 > i0);
        asm volatile("cp.async.wait_group 0;" ::: "memory");
        __syncthreads();
        if (jt + 1 < ntiles) issueKV(jt + 1);

        uint32_t buf = sb + SM_KV + (jt & 1) * KVBUF;
        uint32_t khi_b = buf, klo_b = buf + KVT;
        uint32_t vhi_b = buf + 2 * KVT, vlo_b = buf + 3 * KVT;

        float sf[8][4];
#pragma unroll
        for (int i = 0; i < 8; i++)
#pragma unroll
            for (int q = 0; q < 4; q++) sf[i][q] = 0.f;
#pragma unroll
        for (int pass = 0; pass < 3; pass++) {
            uint32_t qb = sb + (pass == 2 ? SM_QLO : SM_QHI);
            uint32_t kb = (pass == 1 ? klo_b : khi_b);
#pragma unroll
            for (int s = 0; s < 4; s++) {
                uint32_t a[4];
                ldsm4(a, qb + qa_off + s * 32);
#pragma unroll
                for (int p2 = 0; p2 < 4; p2++) {
                    uint32_t bbq[4];
                    ldsm4(bbq, kb + kb_off + p2 * (16 * APB) + s * 32);
                    mma_bf16(sf[p2 * 2], a, bbq[0], bbq[1]);
                    mma_bf16(sf[p2 * 2 + 1], a, bbq[2], bbq[3]);
                }
            }
        }

#pragma unroll
        for (int nt = 0; nt < 8; nt++) {
#pragma unroll
            for (int q = 0; q < 4; q++) {
                int col = nt * 8 + cq + (q & 1);
                float am = (1.0f - __ldg(amrow + j0 + col)) * MASK_BIAS;
                float val = sf[nt][q] * 0.125f;
                if (diag && (j0 + col) > (qrow0 + (q >> 1) * 8)) val = MASK_BIAS;
                sf[nt][q] = val + am;
            }
        }

        float alpha[2];
#pragma unroll
        for (int rh = 0; rh < 2; rh++) {
            float mt = -1e30f;
#pragma unroll
            for (int nt = 0; nt < 8; nt++)
                mt = fmaxf(mt, fmaxf(sf[nt][rh * 2], sf[nt][rh * 2 + 1]));
            mt = fmaxf(mt, __shfl_xor_sync(0xffffffffu, mt, 1));
            mt = fmaxf(mt, __shfl_xor_sync(0xffffffffu, mt, 2));
            float mnew = fmaxf(m_run[rh], mt);
            alpha[rh] = __expf(m_run[rh] - mnew);
            m_run[rh] = mnew;
            float ls = 0.f;
#pragma unroll
            for (int nt = 0; nt < 8; nt++) {
                sf[nt][rh * 2] = __expf(sf[nt][rh * 2] - mnew);
                sf[nt][rh * 2 + 1] = __expf(sf[nt][rh * 2 + 1] - mnew);
                ls += sf[nt][rh * 2] + sf[nt][rh * 2 + 1];
            }
            ls += __shfl_xor_sync(0xffffffffu, ls, 1);
            ls += __shfl_xor_sync(0xffffffffu, ls, 2);
            l_run[rh] = l_run[rh] * alpha[rh] + ls;
        }
#pragma unroll
        for (int nt = 0; nt < 8; nt++) {
            o[nt][0] *= alpha[0]; o[nt][1] *= alpha[0];
            o[nt][2] *= alpha[1]; o[nt][3] *= alpha[1];
        }

#pragma unroll
        for (int s2 = 0; s2 < 4; s2++) {
            float p0 = sf[2 * s2][0], p1 = sf[2 * s2][1], p2v = sf[2 * s2][2], p3 = sf[2 * s2][3];
            float q0 = sf[2 * s2 + 1][0], q1 = sf[2 * s2 + 1][1], q2 = sf[2 * s2 + 1][2], q3 = sf[2 * s2 + 1][3];
            uint32_t phi[4], plo[4];
            phi[0] = packbf(p0, p1); phi[1] = packbf(p2v, p3);
            phi[2] = packbf(q0, q1); phi[3] = packbf(q2, q3);
            {
                __nv_bfloat162 t;
                t = *(__nv_bfloat162*)&phi[0];
                plo[0] = packbf(p0 - __low2float(t), p1 - __high2float(t));
                t = *(__nv_bfloat162*)&phi[1];
                plo[1] = packbf(p2v - __low2float(t), p3 - __high2float(t));
                t = *(__nv_bfloat162*)&phi[2];
                plo[2] = packbf(q0 - __low2float(t), q1 - __high2float(t));
                t = *(__nv_bfloat162*)&phi[3];
                plo[3] = packbf(q2 - __low2float(t), q3 - __high2float(t));
            }
#pragma unroll
            for (int p2 = 0; p2 < 4; p2++) {
                uint32_t vaddr = s2 * (16 * APB) + vt_off + p2 * 32;
                uint32_t bh[4], bl[4];
                ldsm4t(bh, vhi_b + vaddr);
                ldsm4t(bl, vlo_b + vaddr);
                mma_bf16(o[p2 * 2], phi, bh[0], bh[1]);
                mma_bf16(o[p2 * 2 + 1], phi, bh[2], bh[3]);
                mma_bf16(o[p2 * 2], phi, bl[0], bl[1]);
                mma_bf16(o[p2 * 2 + 1], phi, bl[2], bl[3]);
                mma_bf16(o[p2 * 2], plo, bh[0], bh[1]);
                mma_bf16(o[p2 * 2 + 1], plo, bh[2], bh[3]);
            }
        }
    }

    float inv[2] = {1.f / l_run[0], 1.f / l_run[1]};
#pragma unroll
    for (int nt = 0; nt < 8; nt++) {
        int d0 = nt * 8 + cq;
#pragma unroll
        for (int rh = 0; rh < 2; rh++) {
            int row = i0 + wid * 16 + r0 + rh * 8;
            float x = o[nt][rh * 2] * inv[rh];
            float y = o[nt][rh * 2 + 1] * inv[rh];
            __half2 hv = __floats2half2_rn(x, y);
            size_t off = (size_t)(b * Tt + row) * Dd + h * HD + d0;
            *(uint32_t*)&ctx[off] = *(uint32_t*)&hv;
        }
    }
}

// ================= host launcher =================
extern "C" void kernel_launch(void* const* d_in, const int* in_sizes, int n_in,
                              void* d_out, int out_size) {
    const float* inputs_embeds = (const float*)d_in[0];
    const float* attention_mask = (const float*)d_in[1];
    const float* ln1_w = (const float*)d_in[2];
    const float* ln1_b = (const float*)d_in[3];
    const float* attn_w = (const float*)d_in[4];
    const float* attn_b = (const float*)d_in[5];
    const float* proj_w = (const float*)d_in[6];
    const float* proj_b = (const float*)d_in[7];
    const float* ln2_w = (const float*)d_in[8];
    const float* ln2_b = (const float*)d_in[9];
    const float* fc_w = (const float*)d_in[10];
    const float* fc_b = (const float*)d_in[11];
    const float* fcp_w = (const float*)d_in[12];
    const float* fcp_b = (const float*)d_in[13];
    const float* lnf_w = (const float*)d_in[14];
    const float* lnf_b = (const float*)d_in[15];
    float* out = (float*)d_out;

    cudaFuncSetAttribute(attn_mma, cudaFuncAttributeMaxDynamicSharedMemorySize, ATTN_SMEM);
    cudaFuncSetAttribute(gemm_mma<false, false, 2>, cudaFuncAttributeMaxDynamicSharedMemorySize, GEMM_SMEM);
    cudaFuncSetAttribute(gemm_mma<false, true, 0>, cudaFuncAttributeMaxDynamicSharedMemorySize, GEMM_SMEM);
    cudaFuncSetAttribute(gemm_mma<true, false, 1>, cudaFuncAttributeMaxDynamicSharedMemorySize, GEMM_SMEM);

    float *ph;
    __nv_bfloat16 *pqh, *pql;
    __half *px16, *pctx, *pff;
    __half *wqh, *wql, *wph, *wpl, *wfh, *wfl, *wgh, *wgl;
    cudaGetSymbolAddress((void**)&ph, g_h);
    cudaGetSymbolAddress((void**)&pqh, g_qkvhi);
    cudaGetSymbolAddress((void**)&pql, g_qkvlo);
    cudaGetSymbolAddress((void**)&px16, g_x16);
    cudaGetSymbolAddress((void**)&pctx, g_ctx16);
    cudaGetSymbolAddress((void**)&pff, g_ff16);
    cudaGetSymbolAddress((void**)&wqh, g_wqkv_hi);
    cudaGetSymbolAddress((void**)&wql, g_wqkv_lo);
    cudaGetSymbolAddress((void**)&wph, g_wproj_hi);
    cudaGetSymbolAddress((void**)&wpl, g_wproj_lo);
    cudaGetSymbolAddress((void**)&wfh, g_wfc_hi);
    cudaGetSymbolAddress((void**)&wfl, g_wfc_lo);
    cudaGetSymbolAddress((void**)&wgh, g_wfcp_hi);
    cudaGetSymbolAddress((void**)&wgl, g_wfcp_lo);

    const int MT = Bb * Tt;

    copy_kernel<<<(MT * Dd / 4) / 256, 256>>>(inputs_embeds);

    for (int l = 0; l < Ll; l++) {
        wconv_kernel<<<dim3(3 * Dd / 32, Dd / 32), 256>>>(
            attn_w + (size_t)l * Dd * 3 * Dd, wqh + (size_t)l * 3 * Dd * Dd, wql + (size_t)l * 3 * Dd * Dd, Dd, 3 * Dd);
        wconv_kernel<<<dim3(Dd / 32, Dd / 32), 256>>>(
            proj_w + (size_t)l * Dd * Dd, wph + (size_t)l * Dd * Dd, wpl + (size_t)l * Dd * Dd, Dd, Dd);
        wconv_kernel<<<dim3(II / 32, Dd / 32), 256>>>(
            fc_w + (size_t)l * Dd * II, wfh + (size_t)l * II * Dd, wfl + (size_t)l * II * Dd, Dd, II);
        wconv_kernel<<<dim3(Dd / 32, II / 32), 256>>>(
            fcp_w + (size_t)l * II * Dd, wgh + (size_t)l * Dd * II, wgl + (size_t)l * Dd * II, II, Dd);
    }

    for (int l = 0; l < Ll; l++) {
        ln_kernel<true><<<MT, 256>>>(ph, ln1_w + (size_t)l * Dd, ln1_b + (size_t)l * Dd, nullptr, px16);
        gemm_mma<false, false, 2><<<dim3(3 * Dd / 128, MT / 128), 256, GEMM_SMEM>>>(
            px16, wqh + (size_t)l * 3 * Dd * Dd, wql + (size_t)l * 3 * Dd * Dd,
            attn_b + (size_t)l * 3 * Dd, nullptr, nullptr, pqh, pql, MT, 3 * Dd, Dd);
        attn_mma<<<dim3(Tt / 128, Bb * Hh), 256, ATTN_SMEM>>>(pqh, pql, attention_mask, pctx);
        gemm_mma<false, true, 0><<<dim3(Dd / 128, MT / 128), 256, GEMM_SMEM>>>(
            pctx, wph + (size_t)l * Dd * Dd, wpl + (size_t)l * Dd * Dd,
            proj_b + (size_t)l * Dd, ph, nullptr, nullptr, nullptr, MT, Dd, Dd);
        ln_kernel<true><<<MT, 256>>>(ph, ln2_w + (size_t)l * Dd, ln2_b + (size_t)l * Dd, nullptr, px16);
        gemm_mma<true, false, 1><<<dim3(II / 128, MT / 128), 256, GEMM_SMEM>>>(
            px16, wfh + (size_t)l * II * Dd, wfl + (size_t)l * II * Dd,
            fc_b + (size_t)l * II, nullptr, pff, nullptr, nullptr, MT, II, Dd);
        gemm_mma<false, true, 0><<<dim3(Dd / 128, MT / 128), 256, GEMM_SMEM>>>(
            pff, wgh + (size_t)l * Dd * II, wgl + (size_t)l * Dd * II,
            fcp_b + (size_t)l * Dd, ph, nullptr, nullptr, nullptr, MT, Dd, II);
    }
    ln_kernel<false><<<MT, 256>>>(ph, lnf_w, lnf_b, out, nullptr);
}

// round 9
// speedup vs baseline: 3.6401x; 1.1142x over previous
#include <cuda_runtime.h>
#include <cuda_bf16.h>
#include <cuda_fp16.h>
#include <math.h>
#include <stdint.h>

#define Bb 2
#define Tt 2048
#define Dd 1024
#define Hh 16
#define Ll 8
#define II 4096
#define HD 64
#define MASK_BIAS -10000.0f
#define LN_EPS 1e-5f
#define WSCALE 64.0f
#define WISCALE 0.015625f

// ================= scratch =================
__device__ float g_h[Bb * Tt * Dd];
__device__ __half g_qkvhi[Bb * Tt * 3 * Dd], g_qkvlo[Bb * Tt * 3 * Dd];
__device__ __half g_x16[Bb * Tt * Dd];
__device__ __half g_ctx16[Bb * Tt * Dd];
__device__ __half g_ff16[Bb * Tt * II];
// transposed, 64x-scaled fp16 weight slabs [L][N][K]
__device__ __half g_wqkv_hi[Ll * 3 * Dd * Dd], g_wqkv_lo[Ll * 3 * Dd * Dd];
__device__ __half g_wproj_hi[Ll * Dd * Dd], g_wproj_lo[Ll * Dd * Dd];
__device__ __half g_wfc_hi[Ll * II * Dd], g_wfc_lo[Ll * II * Dd];
__device__ __half g_wfcp_hi[Ll * Dd * II], g_wfcp_lo[Ll * Dd * II];

__device__ __forceinline__ uint32_t smem_u32(const void* p) {
    uint32_t a;
    asm("{ .reg .u64 t; cvta.to.shared.u64 t, %1; cvt.u32.u64 %0, t; }" : "=r"(a) : "l"(p));
    return a;
}
__device__ __forceinline__ void ldsm4(uint32_t* r, uint32_t addr) {
    asm volatile("ldmatrix.sync.aligned.m8n8.x4.shared.b16 {%0,%1,%2,%3}, [%4];"
                 : "=r"(r[0]), "=r"(r[1]), "=r"(r[2]), "=r"(r[3]) : "r"(addr));
}
__device__ __forceinline__ void ldsm4t(uint32_t* r, uint32_t addr) {
    asm volatile("ldmatrix.sync.aligned.m8n8.x4.trans.shared.b16 {%0,%1,%2,%3}, [%4];"
                 : "=r"(r[0]), "=r"(r[1]), "=r"(r[2]), "=r"(r[3]) : "r"(addr));
}
__device__ __forceinline__ void mma_f16(float* d, const uint32_t* a, uint32_t b0, uint32_t b1) {
    asm volatile("mma.sync.aligned.m16n8k16.row.col.f32.f16.f16.f32 "
                 "{%0,%1,%2,%3}, {%4,%5,%6,%7}, {%8,%9}, {%0,%1,%2,%3};"
                 : "+f"(d[0]), "+f"(d[1]), "+f"(d[2]), "+f"(d[3])
                 : "r"(a[0]), "r"(a[1]), "r"(a[2]), "r"(a[3]), "r"(b0), "r"(b1));
}
__device__ __forceinline__ uint32_t packh(float x, float y) {
    __half2 t = __floats2half2_rn(x, y);
    return *reinterpret_cast<uint32_t*>(&t);
}
__device__ __forceinline__ void cpa16(uint32_t s, const void* g) {
    asm volatile("cp.async.cg.shared.global [%0], [%1], 16;" :: "r"(s), "l"(g));
}

// ================= small kernels =================
__global__ void copy_kernel(const float* __restrict__ src) {
    int i = blockIdx.x * blockDim.x + threadIdx.x;
    reinterpret_cast<float4*>(g_h)[i] = reinterpret_cast<const float4*>(src)[i];
}

__global__ void wconv_kernel(const float* __restrict__ W, __half* __restrict__ Whi,
                             __half* __restrict__ Wlo, int K, int N) {
    __shared__ float s[32][33];
    int n0 = blockIdx.x * 32, k0 = blockIdx.y * 32;
    int tx = threadIdx.x & 31, ty = threadIdx.x >> 5;
#pragma unroll
    for (int i = 0; i < 4; i++)
        s[ty + i * 8][tx] = W[(size_t)(k0 + ty + i * 8) * N + n0 + tx];
    __syncthreads();
#pragma unroll
    for (int i = 0; i < 4; i++) {
        int n = ty + i * 8;
        float v = s[tx][n] * WSCALE;
        __half hi = __float2half(v);
        size_t idx = (size_t)(n0 + n) * K + k0 + tx;
        Whi[idx] = hi;
        Wlo[idx] = __float2half(v - __half2float(hi));
    }
}

template <bool F16OUT>
__global__ void ln_kernel(const float* __restrict__ x, const float* __restrict__ w,
                          const float* __restrict__ b, float* __restrict__ out,
                          __half* __restrict__ o16) {
    int row = blockIdx.x;
    int tid = threadIdx.x;
    const float* xr = x + (size_t)row * Dd;
    float v[4];
    float sum = 0.f, sq = 0.f;
#pragma unroll
    for (int u = 0; u < 4; u++) {
        v[u] = xr[tid + u * 256];
        sum += v[u];
        sq += v[u] * v[u];
    }
#pragma unroll
    for (int o = 16; o > 0; o >>= 1) {
        sum += __shfl_xor_sync(0xffffffffu, sum, o);
        sq += __shfl_xor_sync(0xffffffffu, sq, o);
    }
    __shared__ float ssum[8], ssq[8], stat[2];
    if ((tid & 31) == 0) { ssum[tid >> 5] = sum; ssq[tid >> 5] = sq; }
    __syncthreads();
    if (tid == 0) {
        float S = 0.f, Q = 0.f;
#pragma unroll
        for (int i = 0; i < 8; i++) { S += ssum[i]; Q += ssq[i]; }
        float mean = S * (1.0f / Dd);
        float var = Q * (1.0f / Dd) - mean * mean;
        stat[0] = mean;
        stat[1] = rsqrtf(var + LN_EPS);
    }
    __syncthreads();
    float mean = stat[0], rstd = stat[1];
#pragma unroll
    for (int u = 0; u < 4; u++) {
        int c = tid + u * 256;
        float y = (v[u] - mean) * rstd * w[c] + b[c];
        if (F16OUT) {
            o16[(size_t)row * Dd + c] = __float2half(y);
        } else {
            out[(size_t)row * Dd + c] = y;
        }
    }
}

// ================= HMMA GEMM (fp16 2-pass, 3-stage, 1 barrier/chunk, 2 CTAs/SM) =================
// OUT: 0 = fp32 C, 1 = fp16 Cf, 2 = fp16 hi/lo for attention (K/V cols x64-scaled)
#define PITCHB 80
#define TILE_BYTES (128 * PITCHB)            // 10240
#define STAGE_BYTES (3 * TILE_BYTES)         // 30720: A, Whi, Wlo
#define GEMM_SMEM (3 * STAGE_BYTES)          // 92160

template <bool RELU, bool RESID, int OUT>
__global__ void __launch_bounds__(256, 2)
gemm_mma(const __half* __restrict__ A,
         const __half* __restrict__ Whi, const __half* __restrict__ Wlo,
         const float* __restrict__ bias, float* __restrict__ C,
         __half* __restrict__ Cf,
         __half* __restrict__ Chi, __half* __restrict__ Clo,
         int M, int N, int K) {
    extern __shared__ char smem[];
    uint32_t sb = smem_u32(smem);
    int tid = threadIdx.x, wid = tid >> 5, lane = tid & 31;
    int warp_m = wid & 1, warp_n = wid >> 1;
    int row0 = blockIdx.y * 128, col0 = blockIdx.x * 128;

    const int KC = K >> 5;

    float acc[4][4][4];
#pragma unroll
    for (int i = 0; i < 4; i++)
#pragma unroll
        for (int j = 0; j < 4; j++)
#pragma unroll
            for (int q = 0; q < 4; q++) acc[i][j][q] = 0.f;

    uint32_t a_off = (warp_m * 64 + (lane & 15)) * PITCHB + ((lane >> 4) << 4);
    uint32_t b_off = (warp_n * 32 + (lane & 7) + ((lane >> 4) << 3)) * PITCHB + (((lane >> 3) & 1) << 4);

    auto issue = [&](int c) {
        int k0 = c << 5;
        uint32_t base = sb + (c % 3) * STAGE_BYTES;
#pragma unroll
        for (int j = 0; j < 6; j++) {
            int lin = j * 256 + tid;
            int tile = lin >> 9;
            int l2 = lin & 511;
            int r = l2 >> 2, seg = l2 & 3;
            const __half* src;
            if (tile == 0)      src = A + (size_t)(row0 + r) * K;
            else if (tile == 1) src = Whi + (size_t)(col0 + r) * K;
            else                src = Wlo + (size_t)(col0 + r) * K;
            cpa16(base + tile * TILE_BYTES + r * PITCHB + seg * 16, src + k0 + seg * 8);
        }
        asm volatile("cp.async.commit_group;" ::: "memory");
    };

    issue(0);
    issue(1);
    for (int c = 0; c < KC; c++) {
        if (c + 1 < KC) {
            asm volatile("cp.async.wait_group 1;" ::: "memory");
        } else {
            asm volatile("cp.async.wait_group 0;" ::: "memory");
        }
        __syncthreads();
        if (c + 2 < KC) issue(c + 2);
        uint32_t stage = sb + (c % 3) * STAGE_BYTES;
        uint32_t a_b = stage;
        uint32_t whi_b = stage + TILE_BYTES;
        uint32_t wlo_b = stage + 2 * TILE_BYTES;
#pragma unroll
        for (int ks = 0; ks < 2; ks++) {
            uint32_t bhi[2][4], blo[2][4];
#pragma unroll
            for (int bt = 0; bt < 2; bt++) {
                ldsm4(bhi[bt], whi_b + b_off + bt * (16 * PITCHB) + ks * 32);
                ldsm4(blo[bt], wlo_b + b_off + bt * (16 * PITCHB) + ks * 32);
            }
#pragma unroll
            for (int mt = 0; mt < 4; mt++) {
                uint32_t ah[4];
                ldsm4(ah, a_b + a_off + mt * (16 * PITCHB) + ks * 32);
#pragma unroll
                for (int nt = 0; nt < 4; nt++) {
                    mma_f16(acc[mt][nt], ah, bhi[nt >> 1][(nt & 1) * 2], bhi[nt >> 1][(nt & 1) * 2 + 1]);
                    mma_f16(acc[mt][nt], ah, blo[nt >> 1][(nt & 1) * 2], blo[nt >> 1][(nt & 1) * 2 + 1]);
                }
            }
        }
    }

    int rin = lane >> 2;
    int colp = (lane & 3) * 2;
#pragma unroll
    for (int mt = 0; mt < 4; mt++) {
#pragma unroll
        for (int half = 0; half < 2; half++) {
            int r = row0 + warp_m * 64 + mt * 16 + rin + half * 8;
            size_t rowoff = (size_t)r * N;
#pragma unroll
            for (int nt = 0; nt < 4; nt++) {
                int cg = col0 + warp_n * 32 + nt * 8 + colp;
                float v0 = acc[mt][nt][half * 2 + 0] * WISCALE + bias[cg];
                float v1 = acc[mt][nt][half * 2 + 1] * WISCALE + bias[cg + 1];
                if (RELU) { v0 = fmaxf(v0, 0.f); v1 = fmaxf(v1, 0.f); }
                if (RESID) {
                    float2 o = *(const float2*)&C[rowoff + cg];
                    v0 += o.x; v1 += o.y;
                }
                if (OUT == 0) {
                    *(float2*)&C[rowoff + cg] = make_float2(v0, v1);
                } else if (OUT == 1) {
                    *(uint32_t*)&Cf[rowoff + cg] = packh(v0, v1);
                } else {
                    // qkv: scale K/V columns by 64 so fp16-lo stays normal
                    float s = (cg >= Dd) ? WSCALE : 1.0f;
                    float y0 = v0 * s, y1 = v1 * s;
                    __half h0 = __float2half(y0), h1 = __float2half(y1);
                    union { __half h[2]; uint32_t u; } ph, pl;
                    ph.h[0] = h0; ph.h[1] = h1;
                    pl.h[0] = __float2half(y0 - __half2float(h0));
                    pl.h[1] = __float2half(y1 - __half2float(h1));
                    *(uint32_t*)&Chi[rowoff + cg] = ph.u;
                    *(uint32_t*)&Clo[rowoff + cg] = pl.u;
                }
            }
        }
    }
}

// ================= HMMA flash attention (fp16 2-pass, double-buffered) =================
// smem: Qf16[128x64] | 2 x {Khi, Klo, Vhi, Vlo}[64x64], pitch 144B
#define APB 144
#define SM_Q  0
#define SM_KV 18432
#define KVBUF 36864
#define KVT   9216
#define ATTN_SMEM (18432 + 2 * KVBUF)

__global__ void __launch_bounds__(256, 2)
attn_mma(const __half* __restrict__ qkvhi, const __half* __restrict__ qkvlo,
         const float* __restrict__ amask, __half* __restrict__ ctx) {
    extern __shared__ char sm[];
    uint32_t sb = smem_u32(sm);
    int tid = threadIdx.x, wid = tid >> 5, lane = tid & 31;
    int i0 = blockIdx.x * 128;
    int b = blockIdx.y >> 4, h = blockIdx.y & 15;
    const size_t hq = (size_t)b * Tt * 3 * Dd + h * HD;

    // Q tile (hi only): 1024 x 16B
#pragma unroll
    for (int j = 0; j < 4; j++) {
        int lin = j * 256 + tid;
        int r = lin >> 3, seg = lin & 7;
        cpa16(sb + SM_Q + r * APB + seg * 16, qkvhi + hq + (size_t)(i0 + r) * 3 * Dd + seg * 8);
    }
    asm volatile("cp.async.commit_group;" ::: "memory");

    int ntiles = i0 / 64 + 2;

    auto issueKV = [&](int jt) {
        int j0 = jt * 64;
        uint32_t buf = sb + SM_KV + (jt & 1) * KVBUF;
#pragma unroll
        for (int j = 0; j < 8; j++) {
            int lin = j * 256 + tid;
            int t = lin >> 9;           // 0:Khi 1:Klo 2:Vhi 3:Vlo
            int l = lin & 511;
            int r = l >> 3, seg = l & 7;
            const __half* basep = (t & 1) ? qkvlo : qkvhi;
            int off = (t < 2) ? Dd : 2 * Dd;
            cpa16(buf + t * KVT + r * APB + seg * 16,
                  basep + hq + (size_t)(j0 + r) * 3 * Dd + off + seg * 8);
        }
        asm volatile("cp.async.commit_group;" ::: "memory");
    };

    issueKV(0);

    float o[8][4];
#pragma unroll
    for (int i = 0; i < 8; i++)
#pragma unroll
        for (int q = 0; q < 4; q++) o[i][q] = 0.f;
    float m_run[2] = {-1e30f, -1e30f}, l_run[2] = {0.f, 0.f};

    int r0 = lane >> 2;
    int cq = (lane & 3) * 2;
    int qrow0 = i0 + wid * 16 + r0;
    const float* amrow = amask + b * Tt;
    const float sscale = 0.125f * WISCALE;   // 1/sqrt(64) / 64 (K scaled by 64)

    uint32_t qa_off = (wid * 16 + (lane & 15)) * APB + ((lane >> 4) << 4);
    uint32_t kb_off = ((lane & 7) + ((lane >> 4) << 3)) * APB + (((lane >> 3) & 1) << 4);
    uint32_t vt_off = (lane & 15) * APB + ((lane >> 4) << 4);

    for (int jt = 0; jt < ntiles; jt++) {
        int j0 = jt * 64;
        bool diag = (j0 + 63 > i0);
        asm volatile("cp.async.wait_group 0;" ::: "memory");
        __syncthreads();
        if (jt + 1 < ntiles) issueKV(jt + 1);

        uint32_t buf = sb + SM_KV + (jt & 1) * KVBUF;
        uint32_t khi_b = buf, klo_b = buf + KVT;
        uint32_t vhi_b = buf + 2 * KVT, vlo_b = buf + 3 * KVT;

        // S = Q (Khi + Klo)^T, 2 passes
        float sf[8][4];
#pragma unroll
        for (int i = 0; i < 8; i++)
#pragma unroll
            for (int q = 0; q < 4; q++) sf[i][q] = 0.f;
#pragma unroll
        for (int pass = 0; pass < 2; pass++) {
            uint32_t kb = (pass ? klo_b : khi_b);
#pragma unroll
            for (int s = 0; s < 4; s++) {
                uint32_t a[4];
                ldsm4(a, sb + SM_Q + qa_off + s * 32);
#pragma unroll
                for (int p2 = 0; p2 < 4; p2++) {
                    uint32_t bbq[4];
                    ldsm4(bbq, kb + kb_off + p2 * (16 * APB) + s * 32);
                    mma_f16(sf[p2 * 2], a, bbq[0], bbq[1]);
                    mma_f16(sf[p2 * 2 + 1], a, bbq[2], bbq[3]);
                }
            }
        }

#pragma unroll
        for (int nt = 0; nt < 8; nt++) {
#pragma unroll
            for (int q = 0; q < 4; q++) {
                int col = nt * 8 + cq + (q & 1);
                float am = (1.0f - __ldg(amrow + j0 + col)) * MASK_BIAS;
                float val = sf[nt][q] * sscale;
                if (diag && (j0 + col) > (qrow0 + (q >> 1) * 8)) val = MASK_BIAS;
                sf[nt][q] = val + am;
            }
        }

        float alpha[2];
#pragma unroll
        for (int rh = 0; rh < 2; rh++) {
            float mt = -1e30f;
#pragma unroll
            for (int nt = 0; nt < 8; nt++)
                mt = fmaxf(mt, fmaxf(sf[nt][rh * 2], sf[nt][rh * 2 + 1]));
            mt = fmaxf(mt, __shfl_xor_sync(0xffffffffu, mt, 1));
            mt = fmaxf(mt, __shfl_xor_sync(0xffffffffu, mt, 2));
            float mnew = fmaxf(m_run[rh], mt);
            alpha[rh] = __expf(m_run[rh] - mnew);
            m_run[rh] = mnew;
            float ls = 0.f;
#pragma unroll
            for (int nt = 0; nt < 8; nt++) {
                sf[nt][rh * 2] = __expf(sf[nt][rh * 2] - mnew);
                sf[nt][rh * 2 + 1] = __expf(sf[nt][rh * 2 + 1] - mnew);
                ls += sf[nt][rh * 2] + sf[nt][rh * 2 + 1];
            }
            ls += __shfl_xor_sync(0xffffffffu, ls, 1);
            ls += __shfl_xor_sync(0xffffffffu, ls, 2);
            l_run[rh] = l_run[rh] * alpha[rh] + ls;
        }
#pragma unroll
        for (int nt = 0; nt < 8; nt++) {
            o[nt][0] *= alpha[0]; o[nt][1] *= alpha[0];
            o[nt][2] *= alpha[1]; o[nt][3] *= alpha[1];
        }

        // PV: P fp16, V hi/lo (x64-scaled), ldsm.trans
#pragma unroll
        for (int s2 = 0; s2 < 4; s2++) {
            uint32_t ph[4];
            ph[0] = packh(sf[2 * s2][0], sf[2 * s2][1]);
            ph[1] = packh(sf[2 * s2][2], sf[2 * s2][3]);
            ph[2] = packh(sf[2 * s2 + 1][0], sf[2 * s2 + 1][1]);
            ph[3] = packh(sf[2 * s2 + 1][2], sf[2 * s2 + 1][3]);
#pragma unroll
            for (int p2 = 0; p2 < 4; p2++) {
                uint32_t vaddr = s2 * (16 * APB) + vt_off + p2 * 32;
                uint32_t bh[4], bl[4];
                ldsm4t(bh, vhi_b + vaddr);
                ldsm4t(bl, vlo_b + vaddr);
                mma_f16(o[p2 * 2], ph, bh[0], bh[1]);
                mma_f16(o[p2 * 2 + 1], ph, bh[2], bh[3]);
                mma_f16(o[p2 * 2], ph, bl[0], bl[1]);
                mma_f16(o[p2 * 2 + 1], ph, bl[2], bl[3]);
            }
        }
    }

    // output: ctx = o / l / 64 (V was x64-scaled)
    float inv[2] = {WISCALE / l_run[0], WISCALE / l_run[1]};
#pragma unroll
    for (int nt = 0; nt < 8; nt++) {
        int d0 = nt * 8 + cq;
#pragma unroll
        for (int rh = 0; rh < 2; rh++) {
            int row = i0 + wid * 16 + r0 + rh * 8;
            size_t off = (size_t)(b * Tt + row) * Dd + h * HD + d0;
            *(uint32_t*)&ctx[off] = packh(o[nt][rh * 2] * inv[rh], o[nt][rh * 2 + 1] * inv[rh]);
        }
    }
}

// ================= host launcher =================
extern "C" void kernel_launch(void* const* d_in, const int* in_sizes, int n_in,
                              void* d_out, int out_size) {
    const float* inputs_embeds = (const float*)d_in[0];
    const float* attention_mask = (const float*)d_in[1];
    const float* ln1_w = (const float*)d_in[2];
    const float* ln1_b = (const float*)d_in[3];
    const float* attn_w = (const float*)d_in[4];
    const float* attn_b = (const float*)d_in[5];
    const float* proj_w = (const float*)d_in[6];
    const float* proj_b = (const float*)d_in[7];
    const float* ln2_w = (const float*)d_in[8];
    const float* ln2_b = (const float*)d_in[9];
    const float* fc_w = (const float*)d_in[10];
    const float* fc_b = (const float*)d_in[11];
    const float* fcp_w = (const float*)d_in[12];
    const float* fcp_b = (const float*)d_in[13];
    const float* lnf_w = (const float*)d_in[14];
    const float* lnf_b = (const float*)d_in[15];
    float* out = (float*)d_out;

    cudaFuncSetAttribute(attn_mma, cudaFuncAttributeMaxDynamicSharedMemorySize, ATTN_SMEM);
    cudaFuncSetAttribute(gemm_mma<false, false, 2>, cudaFuncAttributeMaxDynamicSharedMemorySize, GEMM_SMEM);
    cudaFuncSetAttribute(gemm_mma<false, true, 0>, cudaFuncAttributeMaxDynamicSharedMemorySize, GEMM_SMEM);
    cudaFuncSetAttribute(gemm_mma<true, false, 1>, cudaFuncAttributeMaxDynamicSharedMemorySize, GEMM_SMEM);

    float *ph;
    __half *pqh, *pql, *px16, *pctx, *pff;
    __half *wqh, *wql, *wph, *wpl, *wfh, *wfl, *wgh, *wgl;
    cudaGetSymbolAddress((void**)&ph, g_h);
    cudaGetSymbolAddress((void**)&pqh, g_qkvhi);
    cudaGetSymbolAddress((void**)&pql, g_qkvlo);
    cudaGetSymbolAddress((void**)&px16, g_x16);
    cudaGetSymbolAddress((void**)&pctx, g_ctx16);
    cudaGetSymbolAddress((void**)&pff, g_ff16);
    cudaGetSymbolAddress((void**)&wqh, g_wqkv_hi);
    cudaGetSymbolAddress((void**)&wql, g_wqkv_lo);
    cudaGetSymbolAddress((void**)&wph, g_wproj_hi);
    cudaGetSymbolAddress((void**)&wpl, g_wproj_lo);
    cudaGetSymbolAddress((void**)&wfh, g_wfc_hi);
    cudaGetSymbolAddress((void**)&wfl, g_wfc_lo);
    cudaGetSymbolAddress((void**)&wgh, g_wfcp_hi);
    cudaGetSymbolAddress((void**)&wgl, g_wfcp_lo);

    const int MT = Bb * Tt;

    copy_kernel<<<(MT * Dd / 4) / 256, 256>>>(inputs_embeds);

    for (int l = 0; l < Ll; l++) {
        wconv_kernel<<<dim3(3 * Dd / 32, Dd / 32), 256>>>(
            attn_w + (size_t)l * Dd * 3 * Dd, wqh + (size_t)l * 3 * Dd * Dd, wql + (size_t)l * 3 * Dd * Dd, Dd, 3 * Dd);
        wconv_kernel<<<dim3(Dd / 32, Dd / 32), 256>>>(
            proj_w + (size_t)l * Dd * Dd, wph + (size_t)l * Dd * Dd, wpl + (size_t)l * Dd * Dd, Dd, Dd);
        wconv_kernel<<<dim3(II / 32, Dd / 32), 256>>>(
            fc_w + (size_t)l * Dd * II, wfh + (size_t)l * II * Dd, wfl + (size_t)l * II * Dd, Dd, II);
        wconv_kernel<<<dim3(Dd / 32, II / 32), 256>>>(
            fcp_w + (size_t)l * II * Dd, wgh + (size_t)l * Dd * II, wgl + (size_t)l * Dd * II, II, Dd);
    }

    for (int l = 0; l < Ll; l++) {
        ln_kernel<true><<<MT, 256>>>(ph, ln1_w + (size_t)l * Dd, ln1_b + (size_t)l * Dd, nullptr, px16);
        gemm_mma<false, false, 2><<<dim3(3 * Dd / 128, MT / 128), 256, GEMM_SMEM>>>(
            px16, wqh + (size_t)l * 3 * Dd * Dd, wql + (size_t)l * 3 * Dd * Dd,
            attn_b + (size_t)l * 3 * Dd, nullptr, nullptr, pqh, pql, MT, 3 * Dd, Dd);
        attn_mma<<<dim3(Tt / 128, Bb * Hh), 256, ATTN_SMEM>>>(pqh, pql, attention_mask, pctx);
        gemm_mma<false, true, 0><<<dim3(Dd / 128, MT / 128), 256, GEMM_SMEM>>>(
            pctx, wph + (size_t)l * Dd * Dd, wpl + (size_t)l * Dd * Dd,
            proj_b + (size_t)l * Dd, ph, nullptr, nullptr, nullptr, MT, Dd, Dd);
        ln_kernel<true><<<MT, 256>>>(ph, ln2_w + (size_t)l * Dd, ln2_b + (size_t)l * Dd, nullptr, px16);
        gemm_mma<true, false, 1><<<dim3(II / 128, MT / 128), 256, GEMM_SMEM>>>(
            px16, wfh + (size_t)l * II * Dd, wfl + (size_t)l * II * Dd,
            fc_b + (size_t)l * II, nullptr, pff, nullptr, nullptr, MT, II, Dd);
        gemm_mma<false, true, 0><<<dim3(Dd / 128, MT / 128), 256, GEMM_SMEM>>>(
            pff, wgh + (size_t)l * Dd * II, wgl + (size_t)l * Dd * II,
            fcp_b + (size_t)l * Dd, ph, nullptr, nullptr, nullptr, MT, Dd, II);
    }
    ln_kernel<false><<<MT, 256>>>(ph, lnf_w, lnf_b, out, nullptr);
}

// round 11
// speedup vs baseline: 5.2831x; 1.4514x over previous
#include <cuda_runtime.h>
#include <cuda_bf16.h>
#include <cuda_fp16.h>
#include <math.h>
#include <stdint.h>

#define Bb 2
#define Tt 2048
#define Dd 1024
#define Hh 16
#define Ll 8
#define II 4096
#define HD 64
#define MASK_BIAS -10000.0f
#define LN_EPS 1e-5f
#define KVSCALE 64.0f
#define KVISCALE 0.015625f

// ================= scratch =================
__device__ float g_h[Bb * Tt * Dd];
__device__ __half g_qkvhi[Bb * Tt * 3 * Dd], g_qkvlo[Bb * Tt * 3 * Dd];
__device__ __half g_x16[Bb * Tt * Dd];
__device__ __half g_ctx16[Bb * Tt * Dd];
__device__ __half g_ff16[Bb * Tt * II];
// transposed fp16 weight slabs [L][N][K]
__device__ __half g_wqkv[Ll * 3 * Dd * Dd];
__device__ __half g_wproj[Ll * Dd * Dd];
__device__ __half g_wfc[Ll * II * Dd];
__device__ __half g_wfcp[Ll * Dd * II];

__device__ __forceinline__ uint32_t smem_u32(const void* p) {
    uint32_t a;
    asm("{ .reg .u64 t; cvta.to.shared.u64 t, %1; cvt.u32.u64 %0, t; }" : "=r"(a) : "l"(p));
    return a;
}
__device__ __forceinline__ void ldsm4(uint32_t* r, uint32_t addr) {
    asm volatile("ldmatrix.sync.aligned.m8n8.x4.shared.b16 {%0,%1,%2,%3}, [%4];"
                 : "=r"(r[0]), "=r"(r[1]), "=r"(r[2]), "=r"(r[3]) : "r"(addr));
}
__device__ __forceinline__ void ldsm4t(uint32_t* r, uint32_t addr) {
    asm volatile("ldmatrix.sync.aligned.m8n8.x4.trans.shared.b16 {%0,%1,%2,%3}, [%4];"
                 : "=r"(r[0]), "=r"(r[1]), "=r"(r[2]), "=r"(r[3]) : "r"(addr));
}
__device__ __forceinline__ void mma_f16(float* d, const uint32_t* a, uint32_t b0, uint32_t b1) {
    asm volatile("mma.sync.aligned.m16n8k16.row.col.f32.f16.f16.f32 "
                 "{%0,%1,%2,%3}, {%4,%5,%6,%7}, {%8,%9}, {%0,%1,%2,%3};"
                 : "+f"(d[0]), "+f"(d[1]), "+f"(d[2]), "+f"(d[3])
                 : "r"(a[0]), "r"(a[1]), "r"(a[2]), "r"(a[3]), "r"(b0), "r"(b1));
}
__device__ __forceinline__ uint32_t packh(float x, float y) {
    __half2 t = __floats2half2_rn(x, y);
    return *reinterpret_cast<uint32_t*>(&t);
}
__device__ __forceinline__ void cpa16(uint32_t s, const void* g) {
    asm volatile("cp.async.cg.shared.global [%0], [%1], 16;" :: "r"(s), "l"(g));
}

// ================= small kernels =================
__global__ void copy_kernel(const float* __restrict__ src) {
    int i = blockIdx.x * blockDim.x + threadIdx.x;
    reinterpret_cast<float4*>(g_h)[i] = reinterpret_cast<const float4*>(src)[i];
}

// weight transpose + fp16 convert: W[K][N] -> W'[N][K]
__global__ void wconv_kernel(const float* __restrict__ W, __half* __restrict__ Wo,
                             int K, int N) {
    __shared__ float s[32][33];
    int n0 = blockIdx.x * 32, k0 = blockIdx.y * 32;
    int tx = threadIdx.x & 31, ty = threadIdx.x >> 5;
#pragma unroll
    for (int i = 0; i < 4; i++)
        s[ty + i * 8][tx] = W[(size_t)(k0 + ty + i * 8) * N + n0 + tx];
    __syncthreads();
#pragma unroll
    for (int i = 0; i < 4; i++) {
        int n = ty + i * 8;
        Wo[(size_t)(n0 + n) * K + k0 + tx] = __float2half(s[tx][n]);
    }
}

template <bool F16OUT>
__global__ void ln_kernel(const float* __restrict__ x, const float* __restrict__ w,
                          const float* __restrict__ b, float* __restrict__ out,
                          __half* __restrict__ o16) {
    int row = blockIdx.x;
    int tid = threadIdx.x;
    const float* xr = x + (size_t)row * Dd;
    float v[4];
    float sum = 0.f, sq = 0.f;
#pragma unroll
    for (int u = 0; u < 4; u++) {
        v[u] = xr[tid + u * 256];
        sum += v[u];
        sq += v[u] * v[u];
    }
#pragma unroll
    for (int o = 16; o > 0; o >>= 1) {
        sum += __shfl_xor_sync(0xffffffffu, sum, o);
        sq += __shfl_xor_sync(0xffffffffu, sq, o);
    }
    __shared__ float ssum[8], ssq[8], stat[2];
    if ((tid & 31) == 0) { ssum[tid >> 5] = sum; ssq[tid >> 5] = sq; }
    __syncthreads();
    if (tid == 0) {
        float S = 0.f, Q = 0.f;
#pragma unroll
        for (int i = 0; i < 8; i++) { S += ssum[i]; Q += ssq[i]; }
        float mean = S * (1.0f / Dd);
        float var = Q * (1.0f / Dd) - mean * mean;
        stat[0] = mean;
        stat[1] = rsqrtf(var + LN_EPS);
    }
    __syncthreads();
    float mean = stat[0], rstd = stat[1];
#pragma unroll
    for (int u = 0; u < 4; u++) {
        int c = tid + u * 256;
        float y = (v[u] - mean) * rstd * w[c] + b[c];
        if (F16OUT) {
            o16[(size_t)row * Dd + c] = __float2half(y);
        } else {
            out[(size_t)row * Dd + c] = y;
        }
    }
}

// ================= HMMA GEMM (fp16 single-pass, 3-stage, 2 CTAs/SM) =================
// OUT: 0 = fp32 C, 1 = fp16 Cf, 2 = fp16 hi/lo qkv (K/V cols x64-scaled)
#define PITCHB 80
#define TILE_BYTES (128 * PITCHB)            // 10240
#define STAGE_BYTES (2 * TILE_BYTES)         // 20480: A, W
#define GEMM_SMEM (3 * STAGE_BYTES)          // 61440

template <bool RELU, bool RESID, int OUT>
__global__ void __launch_bounds__(256, 2)
gemm_mma(const __half* __restrict__ A, const __half* __restrict__ W,
         const float* __restrict__ bias, float* __restrict__ C,
         __half* __restrict__ Cf,
         __half* __restrict__ Chi, __half* __restrict__ Clo,
         int M, int N, int K) {
    extern __shared__ char smem[];
    uint32_t sb = smem_u32(smem);
    int tid = threadIdx.x, wid = tid >> 5, lane = tid & 31;
    int warp_m = wid & 1, warp_n = wid >> 1;
    int row0 = blockIdx.y * 128, col0 = blockIdx.x * 128;

    const int KC = K >> 5;

    float acc[4][4][4];
#pragma unroll
    for (int i = 0; i < 4; i++)
#pragma unroll
        for (int j = 0; j < 4; j++)
#pragma unroll
            for (int q = 0; q < 4; q++) acc[i][j][q] = 0.f;

    uint32_t a_off = (warp_m * 64 + (lane & 15)) * PITCHB + ((lane >> 4) << 4);
    uint32_t b_off = (warp_n * 32 + (lane & 7) + ((lane >> 4) << 3)) * PITCHB + (((lane >> 3) & 1) << 4);

    auto issue = [&](int c) {
        int k0 = c << 5;
        uint32_t base = sb + (c % 3) * STAGE_BYTES;
#pragma unroll
        for (int j = 0; j < 4; j++) {
            int lin = j * 256 + tid;          // 0..1023
            int tile = lin >> 9;              // 0:A 1:W
            int l2 = lin & 511;
            int r = l2 >> 2, seg = l2 & 3;
            const __half* src = tile ? (W + (size_t)(col0 + r) * K)
                                     : (A + (size_t)(row0 + r) * K);
            cpa16(base + tile * TILE_BYTES + r * PITCHB + seg * 16, src + k0 + seg * 8);
        }
        asm volatile("cp.async.commit_group;" ::: "memory");
    };

    issue(0);
    issue(1);
    for (int c = 0; c < KC; c++) {
        if (c + 1 < KC) {
            asm volatile("cp.async.wait_group 1;" ::: "memory");
        } else {
            asm volatile("cp.async.wait_group 0;" ::: "memory");
        }
        __syncthreads();
        if (c + 2 < KC) issue(c + 2);
        uint32_t stage = sb + (c % 3) * STAGE_BYTES;
        uint32_t a_b = stage;
        uint32_t w_b = stage + TILE_BYTES;
#pragma unroll
        for (int ks = 0; ks < 2; ks++) {
            uint32_t bw[2][4];
#pragma unroll
            for (int bt = 0; bt < 2; bt++)
                ldsm4(bw[bt], w_b + b_off + bt * (16 * PITCHB) + ks * 32);
#pragma unroll
            for (int mt = 0; mt < 4; mt++) {
                uint32_t ah[4];
                ldsm4(ah, a_b + a_off + mt * (16 * PITCHB) + ks * 32);
#pragma unroll
                for (int nt = 0; nt < 4; nt++)
                    mma_f16(acc[mt][nt], ah, bw[nt >> 1][(nt & 1) * 2], bw[nt >> 1][(nt & 1) * 2 + 1]);
            }
        }
    }

    int rin = lane >> 2;
    int colp = (lane & 3) * 2;
#pragma unroll
    for (int mt = 0; mt < 4; mt++) {
#pragma unroll
        for (int half = 0; half < 2; half++) {
            int r = row0 + warp_m * 64 + mt * 16 + rin + half * 8;
            size_t rowoff = (size_t)r * N;
#pragma unroll
            for (int nt = 0; nt < 4; nt++) {
                int cg = col0 + warp_n * 32 + nt * 8 + colp;
                float v0 = acc[mt][nt][half * 2 + 0] + bias[cg];
                float v1 = acc[mt][nt][half * 2 + 1] + bias[cg + 1];
                if (RELU) { v0 = fmaxf(v0, 0.f); v1 = fmaxf(v1, 0.f); }
                if (RESID) {
                    float2 o = *(const float2*)&C[rowoff + cg];
                    v0 += o.x; v1 += o.y;
                }
                if (OUT == 0) {
                    *(float2*)&C[rowoff + cg] = make_float2(v0, v1);
                } else if (OUT == 1) {
                    *(uint32_t*)&Cf[rowoff + cg] = packh(v0, v1);
                } else {
                    // qkv: scale K/V columns by 64 so fp16-lo stays normal
                    float s = (cg >= Dd) ? KVSCALE : 1.0f;
                    float y0 = v0 * s, y1 = v1 * s;
                    __half h0 = __float2half(y0), h1 = __float2half(y1);
                    union { __half h[2]; uint32_t u; } ph, pl;
                    ph.h[0] = h0; ph.h[1] = h1;
                    pl.h[0] = __float2half(y0 - __half2float(h0));
                    pl.h[1] = __float2half(y1 - __half2float(h1));
                    *(uint32_t*)&Chi[rowoff + cg] = ph.u;
                    *(uint32_t*)&Clo[rowoff + cg] = pl.u;
                }
            }
        }
    }
}

// ================= HMMA flash attention (fp16 2-pass K/V, double-buffered) =================
#define APB 144
#define SM_Q  0
#define SM_KV 18432
#define KVBUF 36864
#define KVT   9216
#define ATTN_SMEM (18432 + 2 * KVBUF)

__global__ void __launch_bounds__(256, 2)
attn_mma(const __half* __restrict__ qkvhi, const __half* __restrict__ qkvlo,
         const float* __restrict__ amask, __half* __restrict__ ctx) {
    extern __shared__ char sm[];
    uint32_t sb = smem_u32(sm);
    int tid = threadIdx.x, wid = tid >> 5, lane = tid & 31;
    int i0 = blockIdx.x * 128;
    int b = blockIdx.y >> 4, h = blockIdx.y & 15;
    const size_t hq = (size_t)b * Tt * 3 * Dd + h * HD;

#pragma unroll
    for (int j = 0; j < 4; j++) {
        int lin = j * 256 + tid;
        int r = lin >> 3, seg = lin & 7;
        cpa16(sb + SM_Q + r * APB + seg * 16, qkvhi + hq + (size_t)(i0 + r) * 3 * Dd + seg * 8);
    }
    asm volatile("cp.async.commit_group;" ::: "memory");

    int ntiles = i0 / 64 + 2;

    auto issueKV = [&](int jt) {
        int j0 = jt * 64;
        uint32_t buf = sb + SM_KV + (jt & 1) * KVBUF;
#pragma unroll
        for (int j = 0; j < 8; j++) {
            int lin = j * 256 + tid;
            int t = lin >> 9;
            int l = lin & 511;
            int r = l >> 3, seg = l & 7;
            const __half* basep = (t & 1) ? qkvlo : qkvhi;
            int off = (t < 2) ? Dd : 2 * Dd;
            cpa16(buf + t * KVT + r * APB + seg * 16,
                  basep + hq + (size_t)(j0 + r) * 3 * Dd + off + seg * 8);
        }
        asm volatile("cp.async.commit_group;" ::: "memory");
    };

    issueKV(0);

    float o[8][4];
#pragma unroll
    for (int i = 0; i < 8; i++)
#pragma unroll
        for (int q = 0; q < 4; q++) o[i][q] = 0.f;
    float m_run[2] = {-1e30f, -1e30f}, l_run[2] = {0.f, 0.f};

    int r0 = lane >> 2;
    int cq = (lane & 3) * 2;
    int qrow0 = i0 + wid * 16 + r0;
    const float* amrow = amask + b * Tt;
    const float sscale = 0.125f * KVISCALE;

    uint32_t qa_off = (wid * 16 + (lane & 15)) * APB + ((lane >> 4) << 4);
    uint32_t kb_off = ((lane & 7) + ((lane >> 4) << 3)) * APB + (((lane >> 3) & 1) << 4);
    uint32_t vt_off = (lane & 15) * APB + ((lane >> 4) << 4);

    for (int jt = 0; jt < ntiles; jt++) {
        int j0 = jt * 64;
        bool diag = (j0 + 63 > i0);
        asm volatile("cp.async.wait_group 0;" ::: "memory");
        __syncthreads();
        if (jt + 1 < ntiles) issueKV(jt + 1);

        uint32_t buf = sb + SM_KV + (jt & 1) * KVBUF;
        uint32_t khi_b = buf, klo_b = buf + KVT;
        uint32_t vhi_b = buf + 2 * KVT, vlo_b = buf + 3 * KVT;

        float sf[8][4];
#pragma unroll
        for (int i = 0; i < 8; i++)
#pragma unroll
            for (int q = 0; q < 4; q++) sf[i][q] = 0.f;
#pragma unroll
        for (int pass = 0; pass < 2; pass++) {
            uint32_t kb = (pass ? klo_b : khi_b);
#pragma unroll
            for (int s = 0; s < 4; s++) {
                uint32_t a[4];
                ldsm4(a, sb + SM_Q + qa_off + s * 32);
#pragma unroll
                for (int p2 = 0; p2 < 4; p2++) {
                    uint32_t bbq[4];
                    ldsm4(bbq, kb + kb_off + p2 * (16 * APB) + s * 32);
                    mma_f16(sf[p2 * 2], a, bbq[0], bbq[1]);
                    mma_f16(sf[p2 * 2 + 1], a, bbq[2], bbq[3]);
                }
            }
        }

#pragma unroll
        for (int nt = 0; nt < 8; nt++) {
#pragma unroll
            for (int q = 0; q < 4; q++) {
                int col = nt * 8 + cq + (q & 1);
                float am = (1.0f - __ldg(amrow + j0 + col)) * MASK_BIAS;
                float val = sf[nt][q] * sscale;
                if (diag && (j0 + col) > (qrow0 + (q >> 1) * 8)) val = MASK_BIAS;
                sf[nt][q] = val + am;
            }
        }

        float alpha[2];
#pragma unroll
        for (int rh = 0; rh < 2; rh++) {
            float mt = -1e30f;
#pragma unroll
            for (int nt = 0; nt < 8; nt++)
                mt = fmaxf(mt, fmaxf(sf[nt][rh * 2], sf[nt][rh * 2 + 1]));
            mt = fmaxf(mt, __shfl_xor_sync(0xffffffffu, mt, 1));
            mt = fmaxf(mt, __shfl_xor_sync(0xffffffffu, mt, 2));
            float mnew = fmaxf(m_run[rh], mt);
            alpha[rh] = __expf(m_run[rh] - mnew);
            m_run[rh] = mnew;
            float ls = 0.f;
#pragma unroll
            for (int nt = 0; nt < 8; nt++) {
                sf[nt][rh * 2] = __expf(sf[nt][rh * 2] - mnew);
                sf[nt][rh * 2 + 1] = __expf(sf[nt][rh * 2 + 1] - mnew);
                ls += sf[nt][rh * 2] + sf[nt][rh * 2 + 1];
            }
            ls += __shfl_xor_sync(0xffffffffu, ls, 1);
            ls += __shfl_xor_sync(0xffffffffu, ls, 2);
            l_run[rh] = l_run[rh] * alpha[rh] + ls;
        }
#pragma unroll
        for (int nt = 0; nt < 8; nt++) {
            o[nt][0] *= alpha[0]; o[nt][1] *= alpha[0];
            o[nt][2] *= alpha[1]; o[nt][3] *= alpha[1];
        }

#pragma unroll
        for (int s2 = 0; s2 < 4; s2++) {
            uint32_t ph[4];
            ph[0] = packh(sf[2 * s2][0], sf[2 * s2][1]);
            ph[1] = packh(sf[2 * s2][2], sf[2 * s2][3]);
            ph[2] = packh(sf[2 * s2 + 1][0], sf[2 * s2 + 1][1]);
            ph[3] = packh(sf[2 * s2 + 1][2], sf[2 * s2 + 1][3]);
#pragma unroll
            for (int p2 = 0; p2 < 4; p2++) {
                uint32_t vaddr = s2 * (16 * APB) + vt_off + p2 * 32;
                uint32_t bh[4], bl[4];
                ldsm4t(bh, vhi_b + vaddr);
                ldsm4t(bl, vlo_b + vaddr);
                mma_f16(o[p2 * 2], ph, bh[0], bh[1]);
                mma_f16(o[p2 * 2 + 1], ph, bh[2], bh[3]);
                mma_f16(o[p2 * 2], ph, bl[0], bl[1]);
                mma_f16(o[p2 * 2 + 1], ph, bl[2], bl[3]);
            }
        }
    }

    float inv[2] = {KVISCALE / l_run[0], KVISCALE / l_run[1]};
#pragma unroll
    for (int nt = 0; nt < 8; nt++) {
        int d0 = nt * 8 + cq;
#pragma unroll
        for (int rh = 0; rh < 2; rh++) {
            int row = i0 + wid * 16 + r0 + rh * 8;
            size_t off = (size_t)(b * Tt + row) * Dd + h * HD + d0;
            *(uint32_t*)&ctx[off] = packh(o[nt][rh * 2] * inv[rh], o[nt][rh * 2 + 1] * inv[rh]);
        }
    }
}

// ================= host launcher =================
extern "C" void kernel_launch(void* const* d_in, const int* in_sizes, int n_in,
                              void* d_out, int out_size) {
    const float* inputs_embeds = (const float*)d_in[0];
    const float* attention_mask = (const float*)d_in[1];
    const float* ln1_w = (const float*)d_in[2];
    const float* ln1_b = (const float*)d_in[3];
    const float* attn_w = (const float*)d_in[4];
    const float* attn_b = (const float*)d_in[5];
    const float* proj_w = (const float*)d_in[6];
    const float* proj_b = (const float*)d_in[7];
    const float* ln2_w = (const float*)d_in[8];
    const float* ln2_b = (const float*)d_in[9];
    const float* fc_w = (const float*)d_in[10];
    const float* fc_b = (const float*)d_in[11];
    const float* fcp_w = (const float*)d_in[12];
    const float* fcp_b = (const float*)d_in[13];
    const float* lnf_w = (const float*)d_in[14];
    const float* lnf_b = (const float*)d_in[15];
    float* out = (float*)d_out;

    cudaFuncSetAttribute(attn_mma, cudaFuncAttributeMaxDynamicSharedMemorySize, ATTN_SMEM);
    cudaFuncSetAttribute(gemm_mma<false, false, 2>, cudaFuncAttributeMaxDynamicSharedMemorySize, GEMM_SMEM);
    cudaFuncSetAttribute(gemm_mma<false, true, 0>, cudaFuncAttributeMaxDynamicSharedMemorySize, GEMM_SMEM);
    cudaFuncSetAttribute(gemm_mma<true, false, 1>, cudaFuncAttributeMaxDynamicSharedMemorySize, GEMM_SMEM);

    float *ph;
    __half *pqh, *pql, *px16, *pctx, *pff;
    __half *wq, *wp, *wf, *wg;
    cudaGetSymbolAddress((void**)&ph, g_h);
    cudaGetSymbolAddress((void**)&pqh, g_qkvhi);
    cudaGetSymbolAddress((void**)&pql, g_qkvlo);
    cudaGetSymbolAddress((void**)&px16, g_x16);
    cudaGetSymbolAddress((void**)&pctx, g_ctx16);
    cudaGetSymbolAddress((void**)&pff, g_ff16);
    cudaGetSymbolAddress((void**)&wq, g_wqkv);
    cudaGetSymbolAddress((void**)&wp, g_wproj);
    cudaGetSymbolAddress((void**)&wf, g_wfc);
    cudaGetSymbolAddress((void**)&wg, g_wfcp);

    const int MT = Bb * Tt;

    copy_kernel<<<(MT * Dd / 4) / 256, 256>>>(inputs_embeds);

    for (int l = 0; l < Ll; l++) {
        wconv_kernel<<<dim3(3 * Dd / 32, Dd / 32), 256>>>(
            attn_w + (size_t)l * Dd * 3 * Dd, wq + (size_t)l * 3 * Dd * Dd, Dd, 3 * Dd);
        wconv_kernel<<<dim3(Dd / 32, Dd / 32), 256>>>(
            proj_w + (size_t)l * Dd * Dd, wp + (size_t)l * Dd * Dd, Dd, Dd);
        wconv_kernel<<<dim3(II / 32, Dd / 32), 256>>>(
            fc_w + (size_t)l * Dd * II, wf + (size_t)l * II * Dd, Dd, II);
        wconv_kernel<<<dim3(Dd / 32, II / 32), 256>>>(
            fcp_w + (size_t)l * II * Dd, wg + (size_t)l * Dd * II, II, Dd);
    }

    for (int l = 0; l < Ll; l++) {
        ln_kernel<true><<<MT, 256>>>(ph, ln1_w + (size_t)l * Dd, ln1_b + (size_t)l * Dd, nullptr, px16);
        gemm_mma<false, false, 2><<<dim3(3 * Dd / 128, MT / 128), 256, GEMM_SMEM>>>(
            px16, wq + (size_t)l * 3 * Dd * Dd,
            attn_b + (size_t)l * 3 * Dd, nullptr, nullptr, pqh, pql, MT, 3 * Dd, Dd);
        attn_mma<<<dim3(Tt / 128, Bb * Hh), 256, ATTN_SMEM>>>(pqh, pql, attention_mask, pctx);
        gemm_mma<false, true, 0><<<dim3(Dd / 128, MT / 128), 256, GEMM_SMEM>>>(
            pctx, wp + (size_t)l * Dd * Dd,
            proj_b + (size_t)l * Dd, ph, nullptr, nullptr, nullptr, MT, Dd, Dd);
        ln_kernel<true><<<MT, 256>>>(ph, ln2_w + (size_t)l * Dd, ln2_b + (size_t)l * Dd, nullptr, px16);
        gemm_mma<true, false, 1><<<dim3(II / 128, MT / 128), 256, GEMM_SMEM>>>(
            px16, wf + (size_t)l * II * Dd,
            fc_b + (size_t)l * II, nullptr, pff, nullptr, nullptr, MT, II, Dd);
        gemm_mma<false, true, 0><<<dim3(Dd / 128, MT / 128), 256, GEMM_SMEM>>>(
            pff, wg + (size_t)l * Dd * II,
            fcp_b + (size_t)l * Dd, ph, nullptr, nullptr, nullptr, MT, Dd, II);
    }
    ln_kernel<false><<<MT, 256>>>(ph, lnf_w, lnf_b, out, nullptr);
}

// round 14
// speedup vs baseline: 5.7882x; 1.0956x over previous
#include <cuda_runtime.h>
#include <cuda_bf16.h>
#include <cuda_fp16.h>
#include <math.h>
#include <stdint.h>

#define Bb 2
#define Tt 2048
#define Dd 1024
#define Hh 16
#define Ll 8
#define II 4096
#define HD 64
#define MASK_BIAS -10000.0f
#define LN_EPS 1e-5f
#define KVSCALE 64.0f
#define KVISCALE 0.015625f

// ================= scratch =================
__device__ float g_h[Bb * Tt * Dd];
__device__ __half g_qkvhi[Bb * Tt * 3 * Dd], g_qkvlo[Bb * Tt * 3 * Dd];
__device__ __half g_x16[Bb * Tt * Dd];
__device__ __half g_ctx16[Bb * Tt * Dd];
__device__ __half g_ff16[Bb * Tt * II];
// transposed fp16 weight slabs [L][N][K]
__device__ __half g_wqkv[Ll * 3 * Dd * Dd];
__device__ __half g_wproj[Ll * Dd * Dd];
__device__ __half g_wfc[Ll * II * Dd];
__device__ __half g_wfcp[Ll * Dd * II];

__device__ __forceinline__ uint32_t smem_u32(const void* p) {
    uint32_t a;
    asm("{ .reg .u64 t; cvta.to.shared.u64 t, %1; cvt.u32.u64 %0, t; }" : "=r"(a) : "l"(p));
    return a;
}
__device__ __forceinline__ void ldsm4(uint32_t* r, uint32_t addr) {
    asm volatile("ldmatrix.sync.aligned.m8n8.x4.shared.b16 {%0,%1,%2,%3}, [%4];"
                 : "=r"(r[0]), "=r"(r[1]), "=r"(r[2]), "=r"(r[3]) : "r"(addr));
}
__device__ __forceinline__ void ldsm4t(uint32_t* r, uint32_t addr) {
    asm volatile("ldmatrix.sync.aligned.m8n8.x4.trans.shared.b16 {%0,%1,%2,%3}, [%4];"
                 : "=r"(r[0]), "=r"(r[1]), "=r"(r[2]), "=r"(r[3]) : "r"(addr));
}
__device__ __forceinline__ void mma_f16(float* d, const uint32_t* a, uint32_t b0, uint32_t b1) {
    asm volatile("mma.sync.aligned.m16n8k16.row.col.f32.f16.f16.f32 "
                 "{%0,%1,%2,%3}, {%4,%5,%6,%7}, {%8,%9}, {%0,%1,%2,%3};"
                 : "+f"(d[0]), "+f"(d[1]), "+f"(d[2]), "+f"(d[3])
                 : "r"(a[0]), "r"(a[1]), "r"(a[2]), "r"(a[3]), "r"(b0), "r"(b1));
}
__device__ __forceinline__ uint32_t packh(float x, float y) {
    __half2 t = __floats2half2_rn(x, y);
    return *reinterpret_cast<uint32_t*>(&t);
}
__device__ __forceinline__ void cpa16(uint32_t s, const void* g) {
    asm volatile("cp.async.cg.shared.global [%0], [%1], 16;" :: "r"(s), "l"(g));
}

// ================= small kernels =================
__global__ void copy_kernel(const float* __restrict__ src) {
    int i = blockIdx.x * blockDim.x + threadIdx.x;
    reinterpret_cast<float4*>(g_h)[i] = reinterpret_cast<const float4*>(src)[i];
}

__global__ void wconv_kernel(const float* __restrict__ W, __half* __restrict__ Wo,
                             int K, int N) {
    __shared__ float s[32][33];
    int n0 = blockIdx.x * 32, k0 = blockIdx.y * 32;
    int tx = threadIdx.x & 31, ty = threadIdx.x >> 5;
#pragma unroll
    for (int i = 0; i < 4; i++)
        s[ty + i * 8][tx] = W[(size_t)(k0 + ty + i * 8) * N + n0 + tx];
    __syncthreads();
#pragma unroll
    for (int i = 0; i < 4; i++) {
        int n = ty + i * 8;
        Wo[(size_t)(n0 + n) * K + k0 + tx] = __float2half(s[tx][n]);
    }
}

template <bool F16OUT>
__global__ void ln_kernel(const float* __restrict__ x, const float* __restrict__ w,
                          const float* __restrict__ b, float* __restrict__ out,
                          __half* __restrict__ o16) {
    int row = blockIdx.x;
    int tid = threadIdx.x;
    const float* xr = x + (size_t)row * Dd;
    float v[4];
    float sum = 0.f, sq = 0.f;
#pragma unroll
    for (int u = 0; u < 4; u++) {
        v[u] = xr[tid + u * 256];
        sum += v[u];
        sq += v[u] * v[u];
    }
#pragma unroll
    for (int o = 16; o > 0; o >>= 1) {
        sum += __shfl_xor_sync(0xffffffffu, sum, o);
        sq += __shfl_xor_sync(0xffffffffu, sq, o);
    }
    __shared__ float ssum[8], ssq[8], stat[2];
    if ((tid & 31) == 0) { ssum[tid >> 5] = sum; ssq[tid >> 5] = sq; }
    __syncthreads();
    if (tid == 0) {
        float S = 0.f, Q = 0.f;
#pragma unroll
        for (int i = 0; i < 8; i++) { S += ssum[i]; Q += ssq[i]; }
        float mean = S * (1.0f / Dd);
        float var = Q * (1.0f / Dd) - mean * mean;
        stat[0] = mean;
        stat[1] = rsqrtf(var + LN_EPS);
    }
    __syncthreads();
    float mean = stat[0], rstd = stat[1];
#pragma unroll
    for (int u = 0; u < 4; u++) {
        int c = tid + u * 256;
        float y = (v[u] - mean) * rstd * w[c] + b[c];
        if (F16OUT) {
            o16[(size_t)row * Dd + c] = __float2half(y);
        } else {
            out[(size_t)row * Dd + c] = y;
        }
    }
}

// ================= HMMA GEMM (fp16, 64x64 warp tile, 128 thr, 3-stage, 2 CTAs/SM) =================
// OUT: 0 = fp32 C, 1 = fp16 Cf, 2 = fp16 hi/lo qkv (K/V cols x64-scaled)
#define PITCHB 80
#define TILE_BYTES (128 * PITCHB)            // 10240
#define STAGE_BYTES (2 * TILE_BYTES)         // 20480: A, W
#define GEMM_SMEM (3 * STAGE_BYTES)          // 61440

template <bool RELU, bool RESID, int OUT>
__global__ void __launch_bounds__(128, 2)
gemm_mma(const __half* __restrict__ A, const __half* __restrict__ W,
         const float* __restrict__ bias, float* __restrict__ C,
         __half* __restrict__ Cf,
         __half* __restrict__ Chi, __half* __restrict__ Clo,
         int M, int N, int K) {
    extern __shared__ char smem[];
    uint32_t sb = smem_u32(smem);
    int tid = threadIdx.x, wid = tid >> 5, lane = tid & 31;
    int warp_m = wid & 1, warp_n = wid >> 1;    // 2 x 2 warp grid, 64x64 warp tile
    int row0 = blockIdx.y * 128, col0 = blockIdx.x * 128;

    const int KC = K >> 5;

    float acc[4][8][4];
#pragma unroll
    for (int i = 0; i < 4; i++)
#pragma unroll
        for (int j = 0; j < 8; j++)
#pragma unroll
            for (int q = 0; q < 4; q++) acc[i][j][q] = 0.f;

    uint32_t a_off = (warp_m * 64 + (lane & 15)) * PITCHB + ((lane >> 4) << 4);
    uint32_t b_off = (warp_n * 64 + (lane & 7) + ((lane >> 4) << 3)) * PITCHB + (((lane >> 3) & 1) << 4);

    auto issue = [&](int c) {
        int k0 = c << 5;
        uint32_t base = sb + (c % 3) * STAGE_BYTES;
#pragma unroll
        for (int j = 0; j < 8; j++) {
            int lin = j * 128 + tid;          // 0..1023
            int tile = lin >> 9;              // 0:A 1:W
            int l2 = lin & 511;
            int r = l2 >> 2, seg = l2 & 3;
            const __half* src = tile ? (W + (size_t)(col0 + r) * K)
                                     : (A + (size_t)(row0 + r) * K);
            cpa16(base + tile * TILE_BYTES + r * PITCHB + seg * 16, src + k0 + seg * 8);
        }
        asm volatile("cp.async.commit_group;" ::: "memory");
    };

    issue(0);
    issue(1);
    for (int c = 0; c < KC; c++) {
        if (c + 1 < KC) {
            asm volatile("cp.async.wait_group 1;" ::: "memory");
        } else {
            asm volatile("cp.async.wait_group 0;" ::: "memory");
        }
        __syncthreads();
        if (c + 2 < KC) issue(c + 2);
        uint32_t stage = sb + (c % 3) * STAGE_BYTES;
        uint32_t a_b = stage;
        uint32_t w_b = stage + TILE_BYTES;
#pragma unroll
        for (int ks = 0; ks < 2; ks++) {
            uint32_t bw[4][4];
#pragma unroll
            for (int bt = 0; bt < 4; bt++)
                ldsm4(bw[bt], w_b + b_off + bt * (16 * PITCHB) + ks * 32);
#pragma unroll
            for (int mt = 0; mt < 4; mt++) {
                uint32_t ah[4];
                ldsm4(ah, a_b + a_off + mt * (16 * PITCHB) + ks * 32);
#pragma unroll
                for (int nt = 0; nt < 8; nt++)
                    mma_f16(acc[mt][nt], ah, bw[nt >> 1][(nt & 1) * 2], bw[nt >> 1][(nt & 1) * 2 + 1]);
            }
        }
    }

    int rin = lane >> 2;
    int colp = (lane & 3) * 2;
#pragma unroll
    for (int mt = 0; mt < 4; mt++) {
#pragma unroll
        for (int half = 0; half < 2; half++) {
            int r = row0 + warp_m * 64 + mt * 16 + rin + half * 8;
            size_t rowoff = (size_t)r * N;
#pragma unroll
            for (int nt = 0; nt < 8; nt++) {
                int cg = col0 + warp_n * 64 + nt * 8 + colp;
                float v0 = acc[mt][nt][half * 2 + 0] + bias[cg];
                float v1 = acc[mt][nt][half * 2 + 1] + bias[cg + 1];
                if (RELU) { v0 = fmaxf(v0, 0.f); v1 = fmaxf(v1, 0.f); }
                if (RESID) {
                    float2 o = *(const float2*)&C[rowoff + cg];
                    v0 += o.x; v1 += o.y;
                }
                if (OUT == 0) {
                    *(float2*)&C[rowoff + cg] = make_float2(v0, v1);
                } else if (OUT == 1) {
                    *(uint32_t*)&Cf[rowoff + cg] = packh(v0, v1);
                } else {
                    float s = (cg >= Dd) ? KVSCALE : 1.0f;
                    float y0 = v0 * s, y1 = v1 * s;
                    __half h0 = __float2half(y0), h1 = __float2half(y1);
                    union { __half h[2]; uint32_t u; } ph, pl;
                    ph.h[0] = h0; ph.h[1] = h1;
                    pl.h[0] = __float2half(y0 - __half2float(h0));
                    pl.h[1] = __float2half(y1 - __half2float(h1));
                    *(uint32_t*)&Chi[rowoff + cg] = ph.u;
                    *(uint32_t*)&Clo[rowoff + cg] = pl.u;
                }
            }
        }
    }
}

// ================= HMMA flash attention (fp16 2-pass K/V, double-buffered) =================
#define APB 144
#define SM_Q  0
#define SM_KV 18432
#define KVBUF 36864
#define KVT   9216
#define ATTN_SMEM (18432 + 2 * KVBUF)

__global__ void __launch_bounds__(256, 2)
attn_mma(const __half* __restrict__ qkvhi, const __half* __restrict__ qkvlo,
         const float* __restrict__ amask, __half* __restrict__ ctx) {
    extern __shared__ char sm[];
    uint32_t sb = smem_u32(sm);
    int tid = threadIdx.x, wid = tid >> 5, lane = tid & 31;
    int i0 = blockIdx.x * 128;
    int b = blockIdx.y >> 4, h = blockIdx.y & 15;
    const size_t hq = (size_t)b * Tt * 3 * Dd + h * HD;

#pragma unroll
    for (int j = 0; j < 4; j++) {
        int lin = j * 256 + tid;
        int r = lin >> 3, seg = lin & 7;
        cpa16(sb + SM_Q + r * APB + seg * 16, qkvhi + hq + (size_t)(i0 + r) * 3 * Dd + seg * 8);
    }
    asm volatile("cp.async.commit_group;" ::: "memory");

    int ntiles = i0 / 64 + 2;

    auto issueKV = [&](int jt) {
        int j0 = jt * 64;
        uint32_t buf = sb + SM_KV + (jt & 1) * KVBUF;
#pragma unroll
        for (int j = 0; j < 8; j++) {
            int lin = j * 256 + tid;
            int t = lin >> 9;
            int l = lin & 511;
            int r = l >> 3, seg = l & 7;
            const __half* basep = (t & 1) ? qkvlo : qkvhi;
            int off = (t < 2) ? Dd : 2 * Dd;
            cpa16(buf + t * KVT + r * APB + seg * 16,
                  basep + hq + (size_t)(j0 + r) * 3 * Dd + off + seg * 8);
        }
        asm volatile("cp.async.commit_group;" ::: "memory");
    };

    issueKV(0);

    float o[8][4];
#pragma unroll
    for (int i = 0; i < 8; i++)
#pragma unroll
        for (int q = 0; q < 4; q++) o[i][q] = 0.f;
    float m_run[2] = {-1e30f, -1e30f}, l_run[2] = {0.f, 0.f};

    int r0 = lane >> 2;
    int cq = (lane & 3) * 2;
    int qrow0 = i0 + wid * 16 + r0;
    const float* amrow = amask + b * Tt;
    const float sscale = 0.125f * KVISCALE;

    uint32_t qa_off = (wid * 16 + (lane & 15)) * APB + ((lane >> 4) << 4);
    uint32_t kb_off = ((lane & 7) + ((lane >> 4) << 3)) * APB + (((lane >> 3) & 1) << 4);
    uint32_t vt_off = (lane & 15) * APB + ((lane >> 4) << 4);

    for (int jt = 0; jt < ntiles; jt++) {
        int j0 = jt * 64;
        bool diag = (j0 + 63 > i0);
        asm volatile("cp.async.wait_group 0;" ::: "memory");
        __syncthreads();
        if (jt + 1 < ntiles) issueKV(jt + 1);

        uint32_t buf = sb + SM_KV + (jt & 1) * KVBUF;
        uint32_t khi_b = buf, klo_b = buf + KVT;
        uint32_t vhi_b = buf + 2 * KVT, vlo_b = buf + 3 * KVT;

        float sf[8][4];
#pragma unroll
        for (int i = 0; i < 8; i++)
#pragma unroll
            for (int q = 0; q < 4; q++) sf[i][q] = 0.f;
#pragma unroll
        for (int pass = 0; pass < 2; pass++) {
            uint32_t kb = (pass ? klo_b : khi_b);
#pragma unroll
            for (int s = 0; s < 4; s++) {
                uint32_t a[4];
                ldsm4(a, sb + SM_Q + qa_off + s * 32);
#pragma unroll
                for (int p2 = 0; p2 < 4; p2++) {
                    uint32_t bbq[4];
                    ldsm4(bbq, kb + kb_off + p2 * (16 * APB) + s * 32);
                    mma_f16(sf[p2 * 2], a, bbq[0], bbq[1]);
                    mma_f16(sf[p2 * 2 + 1], a, bbq[2], bbq[3]);
                }
            }
        }

#pragma unroll
        for (int nt = 0; nt < 8; nt++) {
#pragma unroll
            for (int q = 0; q < 4; q++) {
                int col = nt * 8 + cq + (q & 1);
                float am = (1.0f - __ldg(amrow + j0 + col)) * MASK_BIAS;
                float val = sf[nt][q] * sscale;
                if (diag && (j0 + col) > (qrow0 + (q >> 1) * 8)) val = MASK_BIAS;
                sf[nt][q] = val + am;
            }
        }

        float alpha[2];
#pragma unroll
        for (int rh = 0; rh < 2; rh++) {
            float mt = -1e30f;
#pragma unroll
            for (int nt = 0; nt < 8; nt++)
                mt = fmaxf(mt, fmaxf(sf[nt][rh * 2], sf[nt][rh * 2 + 1]));
            mt = fmaxf(mt, __shfl_xor_sync(0xffffffffu, mt, 1));
            mt = fmaxf(mt, __shfl_xor_sync(0xffffffffu, mt, 2));
            float mnew = fmaxf(m_run[rh], mt);
            alpha[rh] = __expf(m_run[rh] - mnew);
            m_run[rh] = mnew;
            float ls = 0.f;
#pragma unroll
            for (int nt = 0; nt < 8; nt++) {
                sf[nt][rh * 2] = __expf(sf[nt][rh * 2] - mnew);
                sf[nt][rh * 2 + 1] = __expf(sf[nt][rh * 2 + 1] - mnew);
                ls += sf[nt][rh * 2] + sf[nt][rh * 2 + 1];
            }
            ls += __shfl_xor_sync(0xffffffffu, ls, 1);
            ls += __shfl_xor_sync(0xffffffffu, ls, 2);
            l_run[rh] = l_run[rh] * alpha[rh] + ls;
        }
#pragma unroll
        for (int nt = 0; nt < 8; nt++) {
            o[nt][0] *= alpha[0]; o[nt][1] *= alpha[0];
            o[nt][2] *= alpha[1]; o[nt][3] *= alpha[1];
        }

#pragma unroll
        for (int s2 = 0; s2 < 4; s2++) {
            uint32_t ph[4];
            ph[0] = packh(sf[2 * s2][0], sf[2 * s2][1]);
            ph[1] = packh(sf[2 * s2][2], sf[2 * s2][3]);
            ph[2] = packh(sf[2 * s2 + 1][0], sf[2 * s2 + 1][1]);
            ph[3] = packh(sf[2 * s2 + 1][2], sf[2 * s2 + 1][3]);
#pragma unroll
            for (int p2 = 0; p2 < 4; p2++) {
                uint32_t vaddr = s2 * (16 * APB) + vt_off + p2 * 32;
                uint32_t bh[4], bl[4];
                ldsm4t(bh, vhi_b + vaddr);
                ldsm4t(bl, vlo_b + vaddr);
                mma_f16(o[p2 * 2], ph, bh[0], bh[1]);
                mma_f16(o[p2 * 2 + 1], ph, bh[2], bh[3]);
                mma_f16(o[p2 * 2], ph, bl[0], bl[1]);
                mma_f16(o[p2 * 2 + 1], ph, bl[2], bl[3]);
            }
        }
    }

    float inv[2] = {KVISCALE / l_run[0], KVISCALE / l_run[1]};
#pragma unroll
    for (int nt = 0; nt < 8; nt++) {
        int d0 = nt * 8 + cq;
#pragma unroll
        for (int rh = 0; rh < 2; rh++) {
            int row = i0 + wid * 16 + r0 + rh * 8;
            size_t off = (size_t)(b * Tt + row) * Dd + h * HD + d0;
            *(uint32_t*)&ctx[off] = packh(o[nt][rh * 2] * inv[rh], o[nt][rh * 2 + 1] * inv[rh]);
        }
    }
}

// ================= host launcher =================
extern "C" void kernel_launch(void* const* d_in, const int* in_sizes, int n_in,
                              void* d_out, int out_size) {
    const float* inputs_embeds = (const float*)d_in[0];
    const float* attention_mask = (const float*)d_in[1];
    const float* ln1_w = (const float*)d_in[2];
    const float* ln1_b = (const float*)d_in[3];
    const float* attn_w = (const float*)d_in[4];
    const float* attn_b = (const float*)d_in[5];
    const float* proj_w = (const float*)d_in[6];
    const float* proj_b = (const float*)d_in[7];
    const float* ln2_w = (const float*)d_in[8];
    const float* ln2_b = (const float*)d_in[9];
    const float* fc_w = (const float*)d_in[10];
    const float* fc_b = (const float*)d_in[11];
    const float* fcp_w = (const float*)d_in[12];
    const float* fcp_b = (const float*)d_in[13];
    const float* lnf_w = (const float*)d_in[14];
    const float* lnf_b = (const float*)d_in[15];
    float* out = (float*)d_out;

    cudaFuncSetAttribute(attn_mma, cudaFuncAttributeMaxDynamicSharedMemorySize, ATTN_SMEM);
    cudaFuncSetAttribute(gemm_mma<false, false, 2>, cudaFuncAttributeMaxDynamicSharedMemorySize, GEMM_SMEM);
    cudaFuncSetAttribute(gemm_mma<false, true, 0>, cudaFuncAttributeMaxDynamicSharedMemorySize, GEMM_SMEM);
    cudaFuncSetAttribute(gemm_mma<true, false, 1>, cudaFuncAttributeMaxDynamicSharedMemorySize, GEMM_SMEM);

    float *ph;
    __half *pqh, *pql, *px16, *pctx, *pff;
    __half *wq, *wp, *wf, *wg;
    cudaGetSymbolAddress((void**)&ph, g_h);
    cudaGetSymbolAddress((void**)&pqh, g_qkvhi);
    cudaGetSymbolAddress((void**)&pql, g_qkvlo);
    cudaGetSymbolAddress((void**)&px16, g_x16);
    cudaGetSymbolAddress((void**)&pctx, g_ctx16);
    cudaGetSymbolAddress((void**)&pff, g_ff16);
    cudaGetSymbolAddress((void**)&wq, g_wqkv);
    cudaGetSymbolAddress((void**)&wp, g_wproj);
    cudaGetSymbolAddress((void**)&wf, g_wfc);
    cudaGetSymbolAddress((void**)&wg, g_wfcp);

    const int MT = Bb * Tt;

    copy_kernel<<<(MT * Dd / 4) / 256, 256>>>(inputs_embeds);

    for (int l = 0; l < Ll; l++) {
        wconv_kernel<<<dim3(3 * Dd / 32, Dd / 32), 256>>>(
            attn_w + (size_t)l * Dd * 3 * Dd, wq + (size_t)l * 3 * Dd * Dd, Dd, 3 * Dd);
        wconv_kernel<<<dim3(Dd / 32, Dd / 32), 256>>>(
            proj_w + (size_t)l * Dd * Dd, wp + (size_t)l * Dd * Dd, Dd, Dd);
        wconv_kernel<<<dim3(II / 32, Dd / 32), 256>>>(
            fc_w + (size_t)l * Dd * II, wf + (size_t)l * II * Dd, Dd, II);
        wconv_kernel<<<dim3(Dd / 32, II / 32), 256>>>(
            fcp_w + (size_t)l * II * Dd, wg + (size_t)l * Dd * II, II, Dd);
    }

    for (int l = 0; l < Ll; l++) {
        ln_kernel<true><<<MT, 256>>>(ph, ln1_w + (size_t)l * Dd, ln1_b + (size_t)l * Dd, nullptr, px16);
        gemm_mma<false, false, 2><<<dim3(3 * Dd / 128, MT / 128), 128, GEMM_SMEM>>>(
            px16, wq + (size_t)l * 3 * Dd * Dd,
            attn_b + (size_t)l * 3 * Dd, nullptr, nullptr, pqh, pql, MT, 3 * Dd, Dd);
        attn_mma<<<dim3(Tt / 128, Bb * Hh), 256, ATTN_SMEM>>>(pqh, pql, attention_mask, pctx);
        gemm_mma<false, true, 0><<<dim3(Dd / 128, MT / 128), 128, GEMM_SMEM>>>(
            pctx, wp + (size_t)l * Dd * Dd,
            proj_b + (size_t)l * Dd, ph, nullptr, nullptr, nullptr, MT, Dd, Dd);
        ln_kernel<true><<<MT, 256>>>(ph, ln2_w + (size_t)l * Dd, ln2_b + (size_t)l * Dd, nullptr, px16);
        gemm_mma<true, false, 1><<<dim3(II / 128, MT / 128), 128, GEMM_SMEM>>>(
            px16, wf + (size_t)l * II * Dd,
            fc_b + (size_t)l * II, nullptr, pff, nullptr, nullptr, MT, II, Dd);
        gemm_mma<false, true, 0><<<dim3(Dd / 128, MT / 128), 128, GEMM_SMEM>>>(
            pff, wg + (size_t)l * Dd * II,
            fcp_b + (size_t)l * Dd, ph, nullptr, nullptr, nullptr, MT, Dd, II);
    }
    ln_kernel<false><<<MT, 256>>>(ph, lnf_w, lnf_b, out, nullptr);
}